// round 1
// baseline (speedup 1.0000x reference)
#include <cuda_runtime.h>

#define BSZ 16
#define NPIX 1024
#define HWD 32
#define SCALE_ATT 0.17677669529663687f

// ---------------- static scratch (no allocations allowed) ----------------
__device__ float g_y1 [BSZ * 512 * NPIX]; // cv1 out: [a (ch 0-255) ; bb (ch 256-511)]
__device__ float g_qkv[BSZ * 512 * NPIX]; // qkv out
__device__ float g_xa [BSZ * 256 * NPIX]; // attention out (+ PE)
__device__ float g_ff [BSZ * 512 * NPIX]; // ffn1 out

__device__ __forceinline__ float silu_f(float v) {
    return v / (1.0f + __expf(-v));
}

// ---------------- generic 1x1-conv GEMM ----------------
// out[b, m, n] = act( (sum_c W[m,c] * X[b,c,n]) * s[m] + bias[m] + res[b,m,n] )
// Tile: BM=128 (out ch), BN=64 (pixels), BK=16. 256 threads, 8x4 microtile.
__global__ __launch_bounds__(256) void gemm1x1(
    const float* __restrict__ X, int in_bstride, int Cin,
    const float* __restrict__ W,
    const float* __restrict__ sc, const float* __restrict__ bi,
    const float* __restrict__ res, int res_bstride,
    float* __restrict__ out, int out_bstride, int act)
{
    __shared__ float Ws[16][128];
    __shared__ float Xs[16][64];

    const int b  = blockIdx.z;
    const int m0 = blockIdx.y * 128;
    const int n0 = blockIdx.x * 64;
    const int tid = threadIdx.x;
    const int ty = tid >> 4;      // 0..15 -> 8 channels each
    const int tx = tid & 15;      // 0..15 -> 4 pixels each

    const float* Xb = X + (size_t)b * in_bstride;

    float acc[8][4];
#pragma unroll
    for (int i = 0; i < 8; i++)
#pragma unroll
        for (int j = 0; j < 4; j++) acc[i][j] = 0.0f;

    for (int k0 = 0; k0 < Cin; k0 += 16) {
        // W tile: Ws[k][m] = W[(m0+m)*Cin + k0+k]
        {
            int m  = tid >> 1;
            int kk = (tid & 1) * 8;
            const float* wp = W + (size_t)(m0 + m) * Cin + k0 + kk;
            float4 w0 = *(const float4*)wp;
            float4 w1 = *(const float4*)(wp + 4);
            Ws[kk + 0][m] = w0.x; Ws[kk + 1][m] = w0.y;
            Ws[kk + 2][m] = w0.z; Ws[kk + 3][m] = w0.w;
            Ws[kk + 4][m] = w1.x; Ws[kk + 5][m] = w1.y;
            Ws[kk + 6][m] = w1.z; Ws[kk + 7][m] = w1.w;
        }
        // X tile: Xs[k][n] = Xb[(k0+k)*NPIX + n0+n]
        {
            int k = tid >> 4;
            int n = (tid & 15) * 4;
            *(float4*)&Xs[k][n] = *(const float4*)&Xb[(size_t)(k0 + k) * NPIX + n0 + n];
        }
        __syncthreads();
#pragma unroll
        for (int k = 0; k < 16; k++) {
            float xr[4];
            *(float4*)xr = *(float4*)&Xs[k][tx * 4];
            float wr[8];
            *(float4*)(wr)     = *(float4*)&Ws[k][ty * 8];
            *(float4*)(wr + 4) = *(float4*)&Ws[k][ty * 8 + 4];
#pragma unroll
            for (int i = 0; i < 8; i++)
#pragma unroll
                for (int j = 0; j < 4; j++)
                    acc[i][j] += wr[i] * xr[j];
        }
        __syncthreads();
    }

#pragma unroll
    for (int i = 0; i < 8; i++) {
        int m = m0 + ty * 8 + i;
        float s  = sc[m];
        float bb = bi[m];
#pragma unroll
        for (int j = 0; j < 4; j++) {
            int n = n0 + tx * 4 + j;
            float v = acc[i][j] * s + bb;
            if (res) v += res[(size_t)b * res_bstride + (size_t)m * NPIX + n];
            if (act) v = silu_f(v);
            out[(size_t)b * out_bstride + (size_t)m * NPIX + n] = v;
        }
    }
}

// ---------------- attention ----------------
// One block = one (b,h) and 16 query rows. Full K in smem; scores row fully
// in-warp (2 rows/warp); PV uses V tiles aliased over the K region.
__global__ __launch_bounds__(256) void attn_kernel(
    const float* __restrict__ qkv, float* __restrict__ xa)
{
    extern __shared__ float sm[];
    float* KV = sm;                  // K: [32][1024] floats; later V tile [128][68]
    float* S  = sm + 32 * NPIX;      // scores/probs: [16][1032] (padded)
    float* Qs = S + 16 * 1032;       // [16][32]

    const int tid  = threadIdx.x;
    const int warp = tid >> 5;
    const int lane = tid & 31;
    const int bh = blockIdx.y;                 // b*4 + h
    const int r0 = blockIdx.x * 16;
    const float* base = qkv + (size_t)bh * 128 * NPIX; // head channel base

    // Load K (local channels 32..63), coalesced float4
    {
        const float4* src = (const float4*)(base + 32 * NPIX);
        float4* dst = (float4*)KV;
#pragma unroll
        for (int i = 0; i < 32; i++) dst[tid + 256 * i] = src[tid + 256 * i];
    }
    // Load Q rows r0..r0+15
    for (int i = tid; i < 16 * 32; i += 256) {
        int r = i >> 5, d = i & 31;
        Qs[i] = base[(size_t)d * NPIX + r0 + r];
    }
    __syncthreads();

    // ---- scores: warp w handles rows 2w, 2w+1; lane owns m = lane + 32j ----
    {
        const int ra = warp * 2, rb = ra + 1;
        float qa[32], qb[32];
#pragma unroll
        for (int d = 0; d < 32; d++) { qa[d] = Qs[ra * 32 + d]; qb[d] = Qs[rb * 32 + d]; }

#pragma unroll 1
        for (int j = 0; j < 32; j += 2) {
            int m0 = lane + 32 * j;
            float a0 = 0.f, a1 = 0.f, b0 = 0.f, b1 = 0.f;
#pragma unroll
            for (int d = 0; d < 32; d++) {
                float k0 = KV[d * NPIX + m0];
                float k1 = KV[d * NPIX + m0 + 32];
                a0 += qa[d] * k0; a1 += qa[d] * k1;
                b0 += qb[d] * k0; b1 += qb[d] * k1;
            }
            S[ra * 1032 + m0]      = a0 * SCALE_ATT;
            S[ra * 1032 + m0 + 32] = a1 * SCALE_ATT;
            S[rb * 1032 + m0]      = b0 * SCALE_ATT;
            S[rb * 1032 + m0 + 32] = b1 * SCALE_ATT;
        }

        // ---- softmax, fully in-warp per row ----
#pragma unroll
        for (int rr = 0; rr < 2; rr++) {
            int r = ra + rr;
            float v[32];
            float mx = -1e30f;
#pragma unroll
            for (int j = 0; j < 32; j++) {
                v[j] = S[r * 1032 + lane + 32 * j];
                mx = fmaxf(mx, v[j]);
            }
#pragma unroll
            for (int o = 16; o > 0; o >>= 1)
                mx = fmaxf(mx, __shfl_xor_sync(0xffffffffu, mx, o));
            float sum = 0.f;
#pragma unroll
            for (int j = 0; j < 32; j++) { v[j] = __expf(v[j] - mx); sum += v[j]; }
#pragma unroll
            for (int o = 16; o > 0; o >>= 1)
                sum += __shfl_xor_sync(0xffffffffu, sum, o);
            float inv = 1.0f / sum;
#pragma unroll
            for (int j = 0; j < 32; j++) S[r * 1032 + lane + 32 * j] = v[j] * inv;
        }
    }
    __syncthreads();

    // ---- PV: out[r, d] = sum_m P[r, m] * V[d, m] ----
    // 128 active threads: r = tid>>3 (16 rows), d8 = (tid&7)*8 (8 d each).
    float acc[8] = {0, 0, 0, 0, 0, 0, 0, 0};
    const int pr = tid >> 3;
    const int pd = (tid & 7) << 3;
    float* Vt = KV; // [mm][68] padded, aliases K region (done with K)

    for (int mt = 0; mt < 8; mt++) {
        // Load V tile: Vt[mm][d] = V[d, mt*128+mm] (coalesced global, padded STS)
#pragma unroll
        for (int i = 0; i < 32; i++) {
            int idx = tid + 256 * i;
            int d = idx >> 7, mm = idx & 127;
            Vt[mm * 68 + d] = base[(size_t)(64 + d) * NPIX + mt * 128 + mm];
        }
        __syncthreads();
        if (tid < 128) {
            const float* Srow = S + pr * 1032 + mt * 128;
#pragma unroll 4
            for (int mm = 0; mm < 128; mm++) {
                float p = Srow[mm];
                const float* vp = Vt + mm * 68 + pd;
                float4 v0 = *(const float4*)vp;
                float4 v1 = *(const float4*)(vp + 4);
                acc[0] += p * v0.x; acc[1] += p * v0.y;
                acc[2] += p * v0.z; acc[3] += p * v0.w;
                acc[4] += p * v1.x; acc[5] += p * v1.y;
                acc[6] += p * v1.z; acc[7] += p * v1.w;
            }
        }
        __syncthreads();
    }
    if (tid < 128) {
#pragma unroll
        for (int k = 0; k < 8; k++)
            xa[(size_t)(bh * 64 + pd + k) * NPIX + r0 + pr] = acc[k];
    }
}

// ---------------- depthwise 3x3 PE conv (adds into xa) ----------------
__global__ __launch_bounds__(256) void dwconv_pe(
    const float* __restrict__ qkv, const float* __restrict__ Wpe,
    const float* __restrict__ s, const float* __restrict__ bi,
    float* __restrict__ xa)
{
    __shared__ float t[34 * 34];
    const int c = blockIdx.x;       // 0..255 (v channel, reshaped)
    const int b = blockIdx.y;
    const int qc = ((c >> 6) * 128) + 64 + (c & 63); // qkv channel of v
    const float* src = qkv + ((size_t)b * 512 + qc) * NPIX;
    const int tid = threadIdx.x;

    for (int i = tid; i < 34 * 34; i += 256) t[i] = 0.0f;
    __syncthreads();
    for (int i = tid; i < NPIX; i += 256) {
        int y = i >> 5, x = i & 31;
        t[(y + 1) * 34 + (x + 1)] = src[i];
    }
    __syncthreads();

    float w[9];
#pragma unroll
    for (int i = 0; i < 9; i++) w[i] = Wpe[c * 9 + i];
    const float scv = s[c], bv = bi[c];
    float* dst = xa + ((size_t)b * 256 + c) * NPIX;

    for (int i = tid; i < NPIX; i += 256) {
        int y = i >> 5, x = i & 31;
        float acc = 0.0f;
#pragma unroll
        for (int ky = 0; ky < 3; ky++)
#pragma unroll
            for (int kx = 0; kx < 3; kx++)
                acc += w[ky * 3 + kx] * t[(y + ky) * 34 + (x + kx)];
        dst[i] += acc * scv + bv;
    }
}

// ---------------- launcher ----------------
extern "C" void kernel_launch(void* const* d_in, const int* in_sizes, int n_in,
                              void* d_out, int out_size)
{
    (void)in_sizes; (void)n_in; (void)out_size;
    const float* x      = (const float*)d_in[0];
    const float* W_cv1  = (const float*)d_in[1];
    const float* s_cv1  = (const float*)d_in[2];
    const float* b_cv1  = (const float*)d_in[3];
    const float* W_qkv  = (const float*)d_in[4];
    const float* s_qkv  = (const float*)d_in[5];
    const float* b_qkv  = (const float*)d_in[6];
    const float* W_proj = (const float*)d_in[7];
    const float* s_proj = (const float*)d_in[8];
    const float* b_proj = (const float*)d_in[9];
    const float* W_pe   = (const float*)d_in[10];
    const float* s_pe   = (const float*)d_in[11];
    const float* b_pe   = (const float*)d_in[12];
    const float* W_ffn1 = (const float*)d_in[13];
    const float* s_ffn1 = (const float*)d_in[14];
    const float* b_ffn1 = (const float*)d_in[15];
    const float* W_ffn2 = (const float*)d_in[16];
    const float* s_ffn2 = (const float*)d_in[17];
    const float* b_ffn2 = (const float*)d_in[18];
    const float* W_cv2  = (const float*)d_in[19];
    const float* s_cv2  = (const float*)d_in[20];
    const float* b_cv2  = (const float*)d_in[21];

    static float *y1 = nullptr, *qk = nullptr, *xab = nullptr, *ffb = nullptr;
    if (!y1) {
        cudaGetSymbolAddress((void**)&y1,  g_y1);
        cudaGetSymbolAddress((void**)&qk,  g_qkv);
        cudaGetSymbolAddress((void**)&xab, g_xa);
        cudaGetSymbolAddress((void**)&ffb, g_ff);
        cudaFuncSetAttribute(attn_kernel,
                             cudaFuncAttributeMaxDynamicSharedMemorySize, 199168);
    }
    float* bb = y1 + 256 * NPIX;   // bb view inside y1 (batch stride 512*NPIX)
    float* out = (float*)d_out;

    dim3 blk(256);

    // cv1: x(512) -> y1(512) [a;bb], SiLU
    gemm1x1<<<dim3(16, 4, BSZ), blk>>>(x, 512 * NPIX, 512, W_cv1, s_cv1, b_cv1,
                                       nullptr, 0, y1, 512 * NPIX, 1);
    // qkv: bb(256) -> qkv(512)
    gemm1x1<<<dim3(16, 4, BSZ), blk>>>(bb, 512 * NPIX, 256, W_qkv, s_qkv, b_qkv,
                                       nullptr, 0, qk, 512 * NPIX, 0);
    // attention -> xa
    attn_kernel<<<dim3(64, 64), blk, 199168>>>(qk, xab);
    // PE depthwise conv on v, adds into xa
    dwconv_pe<<<dim3(256, BSZ), blk>>>(qk, W_pe, s_pe, b_pe, xab);
    // proj: xa(256) -> bb += proj (in-place residual)
    gemm1x1<<<dim3(16, 2, BSZ), blk>>>(xab, 256 * NPIX, 256, W_proj, s_proj, b_proj,
                                       bb, 512 * NPIX, bb, 512 * NPIX, 0);
    // ffn1: bb(256) -> ff(512), SiLU
    gemm1x1<<<dim3(16, 4, BSZ), blk>>>(bb, 512 * NPIX, 256, W_ffn1, s_ffn1, b_ffn1,
                                       nullptr, 0, ffb, 512 * NPIX, 1);
    // ffn2: ff(512) -> bb += ffn2 (in-place residual)
    gemm1x1<<<dim3(16, 2, BSZ), blk>>>(ffb, 512 * NPIX, 512, W_ffn2, s_ffn2, b_ffn2,
                                       bb, 512 * NPIX, bb, 512 * NPIX, 0);
    // cv2: y1(=[a;bb], 512) -> out(512), SiLU
    gemm1x1<<<dim3(16, 4, BSZ), blk>>>(y1, 512 * NPIX, 512, W_cv2, s_cv2, b_cv2,
                                       nullptr, 0, out, 512 * NPIX, 1);
}

// round 2
// speedup vs baseline: 1.0861x; 1.0861x over previous
#include <cuda_runtime.h>

#define BSZ 16
#define NPIX 1024
#define SCALE_ATT 0.17677669529663687f

// ---------------- static scratch ----------------
__device__ float g_f512 [BSZ * 512 * NPIX]; // cv1 f32 out (ch 256-511 = bb residual)
__device__ float g_hi512[BSZ * 512 * NPIX]; // concat hi: a(0-255) | bb/bb2/bb3(256-511)
__device__ float g_lo512[BSZ * 512 * NPIX];
__device__ float g_qkv  [BSZ * 512 * NPIX];
__device__ float g_xaf  [BSZ * 256 * NPIX];
__device__ float g_xahi [BSZ * 256 * NPIX];
__device__ float g_xalo [BSZ * 256 * NPIX];
__device__ float g_ffhi [BSZ * 512 * NPIX];
__device__ float g_fflo [BSZ * 512 * NPIX];
__device__ float g_xhi  [BSZ * 512 * NPIX];
__device__ float g_xlo  [BSZ * 512 * NPIX];
__device__ float g_whi  [983040];
__device__ float g_wlo  [983040];

__device__ __forceinline__ float silu_f(float v) {
    return v / (1.0f + __expf(-v));
}

__device__ __forceinline__ float tf32_rna(float x) {
    unsigned u;
    asm("cvt.rna.tf32.f32 %0, %1;" : "=r"(u) : "f"(x));
    return __uint_as_float(u);
}

__device__ __forceinline__ void split2(float v, float& hi, float& lo) {
    hi = tf32_rna(v);
    lo = tf32_rna(v - hi);
}

__device__ __forceinline__ void mma_tf32(float* c, const unsigned* a, const unsigned* b) {
    asm volatile(
        "mma.sync.aligned.m16n8k8.row.col.f32.tf32.tf32.f32 "
        "{%0,%1,%2,%3}, {%4,%5,%6,%7}, {%8,%9}, {%0,%1,%2,%3};\n"
        : "+f"(c[0]), "+f"(c[1]), "+f"(c[2]), "+f"(c[3])
        : "r"(a[0]), "r"(a[1]), "r"(a[2]), "r"(a[3]), "r"(b[0]), "r"(b[1]));
}

__device__ __forceinline__ void cpa16(void* sdst, const void* gsrc) {
    unsigned s = (unsigned)__cvta_generic_to_shared(sdst);
    asm volatile("cp.async.ca.shared.global [%0], [%1], 16;" :: "r"(s), "l"(gsrc));
}

// ---------------- split kernel (fp32 -> tf32 hi + lo) ----------------
__global__ void split_k(const float4* __restrict__ src, float4* __restrict__ hi,
                        float4* __restrict__ lo, int n4)
{
    int i = blockIdx.x * 256 + threadIdx.x;
    if (i < n4) {
        float4 v = src[i];
        float4 h, l;
        split2(v.x, h.x, l.x); split2(v.y, h.y, l.y);
        split2(v.z, h.z, l.z); split2(v.w, h.w, l.w);
        hi[i] = h; lo[i] = l;
    }
}

// ---------------- tf32 tensor-core GEMM (3xTF32 split) ----------------
#define AST 20
#define BST 136
#define A_SZ (128 * AST)
#define B_SZ (16 * BST)
#define STG (2 * A_SZ + 2 * B_SZ)

__global__ __launch_bounds__(256, 2) void gemm_tf32(
    const float* __restrict__ Xh, const float* __restrict__ Xl, long xbs, int Cin,
    const float* __restrict__ Wh, const float* __restrict__ Wl,
    const float* __restrict__ sc, const float* __restrict__ bi,
    const float* __restrict__ res, long rbs,
    float* __restrict__ outf, long ofbs,
    float* __restrict__ outh, float* __restrict__ outl, long osbs, int act)
{
    extern __shared__ float sm[];
    const int b  = blockIdx.z;
    const int m0 = blockIdx.y * 128;
    const int n0 = blockIdx.x * 128;
    const int tid  = threadIdx.x;
    const int warp = tid >> 5;
    const int lane = tid & 31;
    const int g   = lane >> 2;
    const int tig = lane & 3;
    const int wm = warp >> 2;
    const int wn = warp & 3;

    const float* Xhb = Xh + (size_t)b * xbs;
    const float* Xlb = Xl + (size_t)b * xbs;

    float acc[4][4][4];
#pragma unroll
    for (int f = 0; f < 4; f++)
#pragma unroll
        for (int fn = 0; fn < 4; fn++)
#pragma unroll
            for (int q = 0; q < 4; q++) acc[f][fn][q] = 0.0f;

    auto issue_stage = [&](int s, int buf) {
        float* Ah = sm + buf * STG;
        float* Al = Ah + A_SZ;
        float* Bh = Al + A_SZ;
        float* Bl = Bh + B_SZ;
        int k0 = s * 16;
#pragma unroll
        for (int r = 0; r < 2; r++) {
            int c  = tid + 256 * r;
            int m  = c >> 2, kc = (c & 3) * 4;
            cpa16(Ah + m * AST + kc, Wh + (size_t)(m0 + m) * Cin + k0 + kc);
            cpa16(Al + m * AST + kc, Wl + (size_t)(m0 + m) * Cin + k0 + kc);
            int k  = c >> 5, nc = (c & 31) * 4;
            cpa16(Bh + k * BST + nc, Xhb + (size_t)(k0 + k) * NPIX + n0 + nc);
            cpa16(Bl + k * BST + nc, Xlb + (size_t)(k0 + k) * NPIX + n0 + nc);
        }
        asm volatile("cp.async.commit_group;");
    };

    const int nst = Cin >> 4;
    issue_stage(0, 0);

    for (int s = 0; s < nst; s++) {
        bool more = (s + 1 < nst);
        if (more) issue_stage(s + 1, (s + 1) & 1);
        if (more) asm volatile("cp.async.wait_group 1;");
        else      asm volatile("cp.async.wait_group 0;");
        __syncthreads();

        const float* Ah = sm + (s & 1) * STG;
        const float* Al = Ah + A_SZ;
        const float* Bh = Al + A_SZ;
        const float* Bl = Bh + B_SZ;

#pragma unroll
        for (int ks = 0; ks < 2; ks++) {
            const int kk = ks * 8;
            unsigned bh[4][2], bl[4][2];
#pragma unroll
            for (int fn = 0; fn < 4; fn++) {
                int n = wn * 32 + fn * 8 + g;
                bh[fn][0] = __float_as_uint(Bh[(tig + kk) * BST + n]);
                bh[fn][1] = __float_as_uint(Bh[(tig + 4 + kk) * BST + n]);
                bl[fn][0] = __float_as_uint(Bl[(tig + kk) * BST + n]);
                bl[fn][1] = __float_as_uint(Bl[(tig + 4 + kk) * BST + n]);
            }
#pragma unroll
            for (int f = 0; f < 4; f++) {
                int mr = wm * 64 + f * 16 + g;
                unsigned ah[4], al[4];
                ah[0] = __float_as_uint(Ah[mr * AST + tig + kk]);
                ah[1] = __float_as_uint(Ah[(mr + 8) * AST + tig + kk]);
                ah[2] = __float_as_uint(Ah[mr * AST + tig + 4 + kk]);
                ah[3] = __float_as_uint(Ah[(mr + 8) * AST + tig + 4 + kk]);
                al[0] = __float_as_uint(Al[mr * AST + tig + kk]);
                al[1] = __float_as_uint(Al[(mr + 8) * AST + tig + kk]);
                al[2] = __float_as_uint(Al[mr * AST + tig + 4 + kk]);
                al[3] = __float_as_uint(Al[(mr + 8) * AST + tig + 4 + kk]);
#pragma unroll
                for (int fn = 0; fn < 4; fn++) {
                    mma_tf32(acc[f][fn], ah, bh[fn]);
                    mma_tf32(acc[f][fn], ah, bl[fn]);
                    mma_tf32(acc[f][fn], al, bh[fn]);
                }
            }
        }
        __syncthreads();
    }

#pragma unroll
    for (int f = 0; f < 4; f++) {
        int m = m0 + wm * 64 + f * 16 + g;
        float s0 = sc[m],     b0 = bi[m];
        float s1 = sc[m + 8], b1 = bi[m + 8];
#pragma unroll
        for (int fn = 0; fn < 4; fn++) {
            int n = n0 + wn * 32 + fn * 8 + 2 * tig;
            float v00 = acc[f][fn][0] * s0 + b0;
            float v01 = acc[f][fn][1] * s0 + b0;
            float v10 = acc[f][fn][2] * s1 + b1;
            float v11 = acc[f][fn][3] * s1 + b1;
            if (res) {
                float2 ra = *(const float2*)(res + (size_t)b * rbs + (size_t)m * NPIX + n);
                float2 rb = *(const float2*)(res + (size_t)b * rbs + (size_t)(m + 8) * NPIX + n);
                v00 += ra.x; v01 += ra.y; v10 += rb.x; v11 += rb.y;
            }
            if (act) {
                v00 = silu_f(v00); v01 = silu_f(v01);
                v10 = silu_f(v10); v11 = silu_f(v11);
            }
            if (outf) {
                *(float2*)(outf + (size_t)b * ofbs + (size_t)m * NPIX + n) = make_float2(v00, v01);
                *(float2*)(outf + (size_t)b * ofbs + (size_t)(m + 8) * NPIX + n) = make_float2(v10, v11);
            }
            if (outh) {
                float h00, l00, h01, l01, h10, l10, h11, l11;
                split2(v00, h00, l00); split2(v01, h01, l01);
                split2(v10, h10, l10); split2(v11, h11, l11);
                *(float2*)(outh + (size_t)b * osbs + (size_t)m * NPIX + n) = make_float2(h00, h01);
                *(float2*)(outh + (size_t)b * osbs + (size_t)(m + 8) * NPIX + n) = make_float2(h10, h11);
                *(float2*)(outl + (size_t)b * osbs + (size_t)m * NPIX + n) = make_float2(l00, l01);
                *(float2*)(outl + (size_t)b * osbs + (size_t)(m + 8) * NPIX + n) = make_float2(l10, l11);
            }
        }
    }
}

// ---------------- attention (fp32) ----------------
__global__ __launch_bounds__(256) void attn_kernel(
    const float* __restrict__ qkv, float* __restrict__ xa)
{
    extern __shared__ float smn[];
    float* KV = smn;
    float* S  = smn + 32 * NPIX;
    float* Qs = S + 16 * 1032;

    const int tid  = threadIdx.x;
    const int warp = tid >> 5;
    const int lane = tid & 31;
    const int bh = blockIdx.y;
    const int r0 = blockIdx.x * 16;
    const float* base = qkv + (size_t)bh * 128 * NPIX;

    {
        const float4* src = (const float4*)(base + 32 * NPIX);
        float4* dst = (float4*)KV;
#pragma unroll
        for (int i = 0; i < 32; i++) dst[tid + 256 * i] = src[tid + 256 * i];
    }
    for (int i = tid; i < 16 * 32; i += 256) {
        int r = i >> 5, d = i & 31;
        Qs[i] = base[(size_t)d * NPIX + r0 + r];
    }
    __syncthreads();

    {
        const int ra = warp * 2, rb = ra + 1;
        float qa[32], qb[32];
#pragma unroll
        for (int d = 0; d < 32; d++) { qa[d] = Qs[ra * 32 + d]; qb[d] = Qs[rb * 32 + d]; }

#pragma unroll 1
        for (int j = 0; j < 32; j += 2) {
            int m0 = lane + 32 * j;
            float a0 = 0.f, a1 = 0.f, b0 = 0.f, b1 = 0.f;
#pragma unroll
            for (int d = 0; d < 32; d++) {
                float k0 = KV[d * NPIX + m0];
                float k1 = KV[d * NPIX + m0 + 32];
                a0 += qa[d] * k0; a1 += qa[d] * k1;
                b0 += qb[d] * k0; b1 += qb[d] * k1;
            }
            S[ra * 1032 + m0]      = a0 * SCALE_ATT;
            S[ra * 1032 + m0 + 32] = a1 * SCALE_ATT;
            S[rb * 1032 + m0]      = b0 * SCALE_ATT;
            S[rb * 1032 + m0 + 32] = b1 * SCALE_ATT;
        }

#pragma unroll
        for (int rr = 0; rr < 2; rr++) {
            int r = ra + rr;
            float v[32];
            float mx = -1e30f;
#pragma unroll
            for (int j = 0; j < 32; j++) {
                v[j] = S[r * 1032 + lane + 32 * j];
                mx = fmaxf(mx, v[j]);
            }
#pragma unroll
            for (int o = 16; o > 0; o >>= 1)
                mx = fmaxf(mx, __shfl_xor_sync(0xffffffffu, mx, o));
            float sum = 0.f;
#pragma unroll
            for (int j = 0; j < 32; j++) { v[j] = __expf(v[j] - mx); sum += v[j]; }
#pragma unroll
            for (int o = 16; o > 0; o >>= 1)
                sum += __shfl_xor_sync(0xffffffffu, sum, o);
            float inv = 1.0f / sum;
#pragma unroll
            for (int j = 0; j < 32; j++) S[r * 1032 + lane + 32 * j] = v[j] * inv;
        }
    }
    __syncthreads();

    float acc[8] = {0, 0, 0, 0, 0, 0, 0, 0};
    const int pr = tid >> 3;
    const int pd = (tid & 7) << 3;
    float* Vt = KV;

    for (int mt = 0; mt < 8; mt++) {
#pragma unroll
        for (int i = 0; i < 32; i++) {
            int idx = tid + 256 * i;
            int d = idx >> 7, mm = idx & 127;
            Vt[mm * 68 + d] = base[(size_t)(64 + d) * NPIX + mt * 128 + mm];
        }
        __syncthreads();
        if (tid < 128) {
            const float* Srow = S + pr * 1032 + mt * 128;
#pragma unroll 4
            for (int mm = 0; mm < 128; mm++) {
                float p = Srow[mm];
                const float* vp = Vt + mm * 68 + pd;
                float4 v0 = *(const float4*)vp;
                float4 v1 = *(const float4*)(vp + 4);
                acc[0] += p * v0.x; acc[1] += p * v0.y;
                acc[2] += p * v0.z; acc[3] += p * v0.w;
                acc[4] += p * v1.x; acc[5] += p * v1.y;
                acc[6] += p * v1.z; acc[7] += p * v1.w;
            }
        }
        __syncthreads();
    }
    if (tid < 128) {
#pragma unroll
        for (int k = 0; k < 8; k++)
            xa[(size_t)(bh * 64 + pd + k) * NPIX + r0 + pr] = acc[k];
    }
}

// ---------------- depthwise 3x3 PE conv -> xa hi/lo ----------------
__global__ __launch_bounds__(256) void dwconv_pe(
    const float* __restrict__ qkv, const float* __restrict__ Wpe,
    const float* __restrict__ s, const float* __restrict__ bi,
    const float* __restrict__ xaf,
    float* __restrict__ xahi, float* __restrict__ xalo)
{
    __shared__ float t[34 * 34];
    const int c = blockIdx.x;
    const int b = blockIdx.y;
    const int qc = ((c >> 6) * 128) + 64 + (c & 63);
    const float* src = qkv + ((size_t)b * 512 + qc) * NPIX;
    const int tid = threadIdx.x;

    for (int i = tid; i < 34 * 34; i += 256) t[i] = 0.0f;
    __syncthreads();
    for (int i = tid; i < NPIX; i += 256) {
        int y = i >> 5, x = i & 31;
        t[(y + 1) * 34 + (x + 1)] = src[i];
    }
    __syncthreads();

    float w[9];
#pragma unroll
    for (int i = 0; i < 9; i++) w[i] = Wpe[c * 9 + i];
    const float scv = s[c], bv = bi[c];
    const size_t off = ((size_t)b * 256 + c) * NPIX;

    for (int i = tid; i < NPIX; i += 256) {
        int y = i >> 5, x = i & 31;
        float acc = 0.0f;
#pragma unroll
        for (int ky = 0; ky < 3; ky++)
#pragma unroll
            for (int kx = 0; kx < 3; kx++)
                acc += w[ky * 3 + kx] * t[(y + ky) * 34 + (x + kx)];
        float v = xaf[off + i] + acc * scv + bv;
        float h, l;
        split2(v, h, l);
        xahi[off + i] = h;
        xalo[off + i] = l;
    }
}

// ---------------- launcher ----------------
extern "C" void kernel_launch(void* const* d_in, const int* in_sizes, int n_in,
                              void* d_out, int out_size)
{
    (void)in_sizes; (void)n_in; (void)out_size;
    const float* x      = (const float*)d_in[0];
    const float* W_cv1  = (const float*)d_in[1];
    const float* s_cv1  = (const float*)d_in[2];
    const float* b_cv1  = (const float*)d_in[3];
    const float* W_qkv  = (const float*)d_in[4];
    const float* s_qkv  = (const float*)d_in[5];
    const float* b_qkv  = (const float*)d_in[6];
    const float* W_proj = (const float*)d_in[7];
    const float* s_proj = (const float*)d_in[8];
    const float* b_proj = (const float*)d_in[9];
    const float* W_pe   = (const float*)d_in[10];
    const float* s_pe   = (const float*)d_in[11];
    const float* b_pe   = (const float*)d_in[12];
    const float* W_ffn1 = (const float*)d_in[13];
    const float* s_ffn1 = (const float*)d_in[14];
    const float* b_ffn1 = (const float*)d_in[15];
    const float* W_ffn2 = (const float*)d_in[16];
    const float* s_ffn2 = (const float*)d_in[17];
    const float* b_ffn2 = (const float*)d_in[18];
    const float* W_cv2  = (const float*)d_in[19];
    const float* s_cv2  = (const float*)d_in[20];
    const float* b_cv2  = (const float*)d_in[21];

    static float *f512 = nullptr, *hi512, *lo512, *qk, *xaf, *xahi, *xalo,
                 *ffhi, *fflo, *xhi, *xlo, *whi, *wlo;
    static const int GEMM_SMEM = STG * 2 * (int)sizeof(float);
    if (!f512) {
        cudaGetSymbolAddress((void**)&f512,  g_f512);
        cudaGetSymbolAddress((void**)&hi512, g_hi512);
        cudaGetSymbolAddress((void**)&lo512, g_lo512);
        cudaGetSymbolAddress((void**)&qk,    g_qkv);
        cudaGetSymbolAddress((void**)&xaf,   g_xaf);
        cudaGetSymbolAddress((void**)&xahi,  g_xahi);
        cudaGetSymbolAddress((void**)&xalo,  g_xalo);
        cudaGetSymbolAddress((void**)&ffhi,  g_ffhi);
        cudaGetSymbolAddress((void**)&fflo,  g_fflo);
        cudaGetSymbolAddress((void**)&xhi,   g_xhi);
        cudaGetSymbolAddress((void**)&xlo,   g_xlo);
        cudaGetSymbolAddress((void**)&whi,   g_whi);
        cudaGetSymbolAddress((void**)&wlo,   g_wlo);
        cudaFuncSetAttribute(attn_kernel,
                             cudaFuncAttributeMaxDynamicSharedMemorySize, 199168);
        cudaFuncSetAttribute(gemm_tf32,
                             cudaFuncAttributeMaxDynamicSharedMemorySize, GEMM_SMEM);
    }
    float* out = (float*)d_out;
    dim3 blk(256);
    const long S512 = 512 * NPIX, S256 = 256 * NPIX;

    {
        int n4 = BSZ * 512 * NPIX / 4;
        split_k<<<(n4 + 255) / 256, blk>>>((const float4*)x, (float4*)xhi, (float4*)xlo, n4);
        struct WS { const float* w; int off, cnt; } ws[6] = {
            {W_cv1, 0, 262144}, {W_qkv, 262144, 131072}, {W_proj, 393216, 65536},
            {W_ffn1, 458752, 131072}, {W_ffn2, 589824, 131072}, {W_cv2, 720896, 262144}};
        for (int i = 0; i < 6; i++) {
            int c4 = ws[i].cnt / 4;
            split_k<<<(c4 + 255) / 256, blk>>>((const float4*)ws[i].w,
                (float4*)(whi + ws[i].off), (float4*)(wlo + ws[i].off), c4);
        }
    }

    // cv1: x(512) -> f32 + hi/lo concat, SiLU
    gemm_tf32<<<dim3(8, 4, BSZ), blk, GEMM_SMEM>>>(
        xhi, xlo, S512, 512, whi, wlo, s_cv1, b_cv1,
        nullptr, 0, f512, S512, hi512, lo512, S512, 1);
    // qkv: bb(256) -> qkv f32
    gemm_tf32<<<dim3(8, 4, BSZ), blk, GEMM_SMEM>>>(
        hi512 + S256, lo512 + S256, S512, 256, whi + 262144, wlo + 262144,
        s_qkv, b_qkv, nullptr, 0, qk, S512, nullptr, nullptr, 0, 0);
    // attention -> xaf
    attn_kernel<<<dim3(64, 64), blk, 199168>>>(qk, xaf);
    // PE dwconv: xaf + conv(v) -> xa hi/lo
    dwconv_pe<<<dim3(256, BSZ), blk>>>(qk, W_pe, s_pe, b_pe, xaf, xahi, xalo);
    // proj: xa(256) + bb -> bb2 f32(in place) + hi/lo
    gemm_tf32<<<dim3(8, 2, BSZ), blk, GEMM_SMEM>>>(
        xahi, xalo, S256, 256, whi + 393216, wlo + 393216, s_proj, b_proj,
        f512 + S256, S512, f512 + S256, S512, hi512 + S256, lo512 + S256, S512, 0);
    // ffn1: bb2(256) -> ff hi/lo (512), SiLU
    gemm_tf32<<<dim3(8, 4, BSZ), blk, GEMM_SMEM>>>(
        hi512 + S256, lo512 + S256, S512, 256, whi + 458752, wlo + 458752,
        s_ffn1, b_ffn1, nullptr, 0, nullptr, 0, ffhi, fflo, S512, 1);
    // ffn2: ff(512) + bb2 -> bb3 hi/lo
    gemm_tf32<<<dim3(8, 2, BSZ), blk, GEMM_SMEM>>>(
        ffhi, fflo, S512, 512, whi + 589824, wlo + 589824, s_ffn2, b_ffn2,
        f512 + S256, S512, nullptr, 0, hi512 + S256, lo512 + S256, S512, 0);
    // cv2: concat(512) -> out, SiLU
    gemm_tf32<<<dim3(8, 4, BSZ), blk, GEMM_SMEM>>>(
        hi512, lo512, S512, 512, whi + 720896, wlo + 720896, s_cv2, b_cv2,
        nullptr, 0, out, S512, nullptr, nullptr, 0, 1);
}

// round 4
// speedup vs baseline: 1.2550x; 1.1554x over previous
#include <cuda_runtime.h>
#include <cuda_bf16.h>
#include <cstdint>

#define BSZ 16
#define NPIX 1024
#define SCALE_ATT 0.17677669529663687f

// ---------------- static scratch ----------------
__device__ __align__(16) __nv_bfloat16 g_xh[BSZ * 512 * NPIX], g_xl[BSZ * 512 * NPIX];
__device__ __align__(16) __nv_bfloat16 g_ch[BSZ * 512 * NPIX], g_cl[BSZ * 512 * NPIX];
__device__ __align__(16) __nv_bfloat16 g_fh[BSZ * 512 * NPIX], g_fl[BSZ * 512 * NPIX];
__device__ __align__(16) __nv_bfloat16 g_ah[BSZ * 256 * NPIX], g_al[BSZ * 256 * NPIX];
__device__ __align__(16) float g_bbf [BSZ * 256 * NPIX];  // bb chain f32 (cm)
__device__ __align__(16) float g_qkvb[BSZ * 512 * NPIX];  // qkv f32 (cm)
__device__ __align__(16) float g_xaf [BSZ * 256 * NPIX];  // attn out f32 (cm)
__device__ __align__(16) __nv_bfloat16 g_wh[983040], g_wl[983040];

__device__ __forceinline__ float silu_f(float v) {
    return v / (1.0f + __expf(-v));
}

__device__ __forceinline__ void bsplit(float v, __nv_bfloat16& h, __nv_bfloat16& l) {
    h = __float2bfloat16(v);
    l = __float2bfloat16(v - __bfloat162float(h));
}

__device__ __forceinline__ uint32_t s2u(const void* p) {
    uint32_t a;
    asm("{ .reg .u64 t; cvta.to.shared.u64 t, %1; cvt.u32.u64 %0, t; }" : "=r"(a) : "l"(p));
    return a;
}

__device__ __forceinline__ void cpa(uint32_t saddr, const void* g) {
    asm volatile("cp.async.cg.shared.global [%0], [%1], 16;" :: "r"(saddr), "l"(g));
}

__device__ __forceinline__ void ldsm_x4(uint32_t* r, uint32_t addr) {
    asm volatile("ldmatrix.sync.aligned.m8n8.x4.shared.b16 {%0,%1,%2,%3}, [%4];"
                 : "=r"(r[0]), "=r"(r[1]), "=r"(r[2]), "=r"(r[3]) : "r"(addr));
}

__device__ __forceinline__ void ldsm_x2t(uint32_t* r, uint32_t addr) {
    asm volatile("ldmatrix.sync.aligned.m8n8.x2.trans.shared.b16 {%0,%1}, [%2];"
                 : "=r"(r[0]), "=r"(r[1]) : "r"(addr));
}

__device__ __forceinline__ void mma_bf16(float* c, const uint32_t* a, const uint32_t* b) {
    asm volatile(
        "mma.sync.aligned.m16n8k16.row.col.f32.bf16.bf16.f32 "
        "{%0,%1,%2,%3}, {%4,%5,%6,%7}, {%8,%9}, {%0,%1,%2,%3};\n"
        : "+f"(c[0]), "+f"(c[1]), "+f"(c[2]), "+f"(c[3])
        : "r"(a[0]), "r"(a[1]), "r"(a[2]), "r"(a[3]), "r"(b[0]), "r"(b[1]));
}

// ---------------- bf16 tensor-core GEMM (3-pass split) ----------------
// D[m, n] = act(scale*((Wh+Wl)·(Xh+Xl)) + bias [+ res]) over K.
// A = W [Cout][K] row-major bf16 hi/lo; B = X [K][NPIX] row-major bf16 hi/lo.
// Block tile: 128(M) x 128(N), BK=16. 8 warps, each 64x32.
#define A_BYTES (128 * 48)              // A tile, 48B row stride
#define B_BYTES (16 * 256)              // B tile, swizzled
#define STAGE_B (2 * A_BYTES + 2 * B_BYTES)  // 20480
#define GSMEM   (2 * STAGE_B)                // 40960

__global__ __launch_bounds__(256, 2) void gemm_bf16(
    const __nv_bfloat16* __restrict__ Xh, const __nv_bfloat16* __restrict__ Xl, long xbs,
    int K,
    const __nv_bfloat16* __restrict__ Wh, const __nv_bfloat16* __restrict__ Wl,
    const float* __restrict__ sc, const float* __restrict__ bi,
    const float* __restrict__ res, long rbs,
    float* __restrict__ outf, long ofbs, int ofoff,
    __nv_bfloat16* __restrict__ oh, __nv_bfloat16* __restrict__ ol, long ohbs,
    int act)
{
    extern __shared__ __align__(16) char smem[];
    const uint32_t sb = s2u(smem);
    const int tid  = threadIdx.x;
    const int warp = tid >> 5;
    const int lane = tid & 31;
    const int g    = lane >> 2;
    const int tig  = lane & 3;
    const int wm   = warp >> 2;   // 0..1
    const int wn   = warp & 3;    // 0..3
    const int b  = blockIdx.z;
    const int n0 = blockIdx.x * 128;
    const int m0 = blockIdx.y * 128;

    const __nv_bfloat16* Xhb = Xh + (size_t)b * xbs;
    const __nv_bfloat16* Xlb = Xl + (size_t)b * xbs;

    float acc[4][4][4];
#pragma unroll
    for (int f = 0; f < 4; f++)
#pragma unroll
        for (int fn = 0; fn < 4; fn++)
#pragma unroll
            for (int q = 0; q < 4; q++) acc[f][fn][q] = 0.0f;

    // cp.async one stage: 4 chunks per thread (Ah, Al, Bh, Bl)
    const int am = tid >> 1, ahh = tid & 1;       // A: row m, k-half
    const int bk = tid >> 4, bnc = tid & 15;      // B: row k, n-chunk
    const uint32_t a_dst = am * 48 + ahh * 16;
    const uint32_t b_dst = bk * 256 + (((uint32_t)(bnc ^ (bk & 7))) << 4);

    auto issue = [&](int c, int buf) {
        const uint32_t st = sb + buf * STAGE_B;
        const int k0 = c * 16;
        cpa(st + a_dst,           Wh + (size_t)(m0 + am) * K + k0 + ahh * 8);
        cpa(st + A_BYTES + a_dst, Wl + (size_t)(m0 + am) * K + k0 + ahh * 8);
        cpa(st + 2 * A_BYTES + b_dst,           Xhb + (size_t)(k0 + bk) * NPIX + n0 + bnc * 8);
        cpa(st + 2 * A_BYTES + B_BYTES + b_dst, Xlb + (size_t)(k0 + bk) * NPIX + n0 + bnc * 8);
        asm volatile("cp.async.commit_group;");
    };

    const int nc = K >> 4;
    issue(0, 0);

    // ldmatrix address components (loop-invariant)
    const int arow  = wm * 64 + (lane & 15);
    const int akoff = (lane >> 4) * 16;
    const int blk   = lane & 15;

    for (int c = 0; c < nc; c++) {
        if (c + 1 < nc) {
            issue(c + 1, (c + 1) & 1);
            asm volatile("cp.async.wait_group 1;");
        } else {
            asm volatile("cp.async.wait_group 0;");
        }
        __syncthreads();

        const uint32_t st   = sb + (c & 1) * STAGE_B;
        const uint32_t Ah_s = st;
        const uint32_t Al_s = st + A_BYTES;
        const uint32_t Bh_s = st + 2 * A_BYTES;

        uint32_t a_h[4][4], a_l[4][4];
#pragma unroll
        for (int f = 0; f < 4; f++) {
            const uint32_t off = (uint32_t)(arow + f * 16) * 48 + akoff;
            ldsm_x4(a_h[f], Ah_s + off);
            ldsm_x4(a_l[f], Al_s + off);
        }
#pragma unroll
        for (int fn = 0; fn < 4; fn++) {
            const int ncb = wn * 4 + fn;
            const uint32_t bd = Bh_s + blk * 256 + (((uint32_t)(ncb ^ (blk & 7))) << 4);
            uint32_t b_h[2], b_l[2];
            ldsm_x2t(b_h, bd);
            ldsm_x2t(b_l, bd + B_BYTES);
#pragma unroll
            for (int f = 0; f < 4; f++) {
                mma_bf16(acc[f][fn], a_h[f], b_h);
                mma_bf16(acc[f][fn], a_h[f], b_l);
                mma_bf16(acc[f][fn], a_l[f], b_h);
            }
        }
        __syncthreads();
    }

    // ---------------- epilogue (channel-major) ----------------
    const bool do_f = (outf != nullptr) && (m0 >= ofoff);
#pragma unroll
    for (int f = 0; f < 4; f++) {
        const int m = m0 + wm * 64 + f * 16 + g;
        const float s0 = sc[m],     b0 = bi[m];
        const float s1 = sc[m + 8], b1 = bi[m + 8];
#pragma unroll
        for (int fn = 0; fn < 4; fn++) {
            const int n = n0 + wn * 32 + fn * 8 + 2 * tig;
            float v00 = acc[f][fn][0] * s0 + b0;
            float v01 = acc[f][fn][1] * s0 + b0;
            float v10 = acc[f][fn][2] * s1 + b1;
            float v11 = acc[f][fn][3] * s1 + b1;
            if (res) {
                float2 ra = *(const float2*)(res + (size_t)b * rbs + (size_t)m * NPIX + n);
                float2 rb = *(const float2*)(res + (size_t)b * rbs + (size_t)(m + 8) * NPIX + n);
                v00 += ra.x; v01 += ra.y; v10 += rb.x; v11 += rb.y;
            }
            if (act) {
                v00 = silu_f(v00); v01 = silu_f(v01);
                v10 = silu_f(v10); v11 = silu_f(v11);
            }
            if (do_f) {
                const int mo = m - ofoff;
                *(float2*)(outf + (size_t)b * ofbs + (size_t)mo * NPIX + n) = make_float2(v00, v01);
                *(float2*)(outf + (size_t)b * ofbs + (size_t)(mo + 8) * NPIX + n) = make_float2(v10, v11);
            }
            if (oh) {
                __nv_bfloat16 h00, l00, h01, l01, h10, l10, h11, l11;
                bsplit(v00, h00, l00); bsplit(v01, h01, l01);
                bsplit(v10, h10, l10); bsplit(v11, h11, l11);
                __nv_bfloat162* hp0 = (__nv_bfloat162*)(oh + (size_t)b * ohbs + (size_t)m * NPIX + n);
                __nv_bfloat162* hp1 = (__nv_bfloat162*)(oh + (size_t)b * ohbs + (size_t)(m + 8) * NPIX + n);
                __nv_bfloat162* lp0 = (__nv_bfloat162*)(ol + (size_t)b * ohbs + (size_t)m * NPIX + n);
                __nv_bfloat162* lp1 = (__nv_bfloat162*)(ol + (size_t)b * ohbs + (size_t)(m + 8) * NPIX + n);
                *hp0 = __nv_bfloat162(h00, h01);
                *hp1 = __nv_bfloat162(h10, h11);
                *lp0 = __nv_bfloat162(l00, l01);
                *lp1 = __nv_bfloat162(l10, l11);
            }
        }
    }
}

// ---------------- elementwise split fp32 -> bf16 hi/lo ----------------
__global__ void split_k(const float4* __restrict__ src, uint2* __restrict__ hi,
                        uint2* __restrict__ lo, int n4)
{
    int i = blockIdx.x * 256 + threadIdx.x;
    if (i < n4) {
        float4 v = src[i];
        __nv_bfloat16 h[4], l[4];
        bsplit(v.x, h[0], l[0]); bsplit(v.y, h[1], l[1]);
        bsplit(v.z, h[2], l[2]); bsplit(v.w, h[3], l[3]);
        hi[i] = *(uint2*)h;
        lo[i] = *(uint2*)l;
    }
}

// ---------------- attention (fp32, channel-major qkv) ----------------
__global__ __launch_bounds__(256) void attn_kernel(
    const float* __restrict__ qkv, float* __restrict__ xa)
{
    extern __shared__ float smn[];
    float* KV = smn;
    float* S  = smn + 32 * NPIX;
    float* Qs = S + 16 * 1032;

    const int tid  = threadIdx.x;
    const int warp = tid >> 5;
    const int lane = tid & 31;
    const int bh = blockIdx.y;
    const int r0 = blockIdx.x * 16;
    const float* base = qkv + (size_t)bh * 128 * NPIX;

    {
        const float4* src = (const float4*)(base + 32 * NPIX);
        float4* dst = (float4*)KV;
#pragma unroll
        for (int i = 0; i < 32; i++) dst[tid + 256 * i] = src[tid + 256 * i];
    }
    for (int i = tid; i < 16 * 32; i += 256) {
        int r = i >> 5, d = i & 31;
        Qs[i] = base[(size_t)d * NPIX + r0 + r];
    }
    __syncthreads();

    {
        const int ra = warp * 2, rb = ra + 1;
        float qa[32], qb[32];
#pragma unroll
        for (int d = 0; d < 32; d++) { qa[d] = Qs[ra * 32 + d]; qb[d] = Qs[rb * 32 + d]; }

#pragma unroll 1
        for (int j = 0; j < 32; j += 2) {
            int m0 = lane + 32 * j;
            float a0 = 0.f, a1 = 0.f, b0 = 0.f, b1 = 0.f;
#pragma unroll
            for (int d = 0; d < 32; d++) {
                float k0 = KV[d * NPIX + m0];
                float k1 = KV[d * NPIX + m0 + 32];
                a0 += qa[d] * k0; a1 += qa[d] * k1;
                b0 += qb[d] * k0; b1 += qb[d] * k1;
            }
            S[ra * 1032 + m0]      = a0 * SCALE_ATT;
            S[ra * 1032 + m0 + 32] = a1 * SCALE_ATT;
            S[rb * 1032 + m0]      = b0 * SCALE_ATT;
            S[rb * 1032 + m0 + 32] = b1 * SCALE_ATT;
        }

#pragma unroll
        for (int rr = 0; rr < 2; rr++) {
            int r = ra + rr;
            float v[32];
            float mx = -1e30f;
#pragma unroll
            for (int j = 0; j < 32; j++) {
                v[j] = S[r * 1032 + lane + 32 * j];
                mx = fmaxf(mx, v[j]);
            }
#pragma unroll
            for (int o = 16; o > 0; o >>= 1)
                mx = fmaxf(mx, __shfl_xor_sync(0xffffffffu, mx, o));
            float sum = 0.f;
#pragma unroll
            for (int j = 0; j < 32; j++) { v[j] = __expf(v[j] - mx); sum += v[j]; }
#pragma unroll
            for (int o = 16; o > 0; o >>= 1)
                sum += __shfl_xor_sync(0xffffffffu, sum, o);
            float inv = 1.0f / sum;
#pragma unroll
            for (int j = 0; j < 32; j++) S[r * 1032 + lane + 32 * j] = v[j] * inv;
        }
    }
    __syncthreads();

    float acc[8] = {0, 0, 0, 0, 0, 0, 0, 0};
    const int pr = tid >> 3;
    const int pd = (tid & 7) << 3;
    float* Vt = KV;

    for (int mt = 0; mt < 8; mt++) {
#pragma unroll
        for (int i = 0; i < 32; i++) {
            int idx = tid + 256 * i;
            int d = idx >> 7, mm = idx & 127;
            Vt[mm * 68 + d] = base[(size_t)(64 + d) * NPIX + mt * 128 + mm];
        }
        __syncthreads();
        if (tid < 128) {
            const float* Srow = S + pr * 1032 + mt * 128;
#pragma unroll 4
            for (int mm = 0; mm < 128; mm++) {
                float p = Srow[mm];
                const float* vp = Vt + mm * 68 + pd;
                float4 v0 = *(const float4*)vp;
                float4 v1 = *(const float4*)(vp + 4);
                acc[0] += p * v0.x; acc[1] += p * v0.y;
                acc[2] += p * v0.z; acc[3] += p * v0.w;
                acc[4] += p * v1.x; acc[5] += p * v1.y;
                acc[6] += p * v1.z; acc[7] += p * v1.w;
            }
        }
        __syncthreads();
    }
    if (tid < 128) {
#pragma unroll
        for (int k = 0; k < 8; k++)
            xa[(size_t)(bh * 64 + pd + k) * NPIX + r0 + pr] = acc[k];
    }
}

// ---------------- depthwise 3x3 PE -> xa bf16 hi/lo (cm) ----------------
__global__ __launch_bounds__(256) void dwconv_pe(
    const float* __restrict__ qkv, const float* __restrict__ Wpe,
    const float* __restrict__ s, const float* __restrict__ bi,
    const float* __restrict__ xaf,
    __nv_bfloat16* __restrict__ xah, __nv_bfloat16* __restrict__ xal)
{
    __shared__ float t[34 * 34];
    const int c = blockIdx.x;
    const int b = blockIdx.y;
    const int qc = ((c >> 6) * 128) + 64 + (c & 63);
    const float* src = qkv + ((size_t)b * 512 + qc) * NPIX;
    const int tid = threadIdx.x;

    for (int i = tid; i < 34 * 34; i += 256) t[i] = 0.0f;
    __syncthreads();
    for (int i = tid; i < NPIX; i += 256) {
        int y = i >> 5, x = i & 31;
        t[(y + 1) * 34 + (x + 1)] = src[i];
    }
    __syncthreads();

    float w[9];
#pragma unroll
    for (int i = 0; i < 9; i++) w[i] = Wpe[c * 9 + i];
    const float scv = s[c], bv = bi[c];
    const size_t off = ((size_t)b * 256 + c) * NPIX;

    for (int i = tid; i < NPIX; i += 256) {
        int y = i >> 5, x = i & 31;
        float acc = 0.0f;
#pragma unroll
        for (int ky = 0; ky < 3; ky++)
#pragma unroll
            for (int kx = 0; kx < 3; kx++)
                acc += w[ky * 3 + kx] * t[(y + ky) * 34 + (x + kx)];
        float v = xaf[off + i] + acc * scv + bv;
        __nv_bfloat16 h, l;
        bsplit(v, h, l);
        xah[off + i] = h;
        xal[off + i] = l;
    }
}

// ---------------- launcher ----------------
extern "C" void kernel_launch(void* const* d_in, const int* in_sizes, int n_in,
                              void* d_out, int out_size)
{
    (void)in_sizes; (void)n_in; (void)out_size;
    const float* x      = (const float*)d_in[0];
    const float* W_cv1  = (const float*)d_in[1];
    const float* s_cv1  = (const float*)d_in[2];
    const float* b_cv1  = (const float*)d_in[3];
    const float* W_qkv  = (const float*)d_in[4];
    const float* s_qkv  = (const float*)d_in[5];
    const float* b_qkv  = (const float*)d_in[6];
    const float* W_proj = (const float*)d_in[7];
    const float* s_proj = (const float*)d_in[8];
    const float* b_proj = (const float*)d_in[9];
    const float* W_pe   = (const float*)d_in[10];
    const float* s_pe   = (const float*)d_in[11];
    const float* b_pe   = (const float*)d_in[12];
    const float* W_ffn1 = (const float*)d_in[13];
    const float* s_ffn1 = (const float*)d_in[14];
    const float* b_ffn1 = (const float*)d_in[15];
    const float* W_ffn2 = (const float*)d_in[16];
    const float* s_ffn2 = (const float*)d_in[17];
    const float* b_ffn2 = (const float*)d_in[18];
    const float* W_cv2  = (const float*)d_in[19];
    const float* s_cv2  = (const float*)d_in[20];
    const float* b_cv2  = (const float*)d_in[21];

    static __nv_bfloat16 *xh = nullptr, *xl, *ch, *cl, *fh, *fl, *ah, *al, *wh, *wl;
    static float *bbf, *qkvb, *xaf;
    if (!xh) {
        cudaGetSymbolAddress((void**)&xh,  g_xh);
        cudaGetSymbolAddress((void**)&xl,  g_xl);
        cudaGetSymbolAddress((void**)&ch,  g_ch);
        cudaGetSymbolAddress((void**)&cl,  g_cl);
        cudaGetSymbolAddress((void**)&fh,  g_fh);
        cudaGetSymbolAddress((void**)&fl,  g_fl);
        cudaGetSymbolAddress((void**)&ah,  g_ah);
        cudaGetSymbolAddress((void**)&al,  g_al);
        cudaGetSymbolAddress((void**)&wh,  g_wh);
        cudaGetSymbolAddress((void**)&wl,  g_wl);
        cudaGetSymbolAddress((void**)&bbf,  g_bbf);
        cudaGetSymbolAddress((void**)&qkvb, g_qkvb);
        cudaGetSymbolAddress((void**)&xaf,  g_xaf);
        cudaFuncSetAttribute(attn_kernel,
                             cudaFuncAttributeMaxDynamicSharedMemorySize, 199168);
        cudaFuncSetAttribute(gemm_bf16,
                             cudaFuncAttributeMaxDynamicSharedMemorySize, GSMEM);
    }
    float* out = (float*)d_out;
    const long S512 = 512 * NPIX, S256 = 256 * NPIX;

    // --- splits: input x + all 6 weights ---
    {
        int n4 = BSZ * 512 * NPIX / 4;
        split_k<<<(n4 + 255) / 256, 256>>>((const float4*)x, (uint2*)xh, (uint2*)xl, n4);
        struct WS { const float* w; int off, cnt; } ws[6] = {
            {W_cv1, 0, 262144}, {W_qkv, 262144, 131072}, {W_proj, 393216, 65536},
            {W_ffn1, 458752, 131072}, {W_ffn2, 589824, 131072}, {W_cv2, 720896, 262144}};
        for (int i = 0; i < 6; i++) {
            int c4 = ws[i].cnt / 4;
            split_k<<<(c4 + 255) / 256, 256>>>((const float4*)ws[i].w,
                (uint2*)(wh + ws[i].off), (uint2*)(wl + ws[i].off), c4);
        }
    }

    // cv1: x(512) -> cat hi/lo [a|bb], f32 only for ch>=256 (bbf), SiLU
    gemm_bf16<<<dim3(8, 4, BSZ), 256, GSMEM>>>(
        xh, xl, S512, 512, wh, wl, s_cv1, b_cv1,
        nullptr, 0, bbf, S256, 256, ch, cl, S512, 1);
    // qkv: bb(256) -> qkv f32 cm
    gemm_bf16<<<dim3(8, 4, BSZ), 256, GSMEM>>>(
        ch + S256, cl + S256, S512, 256, wh + 262144, wl + 262144, s_qkv, b_qkv,
        nullptr, 0, qkvb, S512, 0, nullptr, nullptr, 0, 0);
    // attention -> xaf
    attn_kernel<<<dim3(64, 64), 256, 199168>>>(qkvb, xaf);
    // PE dwconv: xaf + conv(v) -> xa bf16 hi/lo
    dwconv_pe<<<dim3(256, BSZ), 256>>>(qkvb, W_pe, s_pe, b_pe, xaf, ah, al);
    // proj: xa(256) + bb -> bb2 f32 (in-place bbf) + hi/lo (cat ch256+)
    gemm_bf16<<<dim3(8, 2, BSZ), 256, GSMEM>>>(
        ah, al, S256, 256, wh + 393216, wl + 393216, s_proj, b_proj,
        bbf, S256, bbf, S256, 0, ch + S256, cl + S256, S512, 0);
    // ffn1: bb2(256) -> ff hi/lo (512), SiLU
    gemm_bf16<<<dim3(8, 4, BSZ), 256, GSMEM>>>(
        ch + S256, cl + S256, S512, 256, wh + 458752, wl + 458752, s_ffn1, b_ffn1,
        nullptr, 0, nullptr, 0, 0, fh, fl, S512, 1);
    // ffn2: ff(512) + bb2 -> bb3 hi/lo (cat ch256+)
    gemm_bf16<<<dim3(8, 2, BSZ), 256, GSMEM>>>(
        fh, fl, S512, 512, wh + 589824, wl + 589824, s_ffn2, b_ffn2,
        bbf, S256, nullptr, 0, 0, ch + S256, cl + S256, S512, 0);
    // cv2: cat(512) -> out f32 cm, SiLU
    gemm_bf16<<<dim3(8, 4, BSZ), 256, GSMEM>>>(
        ch, cl, S512, 512, wh + 720896, wl + 720896, s_cv2, b_cv2,
        nullptr, 0, out, S512, 0, nullptr, nullptr, 0, 1);
}

// round 5
// speedup vs baseline: 2.1258x; 1.6939x over previous
#include <cuda_runtime.h>
#include <cuda_bf16.h>
#include <cstdint>

#define BSZ 16
#define NPIX 1024
#define SCALE_ATT 0.17677669529663687f

// ---------------- static scratch ----------------
__device__ __align__(16) __nv_bfloat16 g_xh[BSZ * 512 * NPIX], g_xl[BSZ * 512 * NPIX];
__device__ __align__(16) __nv_bfloat16 g_ch[BSZ * 512 * NPIX], g_cl[BSZ * 512 * NPIX];
__device__ __align__(16) __nv_bfloat16 g_fh[BSZ * 512 * NPIX], g_fl[BSZ * 512 * NPIX];
__device__ __align__(16) __nv_bfloat16 g_ah[BSZ * 256 * NPIX], g_al[BSZ * 256 * NPIX];
__device__ __align__(16) float g_bbf [BSZ * 256 * NPIX];  // bb chain f32 (cm)
__device__ __align__(16) float g_qkvb[BSZ * 512 * NPIX];  // qkv f32 (cm)
__device__ __align__(16) float g_xaf [BSZ * 256 * NPIX];  // attn out f32 (cm)
__device__ __align__(16) __nv_bfloat16 g_wh[983040], g_wl[983040];

__device__ __forceinline__ float silu_f(float v) {
    return v / (1.0f + __expf(-v));
}

__device__ __forceinline__ void bsplit(float v, __nv_bfloat16& h, __nv_bfloat16& l) {
    h = __float2bfloat16(v);
    l = __float2bfloat16(v - __bfloat162float(h));
}

__device__ __forceinline__ uint32_t s2u(const void* p) {
    uint32_t a;
    asm("{ .reg .u64 t; cvta.to.shared.u64 t, %1; cvt.u32.u64 %0, t; }" : "=r"(a) : "l"(p));
    return a;
}

__device__ __forceinline__ void cpa(uint32_t saddr, const void* g) {
    asm volatile("cp.async.cg.shared.global [%0], [%1], 16;" :: "r"(saddr), "l"(g));
}

__device__ __forceinline__ void ldsm_x4(uint32_t* r, uint32_t addr) {
    asm volatile("ldmatrix.sync.aligned.m8n8.x4.shared.b16 {%0,%1,%2,%3}, [%4];"
                 : "=r"(r[0]), "=r"(r[1]), "=r"(r[2]), "=r"(r[3]) : "r"(addr));
}

__device__ __forceinline__ void ldsm_x2t(uint32_t* r, uint32_t addr) {
    asm volatile("ldmatrix.sync.aligned.m8n8.x2.trans.shared.b16 {%0,%1}, [%2];"
                 : "=r"(r[0]), "=r"(r[1]) : "r"(addr));
}

__device__ __forceinline__ void mma_bf16(float* c, const uint32_t* a, const uint32_t* b) {
    asm volatile(
        "mma.sync.aligned.m16n8k16.row.col.f32.bf16.bf16.f32 "
        "{%0,%1,%2,%3}, {%4,%5,%6,%7}, {%8,%9}, {%0,%1,%2,%3};\n"
        : "+f"(c[0]), "+f"(c[1]), "+f"(c[2]), "+f"(c[3])
        : "r"(a[0]), "r"(a[1]), "r"(a[2]), "r"(a[3]), "r"(b[0]), "r"(b[1]));
}

// ---------------- bf16 tensor-core GEMM (3-pass split, 3-stage pipe) ----------------
#define A_BYTES (128 * 48)
#define B_BYTES (16 * 256)
#define STAGE_B (2 * A_BYTES + 2 * B_BYTES)  // 20480
#define GSMEM   (3 * STAGE_B)                // 61440

__global__ __launch_bounds__(256, 2) void gemm_bf16(
    const __nv_bfloat16* __restrict__ Xh, const __nv_bfloat16* __restrict__ Xl, long xbs,
    int K,
    const __nv_bfloat16* __restrict__ Wh, const __nv_bfloat16* __restrict__ Wl,
    const float* __restrict__ sc, const float* __restrict__ bi,
    const float* __restrict__ res, long rbs,
    float* __restrict__ outf, long ofbs, int ofoff,
    __nv_bfloat16* __restrict__ oh, __nv_bfloat16* __restrict__ ol, long ohbs,
    int act)
{
    extern __shared__ __align__(16) char smem[];
    const uint32_t sb = s2u(smem);
    const int tid  = threadIdx.x;
    const int warp = tid >> 5;
    const int lane = tid & 31;
    const int g    = lane >> 2;
    const int tig  = lane & 3;
    const int wm   = warp >> 2;
    const int wn   = warp & 3;
    const int b  = blockIdx.z;
    const int n0 = blockIdx.x * 128;
    const int m0 = blockIdx.y * 128;

    const __nv_bfloat16* Xhb = Xh + (size_t)b * xbs;
    const __nv_bfloat16* Xlb = Xl + (size_t)b * xbs;

    float acc[4][4][4];
#pragma unroll
    for (int f = 0; f < 4; f++)
#pragma unroll
        for (int fn = 0; fn < 4; fn++)
#pragma unroll
            for (int q = 0; q < 4; q++) acc[f][fn][q] = 0.0f;

    const int am = tid >> 1, ahh = tid & 1;
    const int bk = tid >> 4, bnc = tid & 15;
    const uint32_t a_dst = am * 48 + ahh * 16;
    const uint32_t b_dst = bk * 256 + (((uint32_t)(bnc ^ (bk & 7))) << 4);

    auto issue = [&](int c, int buf) {
        const uint32_t st = sb + buf * STAGE_B;
        const int k0 = c * 16;
        cpa(st + a_dst,           Wh + (size_t)(m0 + am) * K + k0 + ahh * 8);
        cpa(st + A_BYTES + a_dst, Wl + (size_t)(m0 + am) * K + k0 + ahh * 8);
        cpa(st + 2 * A_BYTES + b_dst,           Xhb + (size_t)(k0 + bk) * NPIX + n0 + bnc * 8);
        cpa(st + 2 * A_BYTES + B_BYTES + b_dst, Xlb + (size_t)(k0 + bk) * NPIX + n0 + bnc * 8);
        asm volatile("cp.async.commit_group;");
    };

    const int nc = K >> 4;
    issue(0, 0);
    if (nc > 1) issue(1, 1);

    const int arow  = wm * 64 + (lane & 15);
    const int akoff = (lane >> 4) * 16;
    const int blk   = lane & 15;

    int buf = 0;
    for (int c = 0; c < nc; c++) {
        if (c + 1 < nc) asm volatile("cp.async.wait_group 1;");
        else            asm volatile("cp.async.wait_group 0;");
        __syncthreads();

        const uint32_t st   = sb + buf * STAGE_B;
        const uint32_t Ah_s = st;
        const uint32_t Al_s = st + A_BYTES;
        const uint32_t Bh_s = st + 2 * A_BYTES;

        uint32_t a_h[4][4], a_l[4][4];
#pragma unroll
        for (int f = 0; f < 4; f++) {
            const uint32_t off = (uint32_t)(arow + f * 16) * 48 + akoff;
            ldsm_x4(a_h[f], Ah_s + off);
            ldsm_x4(a_l[f], Al_s + off);
        }
#pragma unroll
        for (int fn = 0; fn < 4; fn++) {
            const int ncb = wn * 4 + fn;
            const uint32_t bd = Bh_s + blk * 256 + (((uint32_t)(ncb ^ (blk & 7))) << 4);
            uint32_t b_h[2], b_l[2];
            ldsm_x2t(b_h, bd);
            ldsm_x2t(b_l, bd + B_BYTES);
#pragma unroll
            for (int f = 0; f < 4; f++) {
                mma_bf16(acc[f][fn], a_h[f], b_h);
                mma_bf16(acc[f][fn], a_h[f], b_l);
                mma_bf16(acc[f][fn], a_l[f], b_h);
            }
        }

        if (c + 2 < nc) {
            int nb = buf + 2; if (nb >= 3) nb -= 3;
            issue(c + 2, nb);
        }
        if (++buf == 3) buf = 0;
    }

    // ---------------- epilogue (channel-major) ----------------
    const bool do_f = (outf != nullptr) && (m0 >= ofoff);
#pragma unroll
    for (int f = 0; f < 4; f++) {
        const int m = m0 + wm * 64 + f * 16 + g;
        const float s0 = sc[m],     b0 = bi[m];
        const float s1 = sc[m + 8], b1 = bi[m + 8];
#pragma unroll
        for (int fn = 0; fn < 4; fn++) {
            const int n = n0 + wn * 32 + fn * 8 + 2 * tig;
            float v00 = acc[f][fn][0] * s0 + b0;
            float v01 = acc[f][fn][1] * s0 + b0;
            float v10 = acc[f][fn][2] * s1 + b1;
            float v11 = acc[f][fn][3] * s1 + b1;
            if (res) {
                float2 ra = *(const float2*)(res + (size_t)b * rbs + (size_t)m * NPIX + n);
                float2 rb = *(const float2*)(res + (size_t)b * rbs + (size_t)(m + 8) * NPIX + n);
                v00 += ra.x; v01 += ra.y; v10 += rb.x; v11 += rb.y;
            }
            if (act) {
                v00 = silu_f(v00); v01 = silu_f(v01);
                v10 = silu_f(v10); v11 = silu_f(v11);
            }
            if (do_f) {
                const int mo = m - ofoff;
                *(float2*)(outf + (size_t)b * ofbs + (size_t)mo * NPIX + n) = make_float2(v00, v01);
                *(float2*)(outf + (size_t)b * ofbs + (size_t)(mo + 8) * NPIX + n) = make_float2(v10, v11);
            }
            if (oh) {
                __nv_bfloat16 h00, l00, h01, l01, h10, l10, h11, l11;
                bsplit(v00, h00, l00); bsplit(v01, h01, l01);
                bsplit(v10, h10, l10); bsplit(v11, h11, l11);
                *(__nv_bfloat162*)(oh + (size_t)b * ohbs + (size_t)m * NPIX + n)       = __nv_bfloat162(h00, h01);
                *(__nv_bfloat162*)(oh + (size_t)b * ohbs + (size_t)(m + 8) * NPIX + n) = __nv_bfloat162(h10, h11);
                *(__nv_bfloat162*)(ol + (size_t)b * ohbs + (size_t)m * NPIX + n)       = __nv_bfloat162(l00, l01);
                *(__nv_bfloat162*)(ol + (size_t)b * ohbs + (size_t)(m + 8) * NPIX + n) = __nv_bfloat162(l10, l11);
            }
        }
    }
}

// ---------------- elementwise split fp32 -> bf16 hi/lo ----------------
__global__ void split_k(const float4* __restrict__ src, uint2* __restrict__ hi,
                        uint2* __restrict__ lo, int n4)
{
    int i = blockIdx.x * 256 + threadIdx.x;
    if (i < n4) {
        float4 v = src[i];
        __nv_bfloat16 h[4], l[4];
        bsplit(v.x, h[0], l[0]); bsplit(v.y, h[1], l[1]);
        bsplit(v.z, h[2], l[2]); bsplit(v.w, h[3], l[3]);
        hi[i] = *(uint2*)h;
        lo[i] = *(uint2*)l;
    }
}

// ---------------- attention (fp32, channel-major qkv) ----------------
// smem: KV (K then V tiles) 128KB | S 16x1032 | Qs 16x32
__global__ __launch_bounds__(256) void attn_kernel(
    const float* __restrict__ qkv, float* __restrict__ xa)
{
    extern __shared__ float smn[];
    float* KV = smn;
    float* S  = smn + 32 * NPIX;
    float* Qs = S + 16 * 1032;

    const int tid  = threadIdx.x;
    const int warp = tid >> 5;
    const int lane = tid & 31;
    const int bh = blockIdx.y;
    const int r0 = blockIdx.x * 16;
    const float* base = qkv + (size_t)bh * 128 * NPIX;

    {
        const float4* src = (const float4*)(base + 32 * NPIX);
        float4* dst = (float4*)KV;
#pragma unroll
        for (int i = 0; i < 32; i++) dst[tid + 256 * i] = src[tid + 256 * i];
    }
    for (int i = tid; i < 16 * 32; i += 256) {
        int r = i >> 5, d = i & 31;
        Qs[i] = base[(size_t)d * NPIX + r0 + r];
    }
    __syncthreads();

    // ---- scores + softmax (warp w: rows 2w, 2w+1) ----
    {
        const int ra = warp * 2, rb = ra + 1;
        float qa[32], qb[32];
#pragma unroll
        for (int d = 0; d < 32; d++) { qa[d] = Qs[ra * 32 + d]; qb[d] = Qs[rb * 32 + d]; }

#pragma unroll 1
        for (int j = 0; j < 32; j += 2) {
            int m0 = lane + 32 * j;
            float a0 = 0.f, a1 = 0.f, b0 = 0.f, b1 = 0.f;
#pragma unroll
            for (int d = 0; d < 32; d++) {
                float k0 = KV[d * NPIX + m0];
                float k1 = KV[d * NPIX + m0 + 32];
                a0 += qa[d] * k0; a1 += qa[d] * k1;
                b0 += qb[d] * k0; b1 += qb[d] * k1;
            }
            S[ra * 1032 + m0]      = a0 * SCALE_ATT;
            S[ra * 1032 + m0 + 32] = a1 * SCALE_ATT;
            S[rb * 1032 + m0]      = b0 * SCALE_ATT;
            S[rb * 1032 + m0 + 32] = b1 * SCALE_ATT;
        }

#pragma unroll
        for (int rr = 0; rr < 2; rr++) {
            int r = ra + rr;
            float v[32];
            float mx = -1e30f;
#pragma unroll
            for (int j = 0; j < 32; j++) {
                v[j] = S[r * 1032 + lane + 32 * j];
                mx = fmaxf(mx, v[j]);
            }
#pragma unroll
            for (int o = 16; o > 0; o >>= 1)
                mx = fmaxf(mx, __shfl_xor_sync(0xffffffffu, mx, o));
            float sum = 0.f;
#pragma unroll
            for (int j = 0; j < 32; j++) { v[j] = __expf(v[j] - mx); sum += v[j]; }
#pragma unroll
            for (int o = 16; o > 0; o >>= 1)
                sum += __shfl_xor_sync(0xffffffffu, sum, o);
            float inv = 1.0f / sum;
#pragma unroll
            for (int j = 0; j < 32; j++) S[r * 1032 + lane + 32 * j] = v[j] * inv;
        }
    }
    __syncthreads();

    // ---- PV: 256 threads = 4 m-quarters x 4 row-groups x 16 d-groups ----
    // thread: q = tid>>6, rg = (tid>>4)&3, dg = tid&15
    // acc[r 4][d 4] over its 32-m quarter of each 128-m tile.
    const int q  = tid >> 6;
    const int rg = (tid >> 4) & 3;
    const int dg = tid & 15;
    float acc[4][4];
#pragma unroll
    for (int i = 0; i < 4; i++)
#pragma unroll
        for (int j = 0; j < 4; j++) acc[i][j] = 0.0f;

    float* Vt = KV; // [128 m][68 pad] tiles, d contiguous

    for (int mt = 0; mt < 8; mt++) {
#pragma unroll
        for (int i = 0; i < 32; i++) {
            int idx = tid + 256 * i;
            int d = idx >> 7, mm = idx & 127;
            Vt[mm * 68 + d] = base[(size_t)(64 + d) * NPIX + mt * 128 + mm];
        }
        __syncthreads();

        const float* Sb = S + mt * 128 + q * 32;
#pragma unroll 4
        for (int mm = 0; mm < 32; mm++) {
            const int m = q * 32 + mm;
            float4 v4 = *(const float4*)(Vt + m * 68 + dg * 4);
            float p0 = Sb[(rg * 4 + 0) * 1032 + mm];
            float p1 = Sb[(rg * 4 + 1) * 1032 + mm];
            float p2 = Sb[(rg * 4 + 2) * 1032 + mm];
            float p3 = Sb[(rg * 4 + 3) * 1032 + mm];
            acc[0][0] += p0 * v4.x; acc[0][1] += p0 * v4.y;
            acc[0][2] += p0 * v4.z; acc[0][3] += p0 * v4.w;
            acc[1][0] += p1 * v4.x; acc[1][1] += p1 * v4.y;
            acc[1][2] += p1 * v4.z; acc[1][3] += p1 * v4.w;
            acc[2][0] += p2 * v4.x; acc[2][1] += p2 * v4.y;
            acc[2][2] += p2 * v4.z; acc[2][3] += p2 * v4.w;
            acc[3][0] += p3 * v4.x; acc[3][1] += p3 * v4.y;
            acc[3][2] += p3 * v4.z; acc[3][3] += p3 * v4.w;
        }
        __syncthreads();
    }

    // ---- reduce over q (4 partials) via smem (reuse S region) ----
    {
        float* red = S; // 256 threads * 16 floats = 16KB << S size
        float4* rp = (float4*)(red + tid * 16);
#pragma unroll
        for (int i = 0; i < 4; i++)
            rp[i] = make_float4(acc[i][0], acc[i][1], acc[i][2], acc[i][3]);
    }
    __syncthreads();
    if (tid < 64) {
        const int rg2 = tid >> 4;     // row group
        const int dg2 = tid & 15;     // d group
        const float* red = S;
#pragma unroll
        for (int i = 0; i < 4; i++) {         // row within group
            const int r = rg2 * 4 + i;
            float o0 = 0.f, o1 = 0.f, o2 = 0.f, o3 = 0.f;
#pragma unroll
            for (int qq = 0; qq < 4; qq++) {
                const float* p = red + ((qq * 4 + rg2) * 16 + dg2) * 16 + i * 4;
                o0 += p[0]; o1 += p[1]; o2 += p[2]; o3 += p[3];
            }
            const int d = dg2 * 4;
            xa[(size_t)(bh * 64 + d + 0) * NPIX + r0 + r] = o0;
            xa[(size_t)(bh * 64 + d + 1) * NPIX + r0 + r] = o1;
            xa[(size_t)(bh * 64 + d + 2) * NPIX + r0 + r] = o2;
            xa[(size_t)(bh * 64 + d + 3) * NPIX + r0 + r] = o3;
        }
    }
}

// ---------------- depthwise 3x3 PE -> xa bf16 hi/lo (cm) ----------------
__global__ __launch_bounds__(256) void dwconv_pe(
    const float* __restrict__ qkv, const float* __restrict__ Wpe,
    const float* __restrict__ s, const float* __restrict__ bi,
    const float* __restrict__ xaf,
    __nv_bfloat16* __restrict__ xah, __nv_bfloat16* __restrict__ xal)
{
    __shared__ float t[34 * 34];
    const int c = blockIdx.x;
    const int b = blockIdx.y;
    const int qc = ((c >> 6) * 128) + 64 + (c & 63);
    const float* src = qkv + ((size_t)b * 512 + qc) * NPIX;
    const int tid = threadIdx.x;

    for (int i = tid; i < 34 * 34; i += 256) t[i] = 0.0f;
    __syncthreads();
    for (int i = tid; i < NPIX; i += 256) {
        int y = i >> 5, x = i & 31;
        t[(y + 1) * 34 + (x + 1)] = src[i];
    }
    __syncthreads();

    float w[9];
#pragma unroll
    for (int i = 0; i < 9; i++) w[i] = Wpe[c * 9 + i];
    const float scv = s[c], bv = bi[c];
    const size_t off = ((size_t)b * 256 + c) * NPIX;

    for (int i = tid; i < NPIX; i += 256) {
        int y = i >> 5, x = i & 31;
        float acc = 0.0f;
#pragma unroll
        for (int ky = 0; ky < 3; ky++)
#pragma unroll
            for (int kx = 0; kx < 3; kx++)
                acc += w[ky * 3 + kx] * t[(y + ky) * 34 + (x + kx)];
        float v = xaf[off + i] + acc * scv + bv;
        __nv_bfloat16 h, l;
        bsplit(v, h, l);
        xah[off + i] = h;
        xal[off + i] = l;
    }
}

// ---------------- launcher ----------------
extern "C" void kernel_launch(void* const* d_in, const int* in_sizes, int n_in,
                              void* d_out, int out_size)
{
    (void)in_sizes; (void)n_in; (void)out_size;
    const float* x      = (const float*)d_in[0];
    const float* W_cv1  = (const float*)d_in[1];
    const float* s_cv1  = (const float*)d_in[2];
    const float* b_cv1  = (const float*)d_in[3];
    const float* W_qkv  = (const float*)d_in[4];
    const float* s_qkv  = (const float*)d_in[5];
    const float* b_qkv  = (const float*)d_in[6];
    const float* W_proj = (const float*)d_in[7];
    const float* s_proj = (const float*)d_in[8];
    const float* b_proj = (const float*)d_in[9];
    const float* W_pe   = (const float*)d_in[10];
    const float* s_pe   = (const float*)d_in[11];
    const float* b_pe   = (const float*)d_in[12];
    const float* W_ffn1 = (const float*)d_in[13];
    const float* s_ffn1 = (const float*)d_in[14];
    const float* b_ffn1 = (const float*)d_in[15];
    const float* W_ffn2 = (const float*)d_in[16];
    const float* s_ffn2 = (const float*)d_in[17];
    const float* b_ffn2 = (const float*)d_in[18];
    const float* W_cv2  = (const float*)d_in[19];
    const float* s_cv2  = (const float*)d_in[20];
    const float* b_cv2  = (const float*)d_in[21];

    static __nv_bfloat16 *xh = nullptr, *xl, *ch, *cl, *fh, *fl, *ah, *al, *wh, *wl;
    static float *bbf, *qkvb, *xaf;
    if (!xh) {
        cudaGetSymbolAddress((void**)&xh,  g_xh);
        cudaGetSymbolAddress((void**)&xl,  g_xl);
        cudaGetSymbolAddress((void**)&ch,  g_ch);
        cudaGetSymbolAddress((void**)&cl,  g_cl);
        cudaGetSymbolAddress((void**)&fh,  g_fh);
        cudaGetSymbolAddress((void**)&fl,  g_fl);
        cudaGetSymbolAddress((void**)&ah,  g_ah);
        cudaGetSymbolAddress((void**)&al,  g_al);
        cudaGetSymbolAddress((void**)&wh,  g_wh);
        cudaGetSymbolAddress((void**)&wl,  g_wl);
        cudaGetSymbolAddress((void**)&bbf,  g_bbf);
        cudaGetSymbolAddress((void**)&qkvb, g_qkvb);
        cudaGetSymbolAddress((void**)&xaf,  g_xaf);
        cudaFuncSetAttribute(attn_kernel,
                             cudaFuncAttributeMaxDynamicSharedMemorySize, 199168);
        cudaFuncSetAttribute(gemm_bf16,
                             cudaFuncAttributeMaxDynamicSharedMemorySize, GSMEM);
    }
    float* out = (float*)d_out;
    const long S512 = 512 * NPIX, S256 = 256 * NPIX;

    const int W_CV1 = 0, W_QKV = 262144, W_PROJ = 393216,
              W_FFN1 = 458752, W_FFN2 = 589824, W_CV2 = 720896;

    // Launch order arranged so launch index 5 (ncu -s 5 -c 1) = attn_kernel.
    // #0: split x
    {
        int n4 = BSZ * 512 * NPIX / 4;
        split_k<<<(n4 + 255) / 256, 256>>>((const float4*)x, (uint2*)xh, (uint2*)xl, n4);
    }
    // #1: split W_cv1
    split_k<<<262144 / 4 / 256, 256>>>((const float4*)W_cv1, (uint2*)(wh + W_CV1), (uint2*)(wl + W_CV1), 65536);
    // #2: cv1 gemm
    gemm_bf16<<<dim3(8, 4, BSZ), 256, GSMEM>>>(
        xh, xl, S512, 512, wh + W_CV1, wl + W_CV1, s_cv1, b_cv1,
        nullptr, 0, bbf, S256, 256, ch, cl, S512, 1);
    // #3: split W_qkv
    split_k<<<131072 / 4 / 256, 256>>>((const float4*)W_qkv, (uint2*)(wh + W_QKV), (uint2*)(wl + W_QKV), 32768);
    // #4: qkv gemm
    gemm_bf16<<<dim3(8, 4, BSZ), 256, GSMEM>>>(
        ch + S256, cl + S256, S512, 256, wh + W_QKV, wl + W_QKV, s_qkv, b_qkv,
        nullptr, 0, qkvb, S512, 0, nullptr, nullptr, 0, 0);
    // #5: attention  <-- ncu profiles this launch
    attn_kernel<<<dim3(64, 64), 256, 199168>>>(qkvb, xaf);
    // #6: PE dwconv
    dwconv_pe<<<dim3(256, BSZ), 256>>>(qkvb, W_pe, s_pe, b_pe, xaf, ah, al);
    // #7: split W_proj
    split_k<<<65536 / 4 / 256, 256>>>((const float4*)W_proj, (uint2*)(wh + W_PROJ), (uint2*)(wl + W_PROJ), 16384);
    // #8: proj gemm (+bb residual, in-place bbf, re-split into cat ch256+)
    gemm_bf16<<<dim3(8, 2, BSZ), 256, GSMEM>>>(
        ah, al, S256, 256, wh + W_PROJ, wl + W_PROJ, s_proj, b_proj,
        bbf, S256, bbf, S256, 0, ch + S256, cl + S256, S512, 0);
    // #9: split W_ffn1
    split_k<<<131072 / 4 / 256, 256>>>((const float4*)W_ffn1, (uint2*)(wh + W_FFN1), (uint2*)(wl + W_FFN1), 32768);
    // #10: ffn1 gemm (SiLU)
    gemm_bf16<<<dim3(8, 4, BSZ), 256, GSMEM>>>(
        ch + S256, cl + S256, S512, 256, wh + W_FFN1, wl + W_FFN1, s_ffn1, b_ffn1,
        nullptr, 0, nullptr, 0, 0, fh, fl, S512, 1);
    // #11: split W_ffn2
    split_k<<<131072 / 4 / 256, 256>>>((const float4*)W_ffn2, (uint2*)(wh + W_FFN2), (uint2*)(wl + W_FFN2), 32768);
    // #12: ffn2 gemm (+bb2 residual -> cat ch256+)
    gemm_bf16<<<dim3(8, 2, BSZ), 256, GSMEM>>>(
        fh, fl, S512, 512, wh + W_FFN2, wl + W_FFN2, s_ffn2, b_ffn2,
        bbf, S256, nullptr, 0, 0, ch + S256, cl + S256, S512, 0);
    // #13: split W_cv2
    split_k<<<262144 / 4 / 256, 256>>>((const float4*)W_cv2, (uint2*)(wh + W_CV2), (uint2*)(wl + W_CV2), 65536);
    // #14: cv2 gemm -> out (SiLU)
    gemm_bf16<<<dim3(8, 4, BSZ), 256, GSMEM>>>(
        ch, cl, S512, 512, wh + W_CV2, wl + W_CV2, s_cv2, b_cv2,
        nullptr, 0, out, S512, 0, nullptr, nullptr, 0, 1);
}

// round 6
// speedup vs baseline: 4.2679x; 2.0076x over previous
#include <cuda_runtime.h>
#include <cuda_bf16.h>
#include <cstdint>

#define BSZ 16
#define NPIX 1024
#define SCALE_ATT 0.17677669529663687f

// ---------------- static scratch ----------------
__device__ __align__(16) __nv_bfloat16 g_xh[BSZ * 512 * NPIX], g_xl[BSZ * 512 * NPIX];
__device__ __align__(16) __nv_bfloat16 g_ch[BSZ * 512 * NPIX], g_cl[BSZ * 512 * NPIX];
__device__ __align__(16) __nv_bfloat16 g_fh[BSZ * 512 * NPIX], g_fl[BSZ * 512 * NPIX];
__device__ __align__(16) __nv_bfloat16 g_ah[BSZ * 256 * NPIX], g_al[BSZ * 256 * NPIX];
__device__ __align__(16) float g_bbf [BSZ * 256 * NPIX];  // bb chain f32 (cm)
__device__ __align__(16) float g_qkvb[BSZ * 512 * NPIX];  // qkv f32 (cm)
__device__ __align__(16) float g_xaf [BSZ * 256 * NPIX];  // attn out f32 (cm)
__device__ __align__(16) __nv_bfloat16 g_wh[983040], g_wl[983040];

__device__ __forceinline__ float silu_f(float v) {
    return v / (1.0f + __expf(-v));
}

__device__ __forceinline__ void bsplit(float v, __nv_bfloat16& h, __nv_bfloat16& l) {
    h = __float2bfloat16(v);
    l = __float2bfloat16(v - __bfloat162float(h));
}

__device__ __forceinline__ uint32_t s2u(const void* p) {
    uint32_t a;
    asm("{ .reg .u64 t; cvta.to.shared.u64 t, %1; cvt.u32.u64 %0, t; }" : "=r"(a) : "l"(p));
    return a;
}

__device__ __forceinline__ void cpa(uint32_t saddr, const void* g) {
    asm volatile("cp.async.cg.shared.global [%0], [%1], 16;" :: "r"(saddr), "l"(g));
}

__device__ __forceinline__ void ldsm_x4(uint32_t* r, uint32_t addr) {
    asm volatile("ldmatrix.sync.aligned.m8n8.x4.shared.b16 {%0,%1,%2,%3}, [%4];"
                 : "=r"(r[0]), "=r"(r[1]), "=r"(r[2]), "=r"(r[3]) : "r"(addr));
}

__device__ __forceinline__ void ldsm_x4t(uint32_t* r, uint32_t addr) {
    asm volatile("ldmatrix.sync.aligned.m8n8.x4.trans.shared.b16 {%0,%1,%2,%3}, [%4];"
                 : "=r"(r[0]), "=r"(r[1]), "=r"(r[2]), "=r"(r[3]) : "r"(addr));
}

__device__ __forceinline__ void ldsm_x2(uint32_t* r, uint32_t addr) {
    asm volatile("ldmatrix.sync.aligned.m8n8.x2.shared.b16 {%0,%1}, [%2];"
                 : "=r"(r[0]), "=r"(r[1]) : "r"(addr));
}

__device__ __forceinline__ void ldsm_x2t(uint32_t* r, uint32_t addr) {
    asm volatile("ldmatrix.sync.aligned.m8n8.x2.trans.shared.b16 {%0,%1}, [%2];"
                 : "=r"(r[0]), "=r"(r[1]) : "r"(addr));
}

__device__ __forceinline__ void mma_bf16(float* c, const uint32_t* a, const uint32_t* b) {
    asm volatile(
        "mma.sync.aligned.m16n8k16.row.col.f32.bf16.bf16.f32 "
        "{%0,%1,%2,%3}, {%4,%5,%6,%7}, {%8,%9}, {%0,%1,%2,%3};\n"
        : "+f"(c[0]), "+f"(c[1]), "+f"(c[2]), "+f"(c[3])
        : "r"(a[0]), "r"(a[1]), "r"(a[2]), "r"(a[3]), "r"(b[0]), "r"(b[1]));
}

// ---------------- bf16 tensor-core GEMM (3-pass split, 3-stage pipe) ----------------
#define A_BYTES (128 * 48)
#define B_BYTES (16 * 256)
#define STAGE_B (2 * A_BYTES + 2 * B_BYTES)  // 20480
#define GSMEM   (3 * STAGE_B)                // 61440

__global__ __launch_bounds__(256, 2) void gemm_bf16(
    const __nv_bfloat16* __restrict__ Xh, const __nv_bfloat16* __restrict__ Xl, long xbs,
    int K,
    const __nv_bfloat16* __restrict__ Wh, const __nv_bfloat16* __restrict__ Wl,
    const float* __restrict__ sc, const float* __restrict__ bi,
    const float* __restrict__ res, long rbs,
    float* __restrict__ outf, long ofbs, int ofoff,
    __nv_bfloat16* __restrict__ oh, __nv_bfloat16* __restrict__ ol, long ohbs,
    int act)
{
    extern __shared__ __align__(16) char smem[];
    const uint32_t sb = s2u(smem);
    const int tid  = threadIdx.x;
    const int warp = tid >> 5;
    const int lane = tid & 31;
    const int g    = lane >> 2;
    const int tig  = lane & 3;
    const int wm   = warp >> 2;
    const int wn   = warp & 3;
    const int b  = blockIdx.z;
    const int n0 = blockIdx.x * 128;
    const int m0 = blockIdx.y * 128;

    const __nv_bfloat16* Xhb = Xh + (size_t)b * xbs;
    const __nv_bfloat16* Xlb = Xl + (size_t)b * xbs;

    float acc[4][4][4];
#pragma unroll
    for (int f = 0; f < 4; f++)
#pragma unroll
        for (int fn = 0; fn < 4; fn++)
#pragma unroll
            for (int q = 0; q < 4; q++) acc[f][fn][q] = 0.0f;

    const int am = tid >> 1, ahh = tid & 1;
    const int bk = tid >> 4, bnc = tid & 15;
    const uint32_t a_dst = am * 48 + ahh * 16;
    const uint32_t b_dst = bk * 256 + (((uint32_t)(bnc ^ (bk & 7))) << 4);

    auto issue = [&](int c, int buf) {
        const uint32_t st = sb + buf * STAGE_B;
        const int k0 = c * 16;
        cpa(st + a_dst,           Wh + (size_t)(m0 + am) * K + k0 + ahh * 8);
        cpa(st + A_BYTES + a_dst, Wl + (size_t)(m0 + am) * K + k0 + ahh * 8);
        cpa(st + 2 * A_BYTES + b_dst,           Xhb + (size_t)(k0 + bk) * NPIX + n0 + bnc * 8);
        cpa(st + 2 * A_BYTES + B_BYTES + b_dst, Xlb + (size_t)(k0 + bk) * NPIX + n0 + bnc * 8);
        asm volatile("cp.async.commit_group;");
    };

    const int nc = K >> 4;
    issue(0, 0);
    if (nc > 1) issue(1, 1);

    const int arow  = wm * 64 + (lane & 15);
    const int akoff = (lane >> 4) * 16;
    const int blk   = lane & 15;

    int buf = 0;
    for (int c = 0; c < nc; c++) {
        if (c + 1 < nc) asm volatile("cp.async.wait_group 1;");
        else            asm volatile("cp.async.wait_group 0;");
        __syncthreads();

        const uint32_t st   = sb + buf * STAGE_B;
        const uint32_t Ah_s = st;
        const uint32_t Al_s = st + A_BYTES;
        const uint32_t Bh_s = st + 2 * A_BYTES;

        uint32_t a_h[4][4], a_l[4][4];
#pragma unroll
        for (int f = 0; f < 4; f++) {
            const uint32_t off = (uint32_t)(arow + f * 16) * 48 + akoff;
            ldsm_x4(a_h[f], Ah_s + off);
            ldsm_x4(a_l[f], Al_s + off);
        }
#pragma unroll
        for (int fn = 0; fn < 4; fn++) {
            const int ncb = wn * 4 + fn;
            const uint32_t bd = Bh_s + blk * 256 + (((uint32_t)(ncb ^ (blk & 7))) << 4);
            uint32_t b_h[2], b_l[2];
            ldsm_x2t(b_h, bd);
            ldsm_x2t(b_l, bd + B_BYTES);
#pragma unroll
            for (int f = 0; f < 4; f++) {
                mma_bf16(acc[f][fn], a_h[f], b_h);
                mma_bf16(acc[f][fn], a_h[f], b_l);
                mma_bf16(acc[f][fn], a_l[f], b_h);
            }
        }

        if (c + 2 < nc) {
            int nb = buf + 2; if (nb >= 3) nb -= 3;
            issue(c + 2, nb);
        }
        if (++buf == 3) buf = 0;
    }

    // ---------------- epilogue (channel-major) ----------------
    const bool do_f = (outf != nullptr) && (m0 >= ofoff);
#pragma unroll
    for (int f = 0; f < 4; f++) {
        const int m = m0 + wm * 64 + f * 16 + g;
        const float s0 = sc[m],     b0 = bi[m];
        const float s1 = sc[m + 8], b1 = bi[m + 8];
#pragma unroll
        for (int fn = 0; fn < 4; fn++) {
            const int n = n0 + wn * 32 + fn * 8 + 2 * tig;
            float v00 = acc[f][fn][0] * s0 + b0;
            float v01 = acc[f][fn][1] * s0 + b0;
            float v10 = acc[f][fn][2] * s1 + b1;
            float v11 = acc[f][fn][3] * s1 + b1;
            if (res) {
                float2 ra = *(const float2*)(res + (size_t)b * rbs + (size_t)m * NPIX + n);
                float2 rb = *(const float2*)(res + (size_t)b * rbs + (size_t)(m + 8) * NPIX + n);
                v00 += ra.x; v01 += ra.y; v10 += rb.x; v11 += rb.y;
            }
            if (act) {
                v00 = silu_f(v00); v01 = silu_f(v01);
                v10 = silu_f(v10); v11 = silu_f(v11);
            }
            if (do_f) {
                const int mo = m - ofoff;
                *(float2*)(outf + (size_t)b * ofbs + (size_t)mo * NPIX + n) = make_float2(v00, v01);
                *(float2*)(outf + (size_t)b * ofbs + (size_t)(mo + 8) * NPIX + n) = make_float2(v10, v11);
            }
            if (oh) {
                __nv_bfloat16 h00, l00, h01, l01, h10, l10, h11, l11;
                bsplit(v00, h00, l00); bsplit(v01, h01, l01);
                bsplit(v10, h10, l10); bsplit(v11, h11, l11);
                *(__nv_bfloat162*)(oh + (size_t)b * ohbs + (size_t)m * NPIX + n)       = __nv_bfloat162(h00, h01);
                *(__nv_bfloat162*)(oh + (size_t)b * ohbs + (size_t)(m + 8) * NPIX + n) = __nv_bfloat162(h10, h11);
                *(__nv_bfloat162*)(ol + (size_t)b * ohbs + (size_t)m * NPIX + n)       = __nv_bfloat162(l00, l01);
                *(__nv_bfloat162*)(ol + (size_t)b * ohbs + (size_t)(m + 8) * NPIX + n) = __nv_bfloat162(l10, l11);
            }
        }
    }
}

// ---------------- splits ----------------
__global__ void split_k(const float4* __restrict__ src, uint2* __restrict__ hi,
                        uint2* __restrict__ lo, int n4)
{
    int i = blockIdx.x * 256 + threadIdx.x;
    if (i < n4) {
        float4 v = src[i];
        __nv_bfloat16 h[4], l[4];
        bsplit(v.x, h[0], l[0]); bsplit(v.y, h[1], l[1]);
        bsplit(v.z, h[2], l[2]); bsplit(v.w, h[3], l[3]);
        hi[i] = *(uint2*)h;
        lo[i] = *(uint2*)l;
    }
}

__global__ void wsplit_all(
    const float* __restrict__ W0, const float* __restrict__ W1,
    const float* __restrict__ W2, const float* __restrict__ W3,
    const float* __restrict__ W4, const float* __restrict__ W5,
    __nv_bfloat16* __restrict__ wh, __nv_bfloat16* __restrict__ wl)
{
    int blk = blockIdx.x;
    const float* src; int off;
    if      (blk < 256) { src = W0; off = 0;      }
    else if (blk < 384) { src = W1; off = 262144; blk -= 256; }
    else if (blk < 448) { src = W2; off = 393216; blk -= 384; }
    else if (blk < 576) { src = W3; off = 458752; blk -= 448; }
    else if (blk < 704) { src = W4; off = 589824; blk -= 576; }
    else                { src = W5; off = 720896; blk -= 704; }
    int i = blk * 256 + threadIdx.x;
    float4 v = ((const float4*)src)[i];
    __nv_bfloat16 h[4], l[4];
    bsplit(v.x, h[0], l[0]); bsplit(v.y, h[1], l[1]);
    bsplit(v.z, h[2], l[2]); bsplit(v.w, h[3], l[3]);
    ((uint2*)(wh + off))[i] = *(uint2*)h;
    ((uint2*)(wl + off))[i] = *(uint2*)l;
}

// ---------------- tensor-core flash attention ----------------
// CTA = (row-tile of 128 pixels, b*4+h). qkv given as bf16 hi/lo channel-major.
// smem rows of 272B stride (conflict-free for all ldmatrix phases).
#define RS 272
#define OFF_Q 0
#define OFF_K 17408
#define OFF_V 52224
#define OFF_P 121856
#define OFF_RM 191488
#define OFF_RSUM 193536
#define ASMEM 195584

__global__ __launch_bounds__(256) void attn_mma(
    const __nv_bfloat16* __restrict__ qh, const __nv_bfloat16* __restrict__ ql,
    float* __restrict__ xa)
{
    extern __shared__ __align__(16) char smn[];
    const uint32_t sb = s2u(smn);
    float* redmax = (float*)(smn + OFF_RM);
    float* redsum = (float*)(smn + OFF_RSUM);

    const int tid = threadIdx.x;
    const int warp = tid >> 5, lane = tid & 31;
    const int g = lane >> 2, tig = lane & 3;
    const int wm = warp >> 2, wn = warp & 3;
    const int bh = blockIdx.y;
    const int r0 = blockIdx.x * 128;
    const size_t cb = (size_t)bh * 128 * NPIX;

    // ---- async loads ----
    // Q: channels 0..31, pixels r0..r0+127
#pragma unroll
    for (int i = 0; i < 4; i++) {
        int idx = i * 256 + tid;
        int hl = idx >> 9, row = (idx >> 4) & 31, ch = idx & 15;
        const __nv_bfloat16* src = (hl ? ql : qh) + cb + (size_t)row * NPIX + r0 + ch * 8;
        cpa(sb + OFF_Q + hl * 8704 + row * RS + ch * 16, src);
    }
    auto loadK = [&](int mt, int kb) {
#pragma unroll
        for (int i = 0; i < 4; i++) {
            int idx = i * 256 + tid;
            int hl = idx >> 9, row = (idx >> 4) & 31, ch = idx & 15;
            const __nv_bfloat16* src = (hl ? ql : qh) + cb + (size_t)(32 + row) * NPIX + mt * 128 + ch * 8;
            cpa(sb + OFF_K + kb * 17408 + hl * 8704 + row * RS + ch * 16, src);
        }
    };
    auto loadV = [&](int mt, int vb) {
#pragma unroll
        for (int i = 0; i < 8; i++) {
            int idx = i * 256 + tid;
            int hl = idx >> 10, row = (idx >> 4) & 63, ch = idx & 15;
            const __nv_bfloat16* src = (hl ? ql : qh) + cb + (size_t)(64 + row) * NPIX + mt * 128 + ch * 8;
            cpa(sb + OFF_V + vb * 34816 + hl * 17408 + row * RS + ch * 16, src);
        }
    };
    loadK(0, 0); loadV(0, 0);
    asm volatile("cp.async.commit_group;");

    float m_s[8], l_s[8];
#pragma unroll
    for (int i = 0; i < 8; i++) { m_s[i] = -1e30f; l_s[i] = 0.f; }
    float accO[4][2][4];
#pragma unroll
    for (int f = 0; f < 4; f++)
#pragma unroll
        for (int n2 = 0; n2 < 2; n2++)
#pragma unroll
            for (int q = 0; q < 4; q++) accO[f][n2][q] = 0.f;

    for (int mt = 0; mt < 8; mt++) {
        asm volatile("cp.async.wait_group 0;");
        __syncthreads();
        const int kb = mt & 1, vb = mt & 1;

        // ---- S = Q K^T (3-term) ----
        float accS[4][4][4];
#pragma unroll
        for (int f = 0; f < 4; f++)
#pragma unroll
            for (int fn = 0; fn < 4; fn++)
#pragma unroll
                for (int q = 0; q < 4; q++) accS[f][fn][q] = 0.f;

        const int krow = (lane & 7) + ((lane >> 4) << 3);
        const int mcol = ((lane >> 3) & 1) * 8;
#pragma unroll
        for (int kc = 0; kc < 2; kc++) {
            uint32_t qf_h[4][4], qf_l[4][4];
#pragma unroll
            for (int f = 0; f < 4; f++) {
                uint32_t ad = sb + OFF_Q + (kc * 16 + krow) * RS +
                              (wm * 64 + f * 16 + mcol) * 2;
                ldsm_x4t(qf_h[f], ad);
                ldsm_x4t(qf_l[f], ad + 8704);
            }
#pragma unroll
            for (int fn = 0; fn < 4; fn++) {
                uint32_t bd = sb + OFF_K + kb * 17408 + (kc * 16 + (lane & 15)) * RS +
                              (wn * 32 + fn * 8) * 2;
                uint32_t kh2[2], kl2[2];
                ldsm_x2t(kh2, bd);
                ldsm_x2t(kl2, bd + 8704);
#pragma unroll
                for (int f = 0; f < 4; f++) {
                    mma_bf16(accS[f][fn], qf_h[f], kh2);
                    mma_bf16(accS[f][fn], qf_h[f], kl2);
                    mma_bf16(accS[f][fn], qf_l[f], kh2);
                }
            }
        }

        // ---- prefetch next K/V ----
        if (mt + 1 < 8) {
            loadK(mt + 1, kb ^ 1);
            loadV(mt + 1, vb ^ 1);
        }
        asm volatile("cp.async.commit_group;");

        // ---- online softmax ----
#pragma unroll
        for (int f = 0; f < 4; f++)
#pragma unroll
            for (int h = 0; h < 2; h++) {
                float pm = -1e30f;
#pragma unroll
                for (int fn = 0; fn < 4; fn++) {
                    float x0 = accS[f][fn][2 * h]     * SCALE_ATT;
                    float x1 = accS[f][fn][2 * h + 1] * SCALE_ATT;
                    pm = fmaxf(pm, fmaxf(x0, x1));
                }
                pm = fmaxf(pm, __shfl_xor_sync(0xffffffffu, pm, 1));
                pm = fmaxf(pm, __shfl_xor_sync(0xffffffffu, pm, 2));
                if (tig == 0) redmax[(wm * 64 + f * 16 + g + 8 * h) * 4 + wn] = pm;
            }
        __syncthreads();

        float sf_[8];
#pragma unroll
        for (int f = 0; f < 4; f++)
#pragma unroll
            for (int h = 0; h < 2; h++) {
                const int r = wm * 64 + f * 16 + g + 8 * h;
                float mn = fmaxf(fmaxf(redmax[r * 4 + 0], redmax[r * 4 + 1]),
                                 fmaxf(redmax[r * 4 + 2], redmax[r * 4 + 3]));
                const int s = f * 2 + h;
                mn = fmaxf(mn, m_s[s]);
                float sf = __expf(m_s[s] - mn);
                m_s[s] = mn; l_s[s] *= sf; sf_[s] = sf;
            }
#pragma unroll
        for (int f = 0; f < 4; f++)
#pragma unroll
            for (int n2 = 0; n2 < 2; n2++) {
                accO[f][n2][0] *= sf_[f * 2];     accO[f][n2][1] *= sf_[f * 2];
                accO[f][n2][2] *= sf_[f * 2 + 1]; accO[f][n2][3] *= sf_[f * 2 + 1];
            }

        // ---- P = exp(S - m), store bf16 hi/lo, row sums ----
#pragma unroll
        for (int f = 0; f < 4; f++) {
            float ps0 = 0.f, ps1 = 0.f;
            const uint32_t prow0 = (uint32_t)(wm * 64 + f * 16 + g) * RS;
#pragma unroll
            for (int fn = 0; fn < 4; fn++) {
                float p00 = __expf(accS[f][fn][0] * SCALE_ATT - m_s[f * 2]);
                float p01 = __expf(accS[f][fn][1] * SCALE_ATT - m_s[f * 2]);
                float p10 = __expf(accS[f][fn][2] * SCALE_ATT - m_s[f * 2 + 1]);
                float p11 = __expf(accS[f][fn][3] * SCALE_ATT - m_s[f * 2 + 1]);
                ps0 += p00 + p01; ps1 += p10 + p11;
                __nv_bfloat16 h00, l00, h01, l01, h10, l10, h11, l11;
                bsplit(p00, h00, l00); bsplit(p01, h01, l01);
                bsplit(p10, h10, l10); bsplit(p11, h11, l11);
                const uint32_t colb = (uint32_t)(wn * 32 + fn * 8 + 2 * tig) * 2;
                char* ph = smn + OFF_P;
                char* pl = smn + OFF_P + 34816;
                *(__nv_bfloat162*)(ph + prow0 + colb)            = __nv_bfloat162(h00, h01);
                *(__nv_bfloat162*)(ph + prow0 + 8 * RS + colb)   = __nv_bfloat162(h10, h11);
                *(__nv_bfloat162*)(pl + prow0 + colb)            = __nv_bfloat162(l00, l01);
                *(__nv_bfloat162*)(pl + prow0 + 8 * RS + colb)   = __nv_bfloat162(l10, l11);
            }
            ps0 += __shfl_xor_sync(0xffffffffu, ps0, 1);
            ps0 += __shfl_xor_sync(0xffffffffu, ps0, 2);
            ps1 += __shfl_xor_sync(0xffffffffu, ps1, 1);
            ps1 += __shfl_xor_sync(0xffffffffu, ps1, 2);
            if (tig == 0) {
                redsum[(wm * 64 + f * 16 + g) * 4 + wn]     = ps0;
                redsum[(wm * 64 + f * 16 + g + 8) * 4 + wn] = ps1;
            }
        }
        __syncthreads();

#pragma unroll
        for (int f = 0; f < 4; f++)
#pragma unroll
            for (int h = 0; h < 2; h++) {
                const int r = wm * 64 + f * 16 + g + 8 * h;
                l_s[f * 2 + h] += redsum[r * 4 + 0] + redsum[r * 4 + 1] +
                                  redsum[r * 4 + 2] + redsum[r * 4 + 3];
            }

        // ---- O += P V (3-term) ----
        const int pmr  = (lane & 7) + ((lane >> 3) & 1) * 8;
        const int pkc8 = (lane >> 4) * 8;
#pragma unroll
        for (int kc = 0; kc < 8; kc++) {
            uint32_t pa_h[4][4], pa_l[4][4];
#pragma unroll
            for (int f = 0; f < 4; f++) {
                uint32_t ad = sb + OFF_P + (uint32_t)(wm * 64 + f * 16 + pmr) * RS +
                              (kc * 16 + pkc8) * 2;
                ldsm_x4(pa_h[f], ad);
                ldsm_x4(pa_l[f], ad + 34816);
            }
#pragma unroll
            for (int n2 = 0; n2 < 2; n2++) {
                uint32_t bd = sb + OFF_V + vb * 34816 +
                              (uint32_t)(wn * 16 + n2 * 8 + (lane & 7)) * RS +
                              (kc * 16 + ((lane >> 3) & 1) * 8) * 2;
                uint32_t vh2[2], vl2[2];
                ldsm_x2(vh2, bd);
                ldsm_x2(vl2, bd + 17408);
#pragma unroll
                for (int f = 0; f < 4; f++) {
                    mma_bf16(accO[f][n2], pa_h[f], vh2);
                    mma_bf16(accO[f][n2], pa_h[f], vl2);
                    mma_bf16(accO[f][n2], pa_l[f], vh2);
                }
            }
        }
    }

    // ---- write out: xa[(bh*64+d)][r0+row] = O / l ----
    float il[8];
#pragma unroll
    for (int s = 0; s < 8; s++) il[s] = 1.0f / l_s[s];
#pragma unroll
    for (int f = 0; f < 4; f++)
#pragma unroll
        for (int n2 = 0; n2 < 2; n2++) {
            const int d = wn * 16 + n2 * 8 + 2 * tig;
            const int r = r0 + wm * 64 + f * 16 + g;
            xa[(size_t)(bh * 64 + d) * NPIX + r]         = accO[f][n2][0] * il[f * 2];
            xa[(size_t)(bh * 64 + d + 1) * NPIX + r]     = accO[f][n2][1] * il[f * 2];
            xa[(size_t)(bh * 64 + d) * NPIX + r + 8]     = accO[f][n2][2] * il[f * 2 + 1];
            xa[(size_t)(bh * 64 + d + 1) * NPIX + r + 8] = accO[f][n2][3] * il[f * 2 + 1];
        }
}

// ---------------- depthwise 3x3 PE -> xa bf16 hi/lo (cm) ----------------
__global__ __launch_bounds__(256) void dwconv_pe(
    const float* __restrict__ qkv, const float* __restrict__ Wpe,
    const float* __restrict__ s, const float* __restrict__ bi,
    const float* __restrict__ xaf,
    __nv_bfloat16* __restrict__ xah, __nv_bfloat16* __restrict__ xal)
{
    __shared__ float t[34 * 34];
    const int c = blockIdx.x;
    const int b = blockIdx.y;
    const int qc = ((c >> 6) * 128) + 64 + (c & 63);
    const float* src = qkv + ((size_t)b * 512 + qc) * NPIX;
    const int tid = threadIdx.x;

    for (int i = tid; i < 34 * 34; i += 256) t[i] = 0.0f;
    __syncthreads();
    for (int i = tid; i < NPIX; i += 256) {
        int y = i >> 5, x = i & 31;
        t[(y + 1) * 34 + (x + 1)] = src[i];
    }
    __syncthreads();

    float w[9];
#pragma unroll
    for (int i = 0; i < 9; i++) w[i] = Wpe[c * 9 + i];
    const float scv = s[c], bv = bi[c];
    const size_t off = ((size_t)b * 256 + c) * NPIX;

    for (int i = tid; i < NPIX; i += 256) {
        int y = i >> 5, x = i & 31;
        float acc = 0.0f;
#pragma unroll
        for (int ky = 0; ky < 3; ky++)
#pragma unroll
            for (int kx = 0; kx < 3; kx++)
                acc += w[ky * 3 + kx] * t[(y + ky) * 34 + (x + kx)];
        float v = xaf[off + i] + acc * scv + bv;
        __nv_bfloat16 h, l;
        bsplit(v, h, l);
        xah[off + i] = h;
        xal[off + i] = l;
    }
}

// ---------------- launcher ----------------
extern "C" void kernel_launch(void* const* d_in, const int* in_sizes, int n_in,
                              void* d_out, int out_size)
{
    (void)in_sizes; (void)n_in; (void)out_size;
    const float* x      = (const float*)d_in[0];
    const float* W_cv1  = (const float*)d_in[1];
    const float* s_cv1  = (const float*)d_in[2];
    const float* b_cv1  = (const float*)d_in[3];
    const float* W_qkv  = (const float*)d_in[4];
    const float* s_qkv  = (const float*)d_in[5];
    const float* b_qkv  = (const float*)d_in[6];
    const float* W_proj = (const float*)d_in[7];
    const float* s_proj = (const float*)d_in[8];
    const float* b_proj = (const float*)d_in[9];
    const float* W_pe   = (const float*)d_in[10];
    const float* s_pe   = (const float*)d_in[11];
    const float* b_pe   = (const float*)d_in[12];
    const float* W_ffn1 = (const float*)d_in[13];
    const float* s_ffn1 = (const float*)d_in[14];
    const float* b_ffn1 = (const float*)d_in[15];
    const float* W_ffn2 = (const float*)d_in[16];
    const float* s_ffn2 = (const float*)d_in[17];
    const float* b_ffn2 = (const float*)d_in[18];
    const float* W_cv2  = (const float*)d_in[19];
    const float* s_cv2  = (const float*)d_in[20];
    const float* b_cv2  = (const float*)d_in[21];

    static __nv_bfloat16 *xh = nullptr, *xl, *ch, *cl, *fh, *fl, *ah, *al, *wh, *wl;
    static float *bbf, *qkvb, *xaf;
    if (!xh) {
        cudaGetSymbolAddress((void**)&xh,  g_xh);
        cudaGetSymbolAddress((void**)&xl,  g_xl);
        cudaGetSymbolAddress((void**)&ch,  g_ch);
        cudaGetSymbolAddress((void**)&cl,  g_cl);
        cudaGetSymbolAddress((void**)&fh,  g_fh);
        cudaGetSymbolAddress((void**)&fl,  g_fl);
        cudaGetSymbolAddress((void**)&ah,  g_ah);
        cudaGetSymbolAddress((void**)&al,  g_al);
        cudaGetSymbolAddress((void**)&wh,  g_wh);
        cudaGetSymbolAddress((void**)&wl,  g_wl);
        cudaGetSymbolAddress((void**)&bbf,  g_bbf);
        cudaGetSymbolAddress((void**)&qkvb, g_qkvb);
        cudaGetSymbolAddress((void**)&xaf,  g_xaf);
        cudaFuncSetAttribute(attn_mma,
                             cudaFuncAttributeMaxDynamicSharedMemorySize, ASMEM);
        cudaFuncSetAttribute(gemm_bf16,
                             cudaFuncAttributeMaxDynamicSharedMemorySize, GSMEM);
    }
    float* out = (float*)d_out;
    const long S512 = 512 * NPIX, S256 = 256 * NPIX;

    const int W_CV1 = 0, W_QKV = 262144, W_PROJ = 393216,
              W_FFN1 = 458752, W_FFN2 = 589824, W_CV2 = 720896;

    // #0: split x
    {
        int n4 = BSZ * 512 * NPIX / 4;
        split_k<<<(n4 + 255) / 256, 256>>>((const float4*)x, (uint2*)xh, (uint2*)xl, n4);
    }
    // #1: split all weights (one launch)
    wsplit_all<<<960, 256>>>(W_cv1, W_qkv, W_proj, W_ffn1, W_ffn2, W_cv2, wh, wl);
    // #2: cv1 gemm
    gemm_bf16<<<dim3(8, 4, BSZ), 256, GSMEM>>>(
        xh, xl, S512, 512, wh + W_CV1, wl + W_CV1, s_cv1, b_cv1,
        nullptr, 0, bbf, S256, 256, ch, cl, S512, 1);
    // #3: qkv gemm (fp32 for dwconv + bf16 hi/lo for attention)
    gemm_bf16<<<dim3(8, 4, BSZ), 256, GSMEM>>>(
        ch + S256, cl + S256, S512, 256, wh + W_QKV, wl + W_QKV, s_qkv, b_qkv,
        nullptr, 0, qkvb, S512, 0, fh, fl, S512, 0);
    // #4: tensor-core flash attention -> xaf (cm)
    attn_mma<<<dim3(8, 64), 256, ASMEM>>>(fh, fl, xaf);
    // #5: PE dwconv: xaf + conv(v) -> xa bf16 hi/lo
    dwconv_pe<<<dim3(256, BSZ), 256>>>(qkvb, W_pe, s_pe, b_pe, xaf, ah, al);
    // #6: proj gemm (+bb residual, in-place bbf, re-split into cat ch256+)
    gemm_bf16<<<dim3(8, 2, BSZ), 256, GSMEM>>>(
        ah, al, S256, 256, wh + W_PROJ, wl + W_PROJ, s_proj, b_proj,
        bbf, S256, bbf, S256, 0, ch + S256, cl + S256, S512, 0);
    // #7: ffn1 gemm (SiLU)
    gemm_bf16<<<dim3(8, 4, BSZ), 256, GSMEM>>>(
        ch + S256, cl + S256, S512, 256, wh + W_FFN1, wl + W_FFN1, s_ffn1, b_ffn1,
        nullptr, 0, nullptr, 0, 0, fh, fl, S512, 1);
    // #8: ffn2 gemm (+bb2 residual -> cat ch256+)
    gemm_bf16<<<dim3(8, 2, BSZ), 256, GSMEM>>>(
        fh, fl, S512, 512, wh + W_FFN2, wl + W_FFN2, s_ffn2, b_ffn2,
        bbf, S256, nullptr, 0, 0, ch + S256, cl + S256, S512, 0);
    // #9: cv2 gemm -> out (SiLU)
    gemm_bf16<<<dim3(8, 4, BSZ), 256, GSMEM>>>(
        ch, cl, S512, 512, wh + W_CV2, wl + W_CV2, s_cv2, b_cv2,
        nullptr, 0, out, S512, 0, nullptr, nullptr, 0, 1);
}

// round 7
// speedup vs baseline: 4.4816x; 1.0501x over previous
#include <cuda_runtime.h>
#include <cuda_bf16.h>
#include <cstdint>

#define BSZ 16
#define NPIX 1024
#define SCALE_ATT 0.17677669529663687f

// ---------------- static scratch ----------------
__device__ __align__(16) __nv_bfloat16 g_xh[BSZ * 512 * NPIX], g_xl[BSZ * 512 * NPIX];
__device__ __align__(16) __nv_bfloat16 g_ch[BSZ * 512 * NPIX], g_cl[BSZ * 512 * NPIX];
__device__ __align__(16) __nv_bfloat16 g_fh[BSZ * 512 * NPIX], g_fl[BSZ * 512 * NPIX];
__device__ __align__(16) __nv_bfloat16 g_ah[BSZ * 256 * NPIX], g_al[BSZ * 256 * NPIX];
__device__ __align__(16) float g_bbf [BSZ * 256 * NPIX];  // bb chain f32 (cm)
__device__ __align__(16) float g_xaf [BSZ * 256 * NPIX];  // attn out f32 (cm)
__device__ __align__(16) __nv_bfloat16 g_wh[983040], g_wl[983040];

__device__ __forceinline__ float silu_f(float v) {
    return v / (1.0f + __expf(-v));
}

__device__ __forceinline__ void bsplit(float v, __nv_bfloat16& h, __nv_bfloat16& l) {
    h = __float2bfloat16(v);
    l = __float2bfloat16(v - __bfloat162float(h));
}

__device__ __forceinline__ uint32_t s2u(const void* p) {
    uint32_t a;
    asm("{ .reg .u64 t; cvta.to.shared.u64 t, %1; cvt.u32.u64 %0, t; }" : "=r"(a) : "l"(p));
    return a;
}

__device__ __forceinline__ void cpa(uint32_t saddr, const void* g) {
    asm volatile("cp.async.cg.shared.global [%0], [%1], 16;" :: "r"(saddr), "l"(g));
}

__device__ __forceinline__ void ldsm_x4(uint32_t* r, uint32_t addr) {
    asm volatile("ldmatrix.sync.aligned.m8n8.x4.shared.b16 {%0,%1,%2,%3}, [%4];"
                 : "=r"(r[0]), "=r"(r[1]), "=r"(r[2]), "=r"(r[3]) : "r"(addr));
}

__device__ __forceinline__ void ldsm_x4t(uint32_t* r, uint32_t addr) {
    asm volatile("ldmatrix.sync.aligned.m8n8.x4.trans.shared.b16 {%0,%1,%2,%3}, [%4];"
                 : "=r"(r[0]), "=r"(r[1]), "=r"(r[2]), "=r"(r[3]) : "r"(addr));
}

__device__ __forceinline__ void ldsm_x2(uint32_t* r, uint32_t addr) {
    asm volatile("ldmatrix.sync.aligned.m8n8.x2.shared.b16 {%0,%1}, [%2];"
                 : "=r"(r[0]), "=r"(r[1]) : "r"(addr));
}

__device__ __forceinline__ void ldsm_x2t(uint32_t* r, uint32_t addr) {
    asm volatile("ldmatrix.sync.aligned.m8n8.x2.trans.shared.b16 {%0,%1}, [%2];"
                 : "=r"(r[0]), "=r"(r[1]) : "r"(addr));
}

__device__ __forceinline__ void mma_bf16(float* c, const uint32_t* a, const uint32_t* b) {
    asm volatile(
        "mma.sync.aligned.m16n8k16.row.col.f32.bf16.bf16.f32 "
        "{%0,%1,%2,%3}, {%4,%5,%6,%7}, {%8,%9}, {%0,%1,%2,%3};\n"
        : "+f"(c[0]), "+f"(c[1]), "+f"(c[2]), "+f"(c[3])
        : "r"(a[0]), "r"(a[1]), "r"(a[2]), "r"(a[3]), "r"(b[0]), "r"(b[1]));
}

// ---------------- bf16 tensor-core GEMM (3-pass split, BK=32, 3-stage pipe) ----------------
#define A_BYTES (128 * 80)                   // 10240 per half (hi or lo)
#define AB2     (2 * A_BYTES)                // 20480
#define B_BYTES (32 * 256)                   // 8192 per half
#define STAGE_B (AB2 + 2 * B_BYTES)          // 36864
#define GSMEM   (3 * STAGE_B)                // 110592

__global__ __launch_bounds__(256, 2) void gemm_bf16(
    const __nv_bfloat16* __restrict__ Xh, const __nv_bfloat16* __restrict__ Xl, long xbs,
    int K,
    const __nv_bfloat16* __restrict__ Wh, const __nv_bfloat16* __restrict__ Wl,
    const float* __restrict__ sc, const float* __restrict__ bi,
    const float* __restrict__ res, long rbs,
    float* __restrict__ outf, long ofbs, int ofoff,
    __nv_bfloat16* __restrict__ oh, __nv_bfloat16* __restrict__ ol, long ohbs,
    int act)
{
    extern __shared__ __align__(16) char smem[];
    const uint32_t sb = s2u(smem);
    const int tid  = threadIdx.x;
    const int warp = tid >> 5;
    const int lane = tid & 31;
    const int g    = lane >> 2;
    const int tig  = lane & 3;
    const int wm   = warp >> 2;
    const int wn   = warp & 3;
    const int b  = blockIdx.z;
    const int n0 = blockIdx.x * 128;
    const int m0 = blockIdx.y * 128;

    const __nv_bfloat16* Xhb = Xh + (size_t)b * xbs;
    const __nv_bfloat16* Xlb = Xl + (size_t)b * xbs;

    float acc[4][4][4];
#pragma unroll
    for (int f = 0; f < 4; f++)
#pragma unroll
        for (int fn = 0; fn < 4; fn++)
#pragma unroll
            for (int q = 0; q < 4; q++) acc[f][fn][q] = 0.0f;

    auto issue = [&](int c, int buf) {
        const uint32_t st = sb + buf * STAGE_B;
        const int k0 = c * 32;
#pragma unroll
        for (int r = 0; r < 2; r++) {
            const int ca  = tid + 256 * r;
            const int row = ca >> 2, kc16 = ca & 3;              // A: 128 rows x 4 16B-chunks
            const uint32_t ad = st + row * 80 + kc16 * 16;
            cpa(ad,           Wh + (size_t)(m0 + row) * K + k0 + kc16 * 8);
            cpa(ad + A_BYTES, Wl + (size_t)(m0 + row) * K + k0 + kc16 * 8);
            const int kr = ca >> 4, nc2 = ca & 15;               // B: 32 rows x 16 chunks
            const uint32_t bd = st + AB2 + kr * 256 + (((uint32_t)(nc2 ^ (kr & 7))) << 4);
            cpa(bd,           Xhb + (size_t)(k0 + kr) * NPIX + n0 + nc2 * 8);
            cpa(bd + B_BYTES, Xlb + (size_t)(k0 + kr) * NPIX + n0 + nc2 * 8);
        }
        asm volatile("cp.async.commit_group;");
    };

    const int nc = K >> 5;
    issue(0, 0);
    if (nc > 1) issue(1, 1);

    const int arow  = wm * 64 + (lane & 15);
    const int akoff = (lane >> 4) * 16;
    const int blk   = lane & 15;

    int buf = 0;
    for (int c = 0; c < nc; c++) {
        if (c + 1 < nc) asm volatile("cp.async.wait_group 1;");
        else            asm volatile("cp.async.wait_group 0;");
        __syncthreads();

        const uint32_t st = sb + buf * STAGE_B;

#pragma unroll
        for (int kc = 0; kc < 2; kc++) {
            uint32_t a_h[4][4], a_l[4][4];
#pragma unroll
            for (int f = 0; f < 4; f++) {
                const uint32_t off = st + (uint32_t)(arow + f * 16) * 80 + kc * 32 + akoff;
                ldsm_x4(a_h[f], off);
                ldsm_x4(a_l[f], off + A_BYTES);
            }
#pragma unroll
            for (int fn = 0; fn < 4; fn++) {
                const int ncb = wn * 4 + fn;
                const uint32_t bd = st + AB2 + (uint32_t)(kc * 16 + blk) * 256 +
                                    (((uint32_t)(ncb ^ (blk & 7))) << 4);
                uint32_t b_h[2], b_l[2];
                ldsm_x2t(b_h, bd);
                ldsm_x2t(b_l, bd + B_BYTES);
#pragma unroll
                for (int f = 0; f < 4; f++) {
                    mma_bf16(acc[f][fn], a_h[f], b_h);
                    mma_bf16(acc[f][fn], a_h[f], b_l);
                    mma_bf16(acc[f][fn], a_l[f], b_h);
                }
            }
            if (kc == 0 && c + 2 < nc) {
                int nb = buf + 2; if (nb >= 3) nb -= 3;
                issue(c + 2, nb);
            }
        }
        if (++buf == 3) buf = 0;
    }

    // ---------------- epilogue (channel-major) ----------------
    const bool do_f = (outf != nullptr) && (m0 >= ofoff);
#pragma unroll
    for (int f = 0; f < 4; f++) {
        const int m = m0 + wm * 64 + f * 16 + g;
        const float s0 = sc[m],     b0 = bi[m];
        const float s1 = sc[m + 8], b1 = bi[m + 8];
#pragma unroll
        for (int fn = 0; fn < 4; fn++) {
            const int n = n0 + wn * 32 + fn * 8 + 2 * tig;
            float v00 = acc[f][fn][0] * s0 + b0;
            float v01 = acc[f][fn][1] * s0 + b0;
            float v10 = acc[f][fn][2] * s1 + b1;
            float v11 = acc[f][fn][3] * s1 + b1;
            if (res) {
                float2 ra = *(const float2*)(res + (size_t)b * rbs + (size_t)m * NPIX + n);
                float2 rb = *(const float2*)(res + (size_t)b * rbs + (size_t)(m + 8) * NPIX + n);
                v00 += ra.x; v01 += ra.y; v10 += rb.x; v11 += rb.y;
            }
            if (act) {
                v00 = silu_f(v00); v01 = silu_f(v01);
                v10 = silu_f(v10); v11 = silu_f(v11);
            }
            if (do_f) {
                const int mo = m - ofoff;
                *(float2*)(outf + (size_t)b * ofbs + (size_t)mo * NPIX + n) = make_float2(v00, v01);
                *(float2*)(outf + (size_t)b * ofbs + (size_t)(mo + 8) * NPIX + n) = make_float2(v10, v11);
            }
            if (oh) {
                __nv_bfloat16 h00, l00, h01, l01, h10, l10, h11, l11;
                bsplit(v00, h00, l00); bsplit(v01, h01, l01);
                bsplit(v10, h10, l10); bsplit(v11, h11, l11);
                *(__nv_bfloat162*)(oh + (size_t)b * ohbs + (size_t)m * NPIX + n)       = __nv_bfloat162(h00, h01);
                *(__nv_bfloat162*)(oh + (size_t)b * ohbs + (size_t)(m + 8) * NPIX + n) = __nv_bfloat162(h10, h11);
                *(__nv_bfloat162*)(ol + (size_t)b * ohbs + (size_t)m * NPIX + n)       = __nv_bfloat162(l00, l01);
                *(__nv_bfloat162*)(ol + (size_t)b * ohbs + (size_t)(m + 8) * NPIX + n) = __nv_bfloat162(l10, l11);
            }
        }
    }
}

// ---------------- splits ----------------
__global__ void split_k(const float4* __restrict__ src, uint2* __restrict__ hi,
                        uint2* __restrict__ lo, int n4)
{
    int i = blockIdx.x * 256 + threadIdx.x;
    if (i < n4) {
        float4 v = src[i];
        __nv_bfloat16 h[4], l[4];
        bsplit(v.x, h[0], l[0]); bsplit(v.y, h[1], l[1]);
        bsplit(v.z, h[2], l[2]); bsplit(v.w, h[3], l[3]);
        hi[i] = *(uint2*)h;
        lo[i] = *(uint2*)l;
    }
}

__global__ void wsplit_all(
    const float* __restrict__ W0, const float* __restrict__ W1,
    const float* __restrict__ W2, const float* __restrict__ W3,
    const float* __restrict__ W4, const float* __restrict__ W5,
    __nv_bfloat16* __restrict__ wh, __nv_bfloat16* __restrict__ wl)
{
    int blk = blockIdx.x;
    const float* src; int off;
    if      (blk < 256) { src = W0; off = 0;      }
    else if (blk < 384) { src = W1; off = 262144; blk -= 256; }
    else if (blk < 448) { src = W2; off = 393216; blk -= 384; }
    else if (blk < 576) { src = W3; off = 458752; blk -= 448; }
    else if (blk < 704) { src = W4; off = 589824; blk -= 576; }
    else                { src = W5; off = 720896; blk -= 704; }
    int i = blk * 256 + threadIdx.x;
    float4 v = ((const float4*)src)[i];
    __nv_bfloat16 h[4], l[4];
    bsplit(v.x, h[0], l[0]); bsplit(v.y, h[1], l[1]);
    bsplit(v.z, h[2], l[2]); bsplit(v.w, h[3], l[3]);
    ((uint2*)(wh + off))[i] = *(uint2*)h;
    ((uint2*)(wl + off))[i] = *(uint2*)l;
}

// ---------------- tensor-core flash attention ----------------
#define RS 272
#define OFF_Q 0
#define OFF_K 17408
#define OFF_V 52224
#define OFF_P 121856
#define OFF_RM 191488
#define OFF_RSUM 193536
#define ASMEM 195584

__global__ __launch_bounds__(256) void attn_mma(
    const __nv_bfloat16* __restrict__ qh, const __nv_bfloat16* __restrict__ ql,
    float* __restrict__ xa)
{
    extern __shared__ __align__(16) char smn[];
    const uint32_t sb = s2u(smn);
    float* redmax = (float*)(smn + OFF_RM);
    float* redsum = (float*)(smn + OFF_RSUM);

    const int tid = threadIdx.x;
    const int warp = tid >> 5, lane = tid & 31;
    const int g = lane >> 2, tig = lane & 3;
    const int wm = warp >> 2, wn = warp & 3;
    const int bh = blockIdx.y;
    const int r0 = blockIdx.x * 128;
    const size_t cb = (size_t)bh * 128 * NPIX;

#pragma unroll
    for (int i = 0; i < 4; i++) {
        int idx = i * 256 + tid;
        int hl = idx >> 9, row = (idx >> 4) & 31, ch = idx & 15;
        const __nv_bfloat16* src = (hl ? ql : qh) + cb + (size_t)row * NPIX + r0 + ch * 8;
        cpa(sb + OFF_Q + hl * 8704 + row * RS + ch * 16, src);
    }
    auto loadK = [&](int mt, int kb) {
#pragma unroll
        for (int i = 0; i < 4; i++) {
            int idx = i * 256 + tid;
            int hl = idx >> 9, row = (idx >> 4) & 31, ch = idx & 15;
            const __nv_bfloat16* src = (hl ? ql : qh) + cb + (size_t)(32 + row) * NPIX + mt * 128 + ch * 8;
            cpa(sb + OFF_K + kb * 17408 + hl * 8704 + row * RS + ch * 16, src);
        }
    };
    auto loadV = [&](int mt, int vb) {
#pragma unroll
        for (int i = 0; i < 8; i++) {
            int idx = i * 256 + tid;
            int hl = idx >> 10, row = (idx >> 4) & 63, ch = idx & 15;
            const __nv_bfloat16* src = (hl ? ql : qh) + cb + (size_t)(64 + row) * NPIX + mt * 128 + ch * 8;
            cpa(sb + OFF_V + vb * 34816 + hl * 17408 + row * RS + ch * 16, src);
        }
    };
    loadK(0, 0); loadV(0, 0);
    asm volatile("cp.async.commit_group;");

    float m_s[8], l_s[8];
#pragma unroll
    for (int i = 0; i < 8; i++) { m_s[i] = -1e30f; l_s[i] = 0.f; }
    float accO[4][2][4];
#pragma unroll
    for (int f = 0; f < 4; f++)
#pragma unroll
        for (int n2 = 0; n2 < 2; n2++)
#pragma unroll
            for (int q = 0; q < 4; q++) accO[f][n2][q] = 0.f;

    for (int mt = 0; mt < 8; mt++) {
        asm volatile("cp.async.wait_group 0;");
        __syncthreads();
        const int kb = mt & 1, vb = mt & 1;

        float accS[4][4][4];
#pragma unroll
        for (int f = 0; f < 4; f++)
#pragma unroll
            for (int fn = 0; fn < 4; fn++)
#pragma unroll
                for (int q = 0; q < 4; q++) accS[f][fn][q] = 0.f;

        const int krow = (lane & 7) + ((lane >> 4) << 3);
        const int mcol = ((lane >> 3) & 1) * 8;
#pragma unroll
        for (int kc = 0; kc < 2; kc++) {
            uint32_t qf_h[4][4], qf_l[4][4];
#pragma unroll
            for (int f = 0; f < 4; f++) {
                uint32_t ad = sb + OFF_Q + (kc * 16 + krow) * RS +
                              (wm * 64 + f * 16 + mcol) * 2;
                ldsm_x4t(qf_h[f], ad);
                ldsm_x4t(qf_l[f], ad + 8704);
            }
#pragma unroll
            for (int fn = 0; fn < 4; fn++) {
                uint32_t bd = sb + OFF_K + kb * 17408 + (kc * 16 + (lane & 15)) * RS +
                              (wn * 32 + fn * 8) * 2;
                uint32_t kh2[2], kl2[2];
                ldsm_x2t(kh2, bd);
                ldsm_x2t(kl2, bd + 8704);
#pragma unroll
                for (int f = 0; f < 4; f++) {
                    mma_bf16(accS[f][fn], qf_h[f], kh2);
                    mma_bf16(accS[f][fn], qf_h[f], kl2);
                    mma_bf16(accS[f][fn], qf_l[f], kh2);
                }
            }
        }

        if (mt + 1 < 8) {
            loadK(mt + 1, kb ^ 1);
            loadV(mt + 1, vb ^ 1);
        }
        asm volatile("cp.async.commit_group;");

#pragma unroll
        for (int f = 0; f < 4; f++)
#pragma unroll
            for (int h = 0; h < 2; h++) {
                float pm = -1e30f;
#pragma unroll
                for (int fn = 0; fn < 4; fn++) {
                    float x0 = accS[f][fn][2 * h]     * SCALE_ATT;
                    float x1 = accS[f][fn][2 * h + 1] * SCALE_ATT;
                    pm = fmaxf(pm, fmaxf(x0, x1));
                }
                pm = fmaxf(pm, __shfl_xor_sync(0xffffffffu, pm, 1));
                pm = fmaxf(pm, __shfl_xor_sync(0xffffffffu, pm, 2));
                if (tig == 0) redmax[(wm * 64 + f * 16 + g + 8 * h) * 4 + wn] = pm;
            }
        __syncthreads();

        float sf_[8];
#pragma unroll
        for (int f = 0; f < 4; f++)
#pragma unroll
            for (int h = 0; h < 2; h++) {
                const int r = wm * 64 + f * 16 + g + 8 * h;
                float mn = fmaxf(fmaxf(redmax[r * 4 + 0], redmax[r * 4 + 1]),
                                 fmaxf(redmax[r * 4 + 2], redmax[r * 4 + 3]));
                const int s = f * 2 + h;
                mn = fmaxf(mn, m_s[s]);
                float sf = __expf(m_s[s] - mn);
                m_s[s] = mn; l_s[s] *= sf; sf_[s] = sf;
            }
#pragma unroll
        for (int f = 0; f < 4; f++)
#pragma unroll
            for (int n2 = 0; n2 < 2; n2++) {
                accO[f][n2][0] *= sf_[f * 2];     accO[f][n2][1] *= sf_[f * 2];
                accO[f][n2][2] *= sf_[f * 2 + 1]; accO[f][n2][3] *= sf_[f * 2 + 1];
            }

#pragma unroll
        for (int f = 0; f < 4; f++) {
            float ps0 = 0.f, ps1 = 0.f;
            const uint32_t prow0 = (uint32_t)(wm * 64 + f * 16 + g) * RS;
#pragma unroll
            for (int fn = 0; fn < 4; fn++) {
                float p00 = __expf(accS[f][fn][0] * SCALE_ATT - m_s[f * 2]);
                float p01 = __expf(accS[f][fn][1] * SCALE_ATT - m_s[f * 2]);
                float p10 = __expf(accS[f][fn][2] * SCALE_ATT - m_s[f * 2 + 1]);
                float p11 = __expf(accS[f][fn][3] * SCALE_ATT - m_s[f * 2 + 1]);
                ps0 += p00 + p01; ps1 += p10 + p11;
                __nv_bfloat16 h00, l00, h01, l01, h10, l10, h11, l11;
                bsplit(p00, h00, l00); bsplit(p01, h01, l01);
                bsplit(p10, h10, l10); bsplit(p11, h11, l11);
                const uint32_t colb = (uint32_t)(wn * 32 + fn * 8 + 2 * tig) * 2;
                char* ph = smn + OFF_P;
                char* pl = smn + OFF_P + 34816;
                *(__nv_bfloat162*)(ph + prow0 + colb)            = __nv_bfloat162(h00, h01);
                *(__nv_bfloat162*)(ph + prow0 + 8 * RS + colb)   = __nv_bfloat162(h10, h11);
                *(__nv_bfloat162*)(pl + prow0 + colb)            = __nv_bfloat162(l00, l01);
                *(__nv_bfloat162*)(pl + prow0 + 8 * RS + colb)   = __nv_bfloat162(l10, l11);
            }
            ps0 += __shfl_xor_sync(0xffffffffu, ps0, 1);
            ps0 += __shfl_xor_sync(0xffffffffu, ps0, 2);
            ps1 += __shfl_xor_sync(0xffffffffu, ps1, 1);
            ps1 += __shfl_xor_sync(0xffffffffu, ps1, 2);
            if (tig == 0) {
                redsum[(wm * 64 + f * 16 + g) * 4 + wn]     = ps0;
                redsum[(wm * 64 + f * 16 + g + 8) * 4 + wn] = ps1;
            }
        }
        __syncthreads();

#pragma unroll
        for (int f = 0; f < 4; f++)
#pragma unroll
            for (int h = 0; h < 2; h++) {
                const int r = wm * 64 + f * 16 + g + 8 * h;
                l_s[f * 2 + h] += redsum[r * 4 + 0] + redsum[r * 4 + 1] +
                                  redsum[r * 4 + 2] + redsum[r * 4 + 3];
            }

        const int pmr  = (lane & 7) + ((lane >> 3) & 1) * 8;
        const int pkc8 = (lane >> 4) * 8;
#pragma unroll
        for (int kc = 0; kc < 8; kc++) {
            uint32_t pa_h[4][4], pa_l[4][4];
#pragma unroll
            for (int f = 0; f < 4; f++) {
                uint32_t ad = sb + OFF_P + (uint32_t)(wm * 64 + f * 16 + pmr) * RS +
                              (kc * 16 + pkc8) * 2;
                ldsm_x4(pa_h[f], ad);
                ldsm_x4(pa_l[f], ad + 34816);
            }
#pragma unroll
            for (int n2 = 0; n2 < 2; n2++) {
                uint32_t bd = sb + OFF_V + vb * 34816 +
                              (uint32_t)(wn * 16 + n2 * 8 + (lane & 7)) * RS +
                              (kc * 16 + ((lane >> 3) & 1) * 8) * 2;
                uint32_t vh2[2], vl2[2];
                ldsm_x2(vh2, bd);
                ldsm_x2(vl2, bd + 17408);
#pragma unroll
                for (int f = 0; f < 4; f++) {
                    mma_bf16(accO[f][n2], pa_h[f], vh2);
                    mma_bf16(accO[f][n2], pa_h[f], vl2);
                    mma_bf16(accO[f][n2], pa_l[f], vh2);
                }
            }
        }
    }

    float il[8];
#pragma unroll
    for (int s = 0; s < 8; s++) il[s] = 1.0f / l_s[s];
#pragma unroll
    for (int f = 0; f < 4; f++)
#pragma unroll
        for (int n2 = 0; n2 < 2; n2++) {
            const int d = wn * 16 + n2 * 8 + 2 * tig;
            const int r = r0 + wm * 64 + f * 16 + g;
            xa[(size_t)(bh * 64 + d) * NPIX + r]         = accO[f][n2][0] * il[f * 2];
            xa[(size_t)(bh * 64 + d + 1) * NPIX + r]     = accO[f][n2][1] * il[f * 2];
            xa[(size_t)(bh * 64 + d) * NPIX + r + 8]     = accO[f][n2][2] * il[f * 2 + 1];
            xa[(size_t)(bh * 64 + d + 1) * NPIX + r + 8] = accO[f][n2][3] * il[f * 2 + 1];
        }
}

// ---------------- depthwise 3x3 PE (reads v from bf16 hi/lo) -> xa bf16 hi/lo ----------------
__global__ __launch_bounds__(256) void dwconv_pe(
    const __nv_bfloat16* __restrict__ qh, const __nv_bfloat16* __restrict__ ql,
    const float* __restrict__ Wpe,
    const float* __restrict__ s, const float* __restrict__ bi,
    const float* __restrict__ xaf,
    __nv_bfloat16* __restrict__ xah, __nv_bfloat16* __restrict__ xal)
{
    __shared__ float t[34 * 34];
    const int c = blockIdx.x;
    const int b = blockIdx.y;
    const int qc = ((c >> 6) * 128) + 64 + (c & 63);
    const size_t srcoff = ((size_t)b * 512 + qc) * NPIX;
    const int tid = threadIdx.x;

    for (int i = tid; i < 34 * 34; i += 256) t[i] = 0.0f;
    __syncthreads();
    for (int i = tid; i < NPIX; i += 256) {
        int y = i >> 5, x = i & 31;
        t[(y + 1) * 34 + (x + 1)] =
            __bfloat162float(qh[srcoff + i]) + __bfloat162float(ql[srcoff + i]);
    }
    __syncthreads();

    float w[9];
#pragma unroll
    for (int i = 0; i < 9; i++) w[i] = Wpe[c * 9 + i];
    const float scv = s[c], bv = bi[c];
    const size_t off = ((size_t)b * 256 + c) * NPIX;

    for (int i = tid; i < NPIX; i += 256) {
        int y = i >> 5, x = i & 31;
        float acc = 0.0f;
#pragma unroll
        for (int ky = 0; ky < 3; ky++)
#pragma unroll
            for (int kx = 0; kx < 3; kx++)
                acc += w[ky * 3 + kx] * t[(y + ky) * 34 + (x + kx)];
        float v = xaf[off + i] + acc * scv + bv;
        __nv_bfloat16 h, l;
        bsplit(v, h, l);
        xah[off + i] = h;
        xal[off + i] = l;
    }
}

// ---------------- launcher ----------------
extern "C" void kernel_launch(void* const* d_in, const int* in_sizes, int n_in,
                              void* d_out, int out_size)
{
    (void)in_sizes; (void)n_in; (void)out_size;
    const float* x      = (const float*)d_in[0];
    const float* W_cv1  = (const float*)d_in[1];
    const float* s_cv1  = (const float*)d_in[2];
    const float* b_cv1  = (const float*)d_in[3];
    const float* W_qkv  = (const float*)d_in[4];
    const float* s_qkv  = (const float*)d_in[5];
    const float* b_qkv  = (const float*)d_in[6];
    const float* W_proj = (const float*)d_in[7];
    const float* s_proj = (const float*)d_in[8];
    const float* b_proj = (const float*)d_in[9];
    const float* W_pe   = (const float*)d_in[10];
    const float* s_pe   = (const float*)d_in[11];
    const float* b_pe   = (const float*)d_in[12];
    const float* W_ffn1 = (const float*)d_in[13];
    const float* s_ffn1 = (const float*)d_in[14];
    const float* b_ffn1 = (const float*)d_in[15];
    const float* W_ffn2 = (const float*)d_in[16];
    const float* s_ffn2 = (const float*)d_in[17];
    const float* b_ffn2 = (const float*)d_in[18];
    const float* W_cv2  = (const float*)d_in[19];
    const float* s_cv2  = (const float*)d_in[20];
    const float* b_cv2  = (const float*)d_in[21];

    static __nv_bfloat16 *xh = nullptr, *xl, *ch, *cl, *fh, *fl, *ah, *al, *wh, *wl;
    static float *bbf, *xaf;
    if (!xh) {
        cudaGetSymbolAddress((void**)&xh,  g_xh);
        cudaGetSymbolAddress((void**)&xl,  g_xl);
        cudaGetSymbolAddress((void**)&ch,  g_ch);
        cudaGetSymbolAddress((void**)&cl,  g_cl);
        cudaGetSymbolAddress((void**)&fh,  g_fh);
        cudaGetSymbolAddress((void**)&fl,  g_fl);
        cudaGetSymbolAddress((void**)&ah,  g_ah);
        cudaGetSymbolAddress((void**)&al,  g_al);
        cudaGetSymbolAddress((void**)&wh,  g_wh);
        cudaGetSymbolAddress((void**)&wl,  g_wl);
        cudaGetSymbolAddress((void**)&bbf,  g_bbf);
        cudaGetSymbolAddress((void**)&xaf,  g_xaf);
        cudaFuncSetAttribute(attn_mma,
                             cudaFuncAttributeMaxDynamicSharedMemorySize, ASMEM);
        cudaFuncSetAttribute(gemm_bf16,
                             cudaFuncAttributeMaxDynamicSharedMemorySize, GSMEM);
    }
    float* out = (float*)d_out;
    const long S512 = 512 * NPIX, S256 = 256 * NPIX;

    const int W_CV1 = 0, W_QKV = 262144, W_PROJ = 393216,
              W_FFN1 = 458752, W_FFN2 = 589824, W_CV2 = 720896;

    // #0: split x
    {
        int n4 = BSZ * 512 * NPIX / 4;
        split_k<<<(n4 + 255) / 256, 256>>>((const float4*)x, (uint2*)xh, (uint2*)xl, n4);
    }
    // #1: split all weights
    wsplit_all<<<960, 256>>>(W_cv1, W_qkv, W_proj, W_ffn1, W_ffn2, W_cv2, wh, wl);
    // #2: cv1 gemm (SiLU) -> cat hi/lo + bbf fp32 for ch>=256
    gemm_bf16<<<dim3(8, 4, BSZ), 256, GSMEM>>>(
        xh, xl, S512, 512, wh + W_CV1, wl + W_CV1, s_cv1, b_cv1,
        nullptr, 0, bbf, S256, 256, ch, cl, S512, 1);
    // #3: qkv gemm -> bf16 hi/lo only
    gemm_bf16<<<dim3(8, 4, BSZ), 256, GSMEM>>>(
        ch + S256, cl + S256, S512, 256, wh + W_QKV, wl + W_QKV, s_qkv, b_qkv,
        nullptr, 0, nullptr, 0, 1 << 30, fh, fl, S512, 0);
    // #4: tensor-core flash attention -> xaf (cm)
    attn_mma<<<dim3(8, 64), 256, ASMEM>>>(fh, fl, xaf);
    // #5: PE dwconv (v from bf16 hi/lo): xaf + conv(v) -> xa bf16 hi/lo
    dwconv_pe<<<dim3(256, BSZ), 256>>>(fh, fl, W_pe, s_pe, b_pe, xaf, ah, al);
    // #6: proj gemm (+bb residual, in-place bbf, re-split into cat ch256+)
    gemm_bf16<<<dim3(8, 2, BSZ), 256, GSMEM>>>(
        ah, al, S256, 256, wh + W_PROJ, wl + W_PROJ, s_proj, b_proj,
        bbf, S256, bbf, S256, 0, ch + S256, cl + S256, S512, 0);
    // #7: ffn1 gemm (SiLU)
    gemm_bf16<<<dim3(8, 4, BSZ), 256, GSMEM>>>(
        ch + S256, cl + S256, S512, 256, wh + W_FFN1, wl + W_FFN1, s_ffn1, b_ffn1,
        nullptr, 0, nullptr, 0, 1 << 30, fh, fl, S512, 1);
    // #8: ffn2 gemm (+bb2 residual -> cat ch256+)
    gemm_bf16<<<dim3(8, 2, BSZ), 256, GSMEM>>>(
        fh, fl, S512, 512, wh + W_FFN2, wl + W_FFN2, s_ffn2, b_ffn2,
        bbf, S256, nullptr, 0, 1 << 30, ch + S256, cl + S256, S512, 0);
    // #9: cv2 gemm -> out (SiLU)
    gemm_bf16<<<dim3(8, 4, BSZ), 256, GSMEM>>>(
        ch, cl, S512, 512, wh + W_CV2, wl + W_CV2, s_cv2, b_cv2,
        nullptr, 0, out, S512, 0, nullptr, nullptr, 0, 1);
}

// round 8
// speedup vs baseline: 4.9695x; 1.1089x over previous
#include <cuda_runtime.h>
#include <cuda_fp16.h>
#include <cstdint>

#define BSZ 16
#define NPIX 1024
#define SCALE_ATT 0.17677669529663687f

// ---------------- static scratch ----------------
__device__ __align__(16) __half g_xh[BSZ * 512 * NPIX], g_xl[BSZ * 512 * NPIX];
__device__ __align__(16) __half g_ch[BSZ * 512 * NPIX], g_cl[BSZ * 512 * NPIX];
__device__ __align__(16) __half g_fh[BSZ * 512 * NPIX], g_fl[BSZ * 512 * NPIX];
__device__ __align__(16) __half g_ah[BSZ * 256 * NPIX], g_al[BSZ * 256 * NPIX];
__device__ __align__(16) float g_bbf [BSZ * 256 * NPIX];  // bb chain f32 (cm)
__device__ __align__(16) float g_xaf [BSZ * 256 * NPIX];  // attn out f32 (cm)
__device__ __align__(16) __half g_wh[983040], g_wl[983040];

__device__ __forceinline__ float silu_f(float v) {
    return v / (1.0f + __expf(-v));
}

__device__ __forceinline__ void hsplit(float v, __half& h, __half& l) {
    h = __float2half_rn(v);
    l = __float2half_rn(v - __half2float(h));
}

__device__ __forceinline__ uint32_t s2u(const void* p) {
    uint32_t a;
    asm("{ .reg .u64 t; cvta.to.shared.u64 t, %1; cvt.u32.u64 %0, t; }" : "=r"(a) : "l"(p));
    return a;
}

__device__ __forceinline__ void cpa(uint32_t saddr, const void* g) {
    asm volatile("cp.async.cg.shared.global [%0], [%1], 16;" :: "r"(saddr), "l"(g));
}

__device__ __forceinline__ void ldsm_x4(uint32_t* r, uint32_t addr) {
    asm volatile("ldmatrix.sync.aligned.m8n8.x4.shared.b16 {%0,%1,%2,%3}, [%4];"
                 : "=r"(r[0]), "=r"(r[1]), "=r"(r[2]), "=r"(r[3]) : "r"(addr));
}

__device__ __forceinline__ void ldsm_x4t(uint32_t* r, uint32_t addr) {
    asm volatile("ldmatrix.sync.aligned.m8n8.x4.trans.shared.b16 {%0,%1,%2,%3}, [%4];"
                 : "=r"(r[0]), "=r"(r[1]), "=r"(r[2]), "=r"(r[3]) : "r"(addr));
}

__device__ __forceinline__ void mma_f16(float* c, const uint32_t* a, const uint32_t* b) {
    asm volatile(
        "mma.sync.aligned.m16n8k16.row.col.f32.f16.f16.f32 "
        "{%0,%1,%2,%3}, {%4,%5,%6,%7}, {%8,%9}, {%0,%1,%2,%3};\n"
        : "+f"(c[0]), "+f"(c[1]), "+f"(c[2]), "+f"(c[3])
        : "r"(a[0]), "r"(a[1]), "r"(a[2]), "r"(a[3]), "r"(b[0]), "r"(b[1]));
}

// ---------------- fp16 tensor-core GEMM (3-pass split, BK=32, 3-stage pipe) ----------------
#define A_BYTES (128 * 80)                   // 10240 per half (hi or lo)
#define AB2     (2 * A_BYTES)                // 20480
#define B_BYTES (32 * 256)                   // 8192 per half
#define STAGE_B (AB2 + 2 * B_BYTES)          // 36864
#define GSMEM   (3 * STAGE_B)                // 110592

__global__ __launch_bounds__(256, 2) void gemm_f16(
    const __half* __restrict__ Xh, const __half* __restrict__ Xl, long xbs,
    int K,
    const __half* __restrict__ Wh, const __half* __restrict__ Wl,
    const float* __restrict__ sc, const float* __restrict__ bi,
    const float* __restrict__ res, long rbs,
    float* __restrict__ outf, long ofbs, int ofoff,
    __half* __restrict__ oh, __half* __restrict__ ol, long ohbs,
    int act)
{
    extern __shared__ __align__(16) char smem[];
    const uint32_t sb = s2u(smem);
    const int tid  = threadIdx.x;
    const int warp = tid >> 5;
    const int lane = tid & 31;
    const int g    = lane >> 2;
    const int tig  = lane & 3;
    const int wm   = warp >> 2;
    const int wn   = warp & 3;
    const int b  = blockIdx.z;
    const int n0 = blockIdx.x * 128;
    const int m0 = blockIdx.y * 128;

    const __half* Xhb = Xh + (size_t)b * xbs;
    const __half* Xlb = Xl + (size_t)b * xbs;

    float acc[4][4][4];
#pragma unroll
    for (int f = 0; f < 4; f++)
#pragma unroll
        for (int fn = 0; fn < 4; fn++)
#pragma unroll
            for (int q = 0; q < 4; q++) acc[f][fn][q] = 0.0f;

    auto issue = [&](int c, int buf) {
        const uint32_t st = sb + buf * STAGE_B;
        const int k0 = c * 32;
#pragma unroll
        for (int r = 0; r < 2; r++) {
            const int ca  = tid + 256 * r;
            const int row = ca >> 2, kc16 = ca & 3;              // A: 128 rows x 4 16B-chunks
            const uint32_t ad = st + row * 80 + kc16 * 16;
            cpa(ad,           Wh + (size_t)(m0 + row) * K + k0 + kc16 * 8);
            cpa(ad + A_BYTES, Wl + (size_t)(m0 + row) * K + k0 + kc16 * 8);
            const int kr = ca >> 4, nc2 = ca & 15;               // B: 32 rows x 16 chunks
            const uint32_t bd = st + AB2 + kr * 256 + (((uint32_t)(nc2 ^ (kr & 7))) << 4);
            cpa(bd,           Xhb + (size_t)(k0 + kr) * NPIX + n0 + nc2 * 8);
            cpa(bd + B_BYTES, Xlb + (size_t)(k0 + kr) * NPIX + n0 + nc2 * 8);
        }
        asm volatile("cp.async.commit_group;");
    };

    const int nc = K >> 5;
    issue(0, 0);
    if (nc > 1) issue(1, 1);

    const int arow  = wm * 64 + (lane & 15);
    const int akoff = (lane >> 4) * 16;
    const int blk16 = lane & 15;
    const uint32_t bhl = (uint32_t)(lane >> 4) * B_BYTES;  // lanes 16-31 -> lo region

    int buf = 0;
    for (int c = 0; c < nc; c++) {
        if (c + 1 < nc) asm volatile("cp.async.wait_group 1;");
        else            asm volatile("cp.async.wait_group 0;");
        __syncthreads();

        const uint32_t st = sb + buf * STAGE_B;

#pragma unroll
        for (int kc = 0; kc < 2; kc++) {
            uint32_t a_h[4][4], a_l[4][4];
#pragma unroll
            for (int f = 0; f < 4; f++) {
                const uint32_t off = st + (uint32_t)(arow + f * 16) * 80 + kc * 32 + akoff;
                ldsm_x4(a_h[f], off);
                ldsm_x4(a_l[f], off + A_BYTES);
            }
#pragma unroll
            for (int fn = 0; fn < 4; fn++) {
                const int ncb = wn * 4 + fn;
                // x4t: lanes 0-15 hi rows, lanes 16-31 lo rows -> b_h, b_l in one issue
                const uint32_t bd = st + AB2 + bhl + (uint32_t)(kc * 16 + blk16) * 256 +
                                    (((uint32_t)(ncb ^ (blk16 & 7))) << 4);
                uint32_t b4[4];
                ldsm_x4t(b4, bd);
#pragma unroll
                for (int f = 0; f < 4; f++) {
                    mma_f16(acc[f][fn], a_h[f], b4);       // hi*hi
                    mma_f16(acc[f][fn], a_h[f], b4 + 2);   // hi*lo
                    mma_f16(acc[f][fn], a_l[f], b4);       // lo*hi
                }
            }
            if (kc == 0 && c + 2 < nc) {
                int nb = buf + 2; if (nb >= 3) nb -= 3;
                issue(c + 2, nb);
            }
        }
        if (++buf == 3) buf = 0;
    }

    // ---------------- epilogue (channel-major) ----------------
    const bool do_f = (outf != nullptr) && (m0 >= ofoff);
#pragma unroll
    for (int f = 0; f < 4; f++) {
        const int m = m0 + wm * 64 + f * 16 + g;
        const float s0 = sc[m],     b0 = bi[m];
        const float s1 = sc[m + 8], b1 = bi[m + 8];
#pragma unroll
        for (int fn = 0; fn < 4; fn++) {
            const int n = n0 + wn * 32 + fn * 8 + 2 * tig;
            float v00 = acc[f][fn][0] * s0 + b0;
            float v01 = acc[f][fn][1] * s0 + b0;
            float v10 = acc[f][fn][2] * s1 + b1;
            float v11 = acc[f][fn][3] * s1 + b1;
            if (res) {
                float2 ra = *(const float2*)(res + (size_t)b * rbs + (size_t)m * NPIX + n);
                float2 rb = *(const float2*)(res + (size_t)b * rbs + (size_t)(m + 8) * NPIX + n);
                v00 += ra.x; v01 += ra.y; v10 += rb.x; v11 += rb.y;
            }
            if (act) {
                v00 = silu_f(v00); v01 = silu_f(v01);
                v10 = silu_f(v10); v11 = silu_f(v11);
            }
            if (do_f) {
                const int mo = m - ofoff;
                *(float2*)(outf + (size_t)b * ofbs + (size_t)mo * NPIX + n) = make_float2(v00, v01);
                *(float2*)(outf + (size_t)b * ofbs + (size_t)(mo + 8) * NPIX + n) = make_float2(v10, v11);
            }
            if (oh) {
                __half h00, l00, h01, l01, h10, l10, h11, l11;
                hsplit(v00, h00, l00); hsplit(v01, h01, l01);
                hsplit(v10, h10, l10); hsplit(v11, h11, l11);
                *(__half2*)(oh + (size_t)b * ohbs + (size_t)m * NPIX + n)       = __halves2half2(h00, h01);
                *(__half2*)(oh + (size_t)b * ohbs + (size_t)(m + 8) * NPIX + n) = __halves2half2(h10, h11);
                *(__half2*)(ol + (size_t)b * ohbs + (size_t)m * NPIX + n)       = __halves2half2(l00, l01);
                *(__half2*)(ol + (size_t)b * ohbs + (size_t)(m + 8) * NPIX + n) = __halves2half2(l10, l11);
            }
        }
    }
}

// ---------------- splits ----------------
__global__ void split_k(const float4* __restrict__ src, uint2* __restrict__ hi,
                        uint2* __restrict__ lo, int n4)
{
    int i = blockIdx.x * 256 + threadIdx.x;
    if (i < n4) {
        float4 v = src[i];
        __half h[4], l[4];
        hsplit(v.x, h[0], l[0]); hsplit(v.y, h[1], l[1]);
        hsplit(v.z, h[2], l[2]); hsplit(v.w, h[3], l[3]);
        hi[i] = *(uint2*)h;
        lo[i] = *(uint2*)l;
    }
}

__global__ void wsplit_all(
    const float* __restrict__ W0, const float* __restrict__ W1,
    const float* __restrict__ W2, const float* __restrict__ W3,
    const float* __restrict__ W4, const float* __restrict__ W5,
    __half* __restrict__ wh, __half* __restrict__ wl)
{
    int blk = blockIdx.x;
    const float* src; int off;
    if      (blk < 256) { src = W0; off = 0;      }
    else if (blk < 384) { src = W1; off = 262144; blk -= 256; }
    else if (blk < 448) { src = W2; off = 393216; blk -= 384; }
    else if (blk < 576) { src = W3; off = 458752; blk -= 448; }
    else if (blk < 704) { src = W4; off = 589824; blk -= 576; }
    else                { src = W5; off = 720896; blk -= 704; }
    int i = blk * 256 + threadIdx.x;
    float4 v = ((const float4*)src)[i];
    __half h[4], l[4];
    hsplit(v.x, h[0], l[0]); hsplit(v.y, h[1], l[1]);
    hsplit(v.z, h[2], l[2]); hsplit(v.w, h[3], l[3]);
    ((uint2*)(wh + off))[i] = *(uint2*)h;
    ((uint2*)(wl + off))[i] = *(uint2*)l;
}

// ---------------- tensor-core flash attention (fp16, P fp16 single) ----------------
#define RS 272
#define OFF_Q 0
#define OFF_K 17408
#define OFF_V 52224
#define OFF_P 121856
#define OFF_RM 156672
#define OFF_RSUM 158720
#define ASMEM 160768

__global__ __launch_bounds__(256) void attn_mma(
    const __half* __restrict__ qh, const __half* __restrict__ ql,
    float* __restrict__ xa)
{
    extern __shared__ __align__(16) char smn[];
    const uint32_t sb = s2u(smn);
    float* redmax = (float*)(smn + OFF_RM);
    float* redsum = (float*)(smn + OFF_RSUM);

    const int tid = threadIdx.x;
    const int warp = tid >> 5, lane = tid & 31;
    const int g = lane >> 2, tig = lane & 3;
    const int wm = warp >> 2, wn = warp & 3;
    const int bh = blockIdx.y;
    const int r0 = blockIdx.x * 128;
    const size_t cb = (size_t)bh * 128 * NPIX;

#pragma unroll
    for (int i = 0; i < 4; i++) {
        int idx = i * 256 + tid;
        int hl = idx >> 9, row = (idx >> 4) & 31, ch = idx & 15;
        const __half* src = (hl ? ql : qh) + cb + (size_t)row * NPIX + r0 + ch * 8;
        cpa(sb + OFF_Q + hl * 8704 + row * RS + ch * 16, src);
    }
    auto loadK = [&](int mt, int kb) {
#pragma unroll
        for (int i = 0; i < 4; i++) {
            int idx = i * 256 + tid;
            int hl = idx >> 9, row = (idx >> 4) & 31, ch = idx & 15;
            const __half* src = (hl ? ql : qh) + cb + (size_t)(32 + row) * NPIX + mt * 128 + ch * 8;
            cpa(sb + OFF_K + kb * 17408 + hl * 8704 + row * RS + ch * 16, src);
        }
    };
    auto loadV = [&](int mt, int vb) {
#pragma unroll
        for (int i = 0; i < 8; i++) {
            int idx = i * 256 + tid;
            int hl = idx >> 10, row = (idx >> 4) & 63, ch = idx & 15;
            const __half* src = (hl ? ql : qh) + cb + (size_t)(64 + row) * NPIX + mt * 128 + ch * 8;
            cpa(sb + OFF_V + vb * 34816 + hl * 17408 + row * RS + ch * 16, src);
        }
    };
    loadK(0, 0); loadV(0, 0);
    asm volatile("cp.async.commit_group;");

    float m_s[8], l_s[8];
#pragma unroll
    for (int i = 0; i < 8; i++) { m_s[i] = -1e30f; l_s[i] = 0.f; }
    float accO[4][2][4];
#pragma unroll
    for (int f = 0; f < 4; f++)
#pragma unroll
        for (int n2 = 0; n2 < 2; n2++)
#pragma unroll
            for (int q = 0; q < 4; q++) accO[f][n2][q] = 0.f;

    // Q fragments hoisted (loaded once at mt==0)
    uint32_t qfh[2][4][4], qfl[2][4][4];

    const int krow = (lane & 7) + ((lane >> 4) << 3);
    const int mcol = ((lane >> 3) & 1) * 8;
    const uint32_t khl = (uint32_t)(lane >> 4) * 8704;   // K lanes 16-31 -> lo region
    const uint32_t vhl = (uint32_t)(lane >> 4) * 17408;  // V lanes 16-31 -> lo region

    for (int mt = 0; mt < 8; mt++) {
        asm volatile("cp.async.wait_group 0;");
        __syncthreads();
        const int kb = mt & 1, vb = mt & 1;

        if (mt == 0) {
#pragma unroll
            for (int kc = 0; kc < 2; kc++)
#pragma unroll
                for (int f = 0; f < 4; f++) {
                    uint32_t ad = sb + OFF_Q + (kc * 16 + krow) * RS +
                                  (wm * 64 + f * 16 + mcol) * 2;
                    ldsm_x4t(qfh[kc][f], ad);
                    ldsm_x4t(qfl[kc][f], ad + 8704);
                }
        }

        float accS[4][4][4];
#pragma unroll
        for (int f = 0; f < 4; f++)
#pragma unroll
            for (int fn = 0; fn < 4; fn++)
#pragma unroll
                for (int q = 0; q < 4; q++) accS[f][fn][q] = 0.f;

#pragma unroll
        for (int kc = 0; kc < 2; kc++) {
#pragma unroll
            for (int fn = 0; fn < 4; fn++) {
                // x4t: lanes 0-15 Kh rows, 16-31 Kl rows
                uint32_t bd = sb + OFF_K + kb * 17408 + khl +
                              (uint32_t)(kc * 16 + (lane & 15)) * RS + (wn * 32 + fn * 8) * 2;
                uint32_t k4[4];
                ldsm_x4t(k4, bd);
#pragma unroll
                for (int f = 0; f < 4; f++) {
                    mma_f16(accS[f][fn], qfh[kc][f], k4);
                    mma_f16(accS[f][fn], qfh[kc][f], k4 + 2);
                    mma_f16(accS[f][fn], qfl[kc][f], k4);
                }
            }
        }

        if (mt + 1 < 8) {
            loadK(mt + 1, kb ^ 1);
            loadV(mt + 1, vb ^ 1);
        }
        asm volatile("cp.async.commit_group;");

#pragma unroll
        for (int f = 0; f < 4; f++)
#pragma unroll
            for (int h = 0; h < 2; h++) {
                float pm = -1e30f;
#pragma unroll
                for (int fn = 0; fn < 4; fn++) {
                    float x0 = accS[f][fn][2 * h]     * SCALE_ATT;
                    float x1 = accS[f][fn][2 * h + 1] * SCALE_ATT;
                    pm = fmaxf(pm, fmaxf(x0, x1));
                }
                pm = fmaxf(pm, __shfl_xor_sync(0xffffffffu, pm, 1));
                pm = fmaxf(pm, __shfl_xor_sync(0xffffffffu, pm, 2));
                if (tig == 0) redmax[(wm * 64 + f * 16 + g + 8 * h) * 4 + wn] = pm;
            }
        __syncthreads();

        float sf_[8];
#pragma unroll
        for (int f = 0; f < 4; f++)
#pragma unroll
            for (int h = 0; h < 2; h++) {
                const int r = wm * 64 + f * 16 + g + 8 * h;
                float mn = fmaxf(fmaxf(redmax[r * 4 + 0], redmax[r * 4 + 1]),
                                 fmaxf(redmax[r * 4 + 2], redmax[r * 4 + 3]));
                const int s = f * 2 + h;
                mn = fmaxf(mn, m_s[s]);
                float sf = __expf(m_s[s] - mn);
                m_s[s] = mn; l_s[s] *= sf; sf_[s] = sf;
            }
#pragma unroll
        for (int f = 0; f < 4; f++)
#pragma unroll
            for (int n2 = 0; n2 < 2; n2++) {
                accO[f][n2][0] *= sf_[f * 2];     accO[f][n2][1] *= sf_[f * 2];
                accO[f][n2][2] *= sf_[f * 2 + 1]; accO[f][n2][3] *= sf_[f * 2 + 1];
            }

        // ---- P = exp(S - m) -> fp16 (single), row sums ----
#pragma unroll
        for (int f = 0; f < 4; f++) {
            float ps0 = 0.f, ps1 = 0.f;
            const uint32_t prow0 = (uint32_t)(wm * 64 + f * 16 + g) * RS;
#pragma unroll
            for (int fn = 0; fn < 4; fn++) {
                float p00 = __expf(accS[f][fn][0] * SCALE_ATT - m_s[f * 2]);
                float p01 = __expf(accS[f][fn][1] * SCALE_ATT - m_s[f * 2]);
                float p10 = __expf(accS[f][fn][2] * SCALE_ATT - m_s[f * 2 + 1]);
                float p11 = __expf(accS[f][fn][3] * SCALE_ATT - m_s[f * 2 + 1]);
                ps0 += p00 + p01; ps1 += p10 + p11;
                const uint32_t colb = (uint32_t)(wn * 32 + fn * 8 + 2 * tig) * 2;
                char* ph = smn + OFF_P;
                *(__half2*)(ph + prow0 + colb) =
                    __halves2half2(__float2half_rn(p00), __float2half_rn(p01));
                *(__half2*)(ph + prow0 + 8 * RS + colb) =
                    __halves2half2(__float2half_rn(p10), __float2half_rn(p11));
            }
            ps0 += __shfl_xor_sync(0xffffffffu, ps0, 1);
            ps0 += __shfl_xor_sync(0xffffffffu, ps0, 2);
            ps1 += __shfl_xor_sync(0xffffffffu, ps1, 1);
            ps1 += __shfl_xor_sync(0xffffffffu, ps1, 2);
            if (tig == 0) {
                redsum[(wm * 64 + f * 16 + g) * 4 + wn]     = ps0;
                redsum[(wm * 64 + f * 16 + g + 8) * 4 + wn] = ps1;
            }
        }
        __syncthreads();

#pragma unroll
        for (int f = 0; f < 4; f++)
#pragma unroll
            for (int h = 0; h < 2; h++) {
                const int r = wm * 64 + f * 16 + g + 8 * h;
                l_s[f * 2 + h] += redsum[r * 4 + 0] + redsum[r * 4 + 1] +
                                  redsum[r * 4 + 2] + redsum[r * 4 + 3];
            }

        // ---- O += P V (P fp16, V hi+lo => 2-term) ----
        const int pmr  = (lane & 7) + ((lane >> 3) & 1) * 8;
        const int pkc8 = (lane >> 4) * 8;
#pragma unroll
        for (int kc = 0; kc < 8; kc++) {
            uint32_t pa[4][4];
#pragma unroll
            for (int f = 0; f < 4; f++) {
                uint32_t ad = sb + OFF_P + (uint32_t)(wm * 64 + f * 16 + pmr) * RS +
                              (kc * 16 + pkc8) * 2;
                ldsm_x4(pa[f], ad);
            }
#pragma unroll
            for (int n2 = 0; n2 < 2; n2++) {
                // x4: lanes 0-15 Vh, 16-31 Vl
                uint32_t bd = sb + OFF_V + vb * 34816 + vhl +
                              (uint32_t)(wn * 16 + n2 * 8 + (lane & 7)) * RS +
                              (kc * 16 + ((lane >> 3) & 1) * 8) * 2;
                uint32_t v4[4];
                ldsm_x4(v4, bd);
#pragma unroll
                for (int f = 0; f < 4; f++) {
                    mma_f16(accO[f][n2], pa[f], v4);
                    mma_f16(accO[f][n2], pa[f], v4 + 2);
                }
            }
        }
    }

    float il[8];
#pragma unroll
    for (int s = 0; s < 8; s++) il[s] = 1.0f / l_s[s];
#pragma unroll
    for (int f = 0; f < 4; f++)
#pragma unroll
        for (int n2 = 0; n2 < 2; n2++) {
            const int d = wn * 16 + n2 * 8 + 2 * tig;
            const int r = r0 + wm * 64 + f * 16 + g;
            xa[(size_t)(bh * 64 + d) * NPIX + r]         = accO[f][n2][0] * il[f * 2];
            xa[(size_t)(bh * 64 + d + 1) * NPIX + r]     = accO[f][n2][1] * il[f * 2];
            xa[(size_t)(bh * 64 + d) * NPIX + r + 8]     = accO[f][n2][2] * il[f * 2 + 1];
            xa[(size_t)(bh * 64 + d + 1) * NPIX + r + 8] = accO[f][n2][3] * il[f * 2 + 1];
        }
}

// ---------------- depthwise 3x3 PE (reads v from fp16 hi/lo) -> xa fp16 hi/lo ----------------
__global__ __launch_bounds__(256) void dwconv_pe(
    const __half* __restrict__ qh, const __half* __restrict__ ql,
    const float* __restrict__ Wpe,
    const float* __restrict__ s, const float* __restrict__ bi,
    const float* __restrict__ xaf,
    __half* __restrict__ xah, __half* __restrict__ xal)
{
    __shared__ float t[34 * 34];
    const int c = blockIdx.x;
    const int b = blockIdx.y;
    const int qc = ((c >> 6) * 128) + 64 + (c & 63);
    const size_t srcoff = ((size_t)b * 512 + qc) * NPIX;
    const int tid = threadIdx.x;

    for (int i = tid; i < 34 * 34; i += 256) t[i] = 0.0f;
    __syncthreads();
    for (int i = tid; i < NPIX; i += 256) {
        int y = i >> 5, x = i & 31;
        t[(y + 1) * 34 + (x + 1)] =
            __half2float(qh[srcoff + i]) + __half2float(ql[srcoff + i]);
    }
    __syncthreads();

    float w[9];
#pragma unroll
    for (int i = 0; i < 9; i++) w[i] = Wpe[c * 9 + i];
    const float scv = s[c], bv = bi[c];
    const size_t off = ((size_t)b * 256 + c) * NPIX;

    for (int i = tid; i < NPIX; i += 256) {
        int y = i >> 5, x = i & 31;
        float acc = 0.0f;
#pragma unroll
        for (int ky = 0; ky < 3; ky++)
#pragma unroll
            for (int kx = 0; kx < 3; kx++)
                acc += w[ky * 3 + kx] * t[(y + ky) * 34 + (x + kx)];
        float v = xaf[off + i] + acc * scv + bv;
        __half h, l;
        hsplit(v, h, l);
        xah[off + i] = h;
        xal[off + i] = l;
    }
}

// ---------------- launcher ----------------
extern "C" void kernel_launch(void* const* d_in, const int* in_sizes, int n_in,
                              void* d_out, int out_size)
{
    (void)in_sizes; (void)n_in; (void)out_size;
    const float* x      = (const float*)d_in[0];
    const float* W_cv1  = (const float*)d_in[1];
    const float* s_cv1  = (const float*)d_in[2];
    const float* b_cv1  = (const float*)d_in[3];
    const float* W_qkv  = (const float*)d_in[4];
    const float* s_qkv  = (const float*)d_in[5];
    const float* b_qkv  = (const float*)d_in[6];
    const float* W_proj = (const float*)d_in[7];
    const float* s_proj = (const float*)d_in[8];
    const float* b_proj = (const float*)d_in[9];
    const float* W_pe   = (const float*)d_in[10];
    const float* s_pe   = (const float*)d_in[11];
    const float* b_pe   = (const float*)d_in[12];
    const float* W_ffn1 = (const float*)d_in[13];
    const float* s_ffn1 = (const float*)d_in[14];
    const float* b_ffn1 = (const float*)d_in[15];
    const float* W_ffn2 = (const float*)d_in[16];
    const float* s_ffn2 = (const float*)d_in[17];
    const float* b_ffn2 = (const float*)d_in[18];
    const float* W_cv2  = (const float*)d_in[19];
    const float* s_cv2  = (const float*)d_in[20];
    const float* b_cv2  = (const float*)d_in[21];

    static __half *xh = nullptr, *xl, *ch, *cl, *fh, *fl, *ah, *al, *wh, *wl;
    static float *bbf, *xaf;
    if (!xh) {
        cudaGetSymbolAddress((void**)&xh,  g_xh);
        cudaGetSymbolAddress((void**)&xl,  g_xl);
        cudaGetSymbolAddress((void**)&ch,  g_ch);
        cudaGetSymbolAddress((void**)&cl,  g_cl);
        cudaGetSymbolAddress((void**)&fh,  g_fh);
        cudaGetSymbolAddress((void**)&fl,  g_fl);
        cudaGetSymbolAddress((void**)&ah,  g_ah);
        cudaGetSymbolAddress((void**)&al,  g_al);
        cudaGetSymbolAddress((void**)&wh,  g_wh);
        cudaGetSymbolAddress((void**)&wl,  g_wl);
        cudaGetSymbolAddress((void**)&bbf,  g_bbf);
        cudaGetSymbolAddress((void**)&xaf,  g_xaf);
        cudaFuncSetAttribute(attn_mma,
                             cudaFuncAttributeMaxDynamicSharedMemorySize, ASMEM);
        cudaFuncSetAttribute(gemm_f16,
                             cudaFuncAttributeMaxDynamicSharedMemorySize, GSMEM);
    }
    float* out = (float*)d_out;
    const long S512 = 512 * NPIX, S256 = 256 * NPIX;

    const int W_CV1 = 0, W_QKV = 262144, W_PROJ = 393216,
              W_FFN1 = 458752, W_FFN2 = 589824, W_CV2 = 720896;

    // #0: split x
    {
        int n4 = BSZ * 512 * NPIX / 4;
        split_k<<<(n4 + 255) / 256, 256>>>((const float4*)x, (uint2*)xh, (uint2*)xl, n4);
    }
    // #1: split all weights
    wsplit_all<<<960, 256>>>(W_cv1, W_qkv, W_proj, W_ffn1, W_ffn2, W_cv2, wh, wl);
    // #2: cv1 gemm (SiLU) -> cat hi/lo + bbf fp32 for ch>=256
    gemm_f16<<<dim3(8, 4, BSZ), 256, GSMEM>>>(
        xh, xl, S512, 512, wh + W_CV1, wl + W_CV1, s_cv1, b_cv1,
        nullptr, 0, bbf, S256, 256, ch, cl, S512, 1);
    // #3: qkv gemm -> fp16 hi/lo only
    gemm_f16<<<dim3(8, 4, BSZ), 256, GSMEM>>>(
        ch + S256, cl + S256, S512, 256, wh + W_QKV, wl + W_QKV, s_qkv, b_qkv,
        nullptr, 0, nullptr, 0, 1 << 30, fh, fl, S512, 0);
    // #4: tensor-core flash attention -> xaf (cm)
    attn_mma<<<dim3(8, 64), 256, ASMEM>>>(fh, fl, xaf);
    // #5: PE dwconv (v from fp16 hi/lo): xaf + conv(v) -> xa fp16 hi/lo
    dwconv_pe<<<dim3(256, BSZ), 256>>>(fh, fl, W_pe, s_pe, b_pe, xaf, ah, al);
    // #6: proj gemm (+bb residual, in-place bbf, re-split into cat ch256+)
    gemm_f16<<<dim3(8, 2, BSZ), 256, GSMEM>>>(
        ah, al, S256, 256, wh + W_PROJ, wl + W_PROJ, s_proj, b_proj,
        bbf, S256, bbf, S256, 0, ch + S256, cl + S256, S512, 0);
    // #7: ffn1 gemm (SiLU)
    gemm_f16<<<dim3(8, 4, BSZ), 256, GSMEM>>>(
        ch + S256, cl + S256, S512, 256, wh + W_FFN1, wl + W_FFN1, s_ffn1, b_ffn1,
        nullptr, 0, nullptr, 0, 1 << 30, fh, fl, S512, 1);
    // #8: ffn2 gemm (+bb2 residual -> cat ch256+)
    gemm_f16<<<dim3(8, 2, BSZ), 256, GSMEM>>>(
        fh, fl, S512, 512, wh + W_FFN2, wl + W_FFN2, s_ffn2, b_ffn2,
        bbf, S256, nullptr, 0, 1 << 30, ch + S256, cl + S256, S512, 0);
    // #9: cv2 gemm -> out (SiLU)
    gemm_f16<<<dim3(8, 4, BSZ), 256, GSMEM>>>(
        ch, cl, S512, 512, wh + W_CV2, wl + W_CV2, s_cv2, b_cv2,
        nullptr, 0, out, S512, 0, nullptr, nullptr, 0, 1);
}

// round 10
// speedup vs baseline: 5.1342x; 1.0331x over previous
#include <cuda_runtime.h>
#include <cuda_fp16.h>
#include <cstdint>

#define BSZ 16
#define NPIX 1024
#define SCALE_ATT 0.17677669529663687f

// ---------------- static scratch ----------------
__device__ __align__(16) __half g_xh[BSZ * 512 * NPIX], g_xl[BSZ * 512 * NPIX];
__device__ __align__(16) __half g_ch[BSZ * 512 * NPIX], g_cl[BSZ * 512 * NPIX];
__device__ __align__(16) __half g_fh[BSZ * 512 * NPIX], g_fl[BSZ * 512 * NPIX];
__device__ __align__(16) __half g_ah[BSZ * 256 * NPIX], g_al[BSZ * 256 * NPIX];
__device__ __align__(16) float g_bbf [BSZ * 256 * NPIX];  // bb chain f32 (cm)
__device__ __align__(16) float g_xaf [BSZ * 256 * NPIX];  // attn out f32 (cm)
__device__ __align__(16) __half g_wh[983040], g_wl[983040];

__device__ __forceinline__ float silu_f(float v) {
    return v / (1.0f + __expf(-v));
}

__device__ __forceinline__ void hsplit(float v, __half& h, __half& l) {
    h = __float2half_rn(v);
    l = __float2half_rn(v - __half2float(h));
}

__device__ __forceinline__ uint32_t s2u(const void* p) {
    uint32_t a;
    asm("{ .reg .u64 t; cvta.to.shared.u64 t, %1; cvt.u32.u64 %0, t; }" : "=r"(a) : "l"(p));
    return a;
}

__device__ __forceinline__ void cpa(uint32_t saddr, const void* g) {
    asm volatile("cp.async.cg.shared.global [%0], [%1], 16;" :: "r"(saddr), "l"(g));
}

__device__ __forceinline__ void ldsm_x4(uint32_t* r, uint32_t addr) {
    asm volatile("ldmatrix.sync.aligned.m8n8.x4.shared.b16 {%0,%1,%2,%3}, [%4];"
                 : "=r"(r[0]), "=r"(r[1]), "=r"(r[2]), "=r"(r[3]) : "r"(addr));
}

__device__ __forceinline__ void ldsm_x4t(uint32_t* r, uint32_t addr) {
    asm volatile("ldmatrix.sync.aligned.m8n8.x4.trans.shared.b16 {%0,%1,%2,%3}, [%4];"
                 : "=r"(r[0]), "=r"(r[1]), "=r"(r[2]), "=r"(r[3]) : "r"(addr));
}

__device__ __forceinline__ void mma_f16(float* c, const uint32_t* a, const uint32_t* b) {
    asm volatile(
        "mma.sync.aligned.m16n8k16.row.col.f32.f16.f16.f32 "
        "{%0,%1,%2,%3}, {%4,%5,%6,%7}, {%8,%9}, {%0,%1,%2,%3};\n"
        : "+f"(c[0]), "+f"(c[1]), "+f"(c[2]), "+f"(c[3])
        : "r"(a[0]), "r"(a[1]), "r"(a[2]), "r"(a[3]), "r"(b[0]), "r"(b[1]));
}

// ---------------- fp16 tensor-core GEMM (3-pass split, BK=32, 3-stage pipe) ----------------
#define A_BYTES (128 * 80)
#define AB2     (2 * A_BYTES)
#define B_BYTES (32 * 256)
#define STAGE_B (AB2 + 2 * B_BYTES)  // 36864
#define GSMEM   (3 * STAGE_B)        // 110592

__global__ __launch_bounds__(256, 2) void gemm_f16(
    const __half* __restrict__ Xh, const __half* __restrict__ Xl, long xbs,
    int K,
    const __half* __restrict__ Wh, const __half* __restrict__ Wl,
    const float* __restrict__ sc, const float* __restrict__ bi,
    const float* __restrict__ res, long rbs,
    float* __restrict__ outf, long ofbs, int ofoff,
    __half* __restrict__ oh, __half* __restrict__ ol, long ohbs,
    int act)
{
    extern __shared__ __align__(16) char smem[];
    const uint32_t sb = s2u(smem);
    const int tid  = threadIdx.x;
    const int warp = tid >> 5;
    const int lane = tid & 31;
    const int g    = lane >> 2;
    const int tig  = lane & 3;
    const int wm   = warp >> 2;
    const int wn   = warp & 3;
    const int b  = blockIdx.z;
    const int n0 = blockIdx.x * 128;
    const int m0 = blockIdx.y * 128;

    const __half* Xhb = Xh + (size_t)b * xbs;
    const __half* Xlb = Xl + (size_t)b * xbs;

    float acc[4][4][4];
#pragma unroll
    for (int f = 0; f < 4; f++)
#pragma unroll
        for (int fn = 0; fn < 4; fn++)
#pragma unroll
            for (int q = 0; q < 4; q++) acc[f][fn][q] = 0.0f;

    auto issue = [&](int c, int buf) {
        const uint32_t st = sb + buf * STAGE_B;
        const int k0 = c * 32;
#pragma unroll
        for (int r = 0; r < 2; r++) {
            const int ca  = tid + 256 * r;
            const int row = ca >> 2, kc16 = ca & 3;
            const uint32_t ad = st + row * 80 + kc16 * 16;
            cpa(ad,           Wh + (size_t)(m0 + row) * K + k0 + kc16 * 8);
            cpa(ad + A_BYTES, Wl + (size_t)(m0 + row) * K + k0 + kc16 * 8);
            const int kr = ca >> 4, nc2 = ca & 15;
            const uint32_t bd = st + AB2 + kr * 256 + (((uint32_t)(nc2 ^ (kr & 7))) << 4);
            cpa(bd,           Xhb + (size_t)(k0 + kr) * NPIX + n0 + nc2 * 8);
            cpa(bd + B_BYTES, Xlb + (size_t)(k0 + kr) * NPIX + n0 + nc2 * 8);
        }
        asm volatile("cp.async.commit_group;");
    };

    const int nc = K >> 5;
    issue(0, 0);
    if (nc > 1) issue(1, 1);

    const int arow  = wm * 64 + (lane & 15);
    const int akoff = (lane >> 4) * 16;
    const int blk16 = lane & 15;
    const uint32_t bhl = (uint32_t)(lane >> 4) * B_BYTES;

    int buf = 0;
    for (int c = 0; c < nc; c++) {
        if (c + 1 < nc) asm volatile("cp.async.wait_group 1;");
        else            asm volatile("cp.async.wait_group 0;");
        __syncthreads();

        const uint32_t st = sb + buf * STAGE_B;

#pragma unroll
        for (int kc = 0; kc < 2; kc++) {
            uint32_t a_h[4][4], a_l[4][4];
#pragma unroll
            for (int f = 0; f < 4; f++) {
                const uint32_t off = st + (uint32_t)(arow + f * 16) * 80 + kc * 32 + akoff;
                ldsm_x4(a_h[f], off);
                ldsm_x4(a_l[f], off + A_BYTES);
            }
#pragma unroll
            for (int fn = 0; fn < 4; fn++) {
                const int ncb = wn * 4 + fn;
                const uint32_t bd = st + AB2 + bhl + (uint32_t)(kc * 16 + blk16) * 256 +
                                    (((uint32_t)(ncb ^ (blk16 & 7))) << 4);
                uint32_t b4[4];
                ldsm_x4t(b4, bd);
#pragma unroll
                for (int f = 0; f < 4; f++) {
                    mma_f16(acc[f][fn], a_h[f], b4);
                    mma_f16(acc[f][fn], a_h[f], b4 + 2);
                    mma_f16(acc[f][fn], a_l[f], b4);
                }
            }
            if (kc == 0 && c + 2 < nc) {
                int nb = buf + 2; if (nb >= 3) nb -= 3;
                issue(c + 2, nb);
            }
        }
        if (++buf == 3) buf = 0;
    }

    const bool do_f = (outf != nullptr) && (m0 >= ofoff);
#pragma unroll
    for (int f = 0; f < 4; f++) {
        const int m = m0 + wm * 64 + f * 16 + g;
        const float s0 = sc[m],     b0 = bi[m];
        const float s1 = sc[m + 8], b1 = bi[m + 8];
#pragma unroll
        for (int fn = 0; fn < 4; fn++) {
            const int n = n0 + wn * 32 + fn * 8 + 2 * tig;
            float v00 = acc[f][fn][0] * s0 + b0;
            float v01 = acc[f][fn][1] * s0 + b0;
            float v10 = acc[f][fn][2] * s1 + b1;
            float v11 = acc[f][fn][3] * s1 + b1;
            if (res) {
                float2 ra = *(const float2*)(res + (size_t)b * rbs + (size_t)m * NPIX + n);
                float2 rb = *(const float2*)(res + (size_t)b * rbs + (size_t)(m + 8) * NPIX + n);
                v00 += ra.x; v01 += ra.y; v10 += rb.x; v11 += rb.y;
            }
            if (act) {
                v00 = silu_f(v00); v01 = silu_f(v01);
                v10 = silu_f(v10); v11 = silu_f(v11);
            }
            if (do_f) {
                const int mo = m - ofoff;
                *(float2*)(outf + (size_t)b * ofbs + (size_t)mo * NPIX + n) = make_float2(v00, v01);
                *(float2*)(outf + (size_t)b * ofbs + (size_t)(mo + 8) * NPIX + n) = make_float2(v10, v11);
            }
            if (oh) {
                __half h00, l00, h01, l01, h10, l10, h11, l11;
                hsplit(v00, h00, l00); hsplit(v01, h01, l01);
                hsplit(v10, h10, l10); hsplit(v11, h11, l11);
                *(__half2*)(oh + (size_t)b * ohbs + (size_t)m * NPIX + n)       = __halves2half2(h00, h01);
                *(__half2*)(oh + (size_t)b * ohbs + (size_t)(m + 8) * NPIX + n) = __halves2half2(h10, h11);
                *(__half2*)(ol + (size_t)b * ohbs + (size_t)m * NPIX + n)       = __halves2half2(l00, l01);
                *(__half2*)(ol + (size_t)b * ohbs + (size_t)(m + 8) * NPIX + n) = __halves2half2(l10, l11);
            }
        }
    }
}

// ---------------- splits ----------------
__global__ void split_k(const float4* __restrict__ src, uint2* __restrict__ hi,
                        uint2* __restrict__ lo, int n4)
{
    int i = blockIdx.x * 256 + threadIdx.x;
    if (i < n4) {
        float4 v = src[i];
        __half h[4], l[4];
        hsplit(v.x, h[0], l[0]); hsplit(v.y, h[1], l[1]);
        hsplit(v.z, h[2], l[2]); hsplit(v.w, h[3], l[3]);
        hi[i] = *(uint2*)h;
        lo[i] = *(uint2*)l;
    }
}

__global__ void wsplit_all(
    const float* __restrict__ W0, const float* __restrict__ W1,
    const float* __restrict__ W2, const float* __restrict__ W3,
    const float* __restrict__ W4, const float* __restrict__ W5,
    __half* __restrict__ wh, __half* __restrict__ wl)
{
    int blk = blockIdx.x;
    const float* src; int off;
    if      (blk < 256) { src = W0; off = 0;      }
    else if (blk < 384) { src = W1; off = 262144; blk -= 256; }
    else if (blk < 448) { src = W2; off = 393216; blk -= 384; }
    else if (blk < 576) { src = W3; off = 458752; blk -= 448; }
    else if (blk < 704) { src = W4; off = 589824; blk -= 576; }
    else                { src = W5; off = 720896; blk -= 704; }
    int i = blk * 256 + threadIdx.x;
    float4 v = ((const float4*)src)[i];
    __half h[4], l[4];
    hsplit(v.x, h[0], l[0]); hsplit(v.y, h[1], l[1]);
    hsplit(v.z, h[2], l[2]); hsplit(v.w, h[3], l[3]);
    ((uint2*)(wh + off))[i] = *(uint2*)h;
    ((uint2*)(wl + off))[i] = *(uint2*)l;
}

// ---------------- tensor-core flash attention ----------------
// Q plain fp16; K hi/lo (2-term QK, SINGLE buffer, reloaded after QK phase);
// V plain fp16 double-buffered (1-term PV); P plain fp16.
// All row strides 272 B (17x16: ldmatrix-legal + conflict-free). 2 CTAs/SM.
#define RS 272
#define OFF_Q 0                     // 32 x 272            = 8704
#define OFF_RM 8704                 // 2048
#define OFF_RSUM 10752              // 2048
#define OFF_K 12800                 // hi+lo: 2 x 32 x 272 = 17408 (single buffer)
#define OFF_V 30208                 // 2 buf x 64 x 272    = 34816
#define VBUF 17408
#define OFF_P 65024                 // 128 x 272           = 34816
#define ASMEM 99840

__global__ __launch_bounds__(256, 2) void attn_mma(
    const __half* __restrict__ qh, const __half* __restrict__ ql,
    float* __restrict__ xa)
{
    extern __shared__ __align__(16) char smn[];
    const uint32_t sb = s2u(smn);
    float* redmax = (float*)(smn + OFF_RM);
    float* redsum = (float*)(smn + OFF_RSUM);

    const int tid = threadIdx.x;
    const int warp = tid >> 5, lane = tid & 31;
    const int g = lane >> 2, tig = lane & 3;
    const int wm = warp >> 2, wn = warp & 3;
    const int bh = blockIdx.y;
    const int r0 = blockIdx.x * 128;
    const size_t cb = (size_t)bh * 128 * NPIX;

    // Q (hi only): 32 rows x 16 chunks
#pragma unroll
    for (int i = 0; i < 2; i++) {
        int idx = i * 256 + tid;
        int row = idx >> 4, ch = idx & 15;
        cpa(sb + OFF_Q + row * RS + ch * 16, qh + cb + (size_t)row * NPIX + r0 + ch * 8);
    }
    auto loadK = [&](int mt) {
#pragma unroll
        for (int i = 0; i < 4; i++) {
            int idx = i * 256 + tid;
            int hl = idx >> 9, row = (idx >> 4) & 31, ch = idx & 15;
            const __half* src = (hl ? ql : qh) + cb + (size_t)(32 + row) * NPIX + mt * 128 + ch * 8;
            cpa(sb + OFF_K + hl * 8704 + row * RS + ch * 16, src);
        }
    };
    auto loadV = [&](int mt, int vb) {
#pragma unroll
        for (int i = 0; i < 4; i++) {
            int idx = i * 256 + tid;
            int row = (idx >> 4) & 63, ch = idx & 15;
            const __half* src = qh + cb + (size_t)(64 + row) * NPIX + mt * 128 + ch * 8;
            cpa(sb + OFF_V + vb * VBUF + row * RS + ch * 16, src);
        }
    };
    loadK(0); loadV(0, 0);
    asm volatile("cp.async.commit_group;");

    float m_s[8], l_s[8];
#pragma unroll
    for (int i = 0; i < 8; i++) { m_s[i] = -1e30f; l_s[i] = 0.f; }
    float accO[4][2][4];
#pragma unroll
    for (int f = 0; f < 4; f++)
#pragma unroll
        for (int n2 = 0; n2 < 2; n2++)
#pragma unroll
            for (int q = 0; q < 4; q++) accO[f][n2][q] = 0.f;

    const int krow = (lane & 7) + ((lane >> 4) << 3);
    const int mcol = ((lane >> 3) & 1) * 8;
    const uint32_t khl = (uint32_t)(lane >> 4) * 8704;   // K lanes 16-31 -> lo half
    const int vrow = ((lane >> 4) << 3) + (lane & 7);    // +8 rows for lanes 16-31
    const int vch  = ((lane >> 3) & 1) * 8;

    for (int mt = 0; mt < 8; mt++) {
        asm volatile("cp.async.wait_group 0;");
        __syncthreads();
        const int vb = mt & 1;

        // ---- S = Q K^T (Q fp16, K hi+lo => 2-term) ----
        float accS[4][4][4];
#pragma unroll
        for (int f = 0; f < 4; f++)
#pragma unroll
            for (int fn = 0; fn < 4; fn++)
#pragma unroll
                for (int q = 0; q < 4; q++) accS[f][fn][q] = 0.f;

#pragma unroll
        for (int kc = 0; kc < 2; kc++) {
            uint32_t qf[4][4];
#pragma unroll
            for (int f = 0; f < 4; f++) {
                uint32_t ad = sb + OFF_Q + (kc * 16 + krow) * RS +
                              (wm * 64 + f * 16 + mcol) * 2;
                ldsm_x4t(qf[f], ad);
            }
#pragma unroll
            for (int fn = 0; fn < 4; fn++) {
                uint32_t bd = sb + OFF_K + khl +
                              (uint32_t)(kc * 16 + (lane & 15)) * RS + (wn * 32 + fn * 8) * 2;
                uint32_t k4[4];
                ldsm_x4t(k4, bd);
#pragma unroll
                for (int f = 0; f < 4; f++) {
                    mma_f16(accS[f][fn], qf[f], k4);
                    mma_f16(accS[f][fn], qf[f], k4 + 2);
                }
            }
        }

        // ---- softmax max-reduce (barrier also fences K reads) ----
#pragma unroll
        for (int f = 0; f < 4; f++)
#pragma unroll
            for (int h = 0; h < 2; h++) {
                float pm = -1e30f;
#pragma unroll
                for (int fn = 0; fn < 4; fn++) {
                    float x0 = accS[f][fn][2 * h]     * SCALE_ATT;
                    float x1 = accS[f][fn][2 * h + 1] * SCALE_ATT;
                    pm = fmaxf(pm, fmaxf(x0, x1));
                }
                pm = fmaxf(pm, __shfl_xor_sync(0xffffffffu, pm, 1));
                pm = fmaxf(pm, __shfl_xor_sync(0xffffffffu, pm, 2));
                if (tig == 0) redmax[(wm * 64 + f * 16 + g + 8 * h) * 4 + wn] = pm;
            }
        __syncthreads();

        // K buffer free now: prefetch next K (and V into the other buffer)
        if (mt + 1 < 8) {
            loadK(mt + 1);
            loadV(mt + 1, vb ^ 1);
        }
        asm volatile("cp.async.commit_group;");

        float sf_[8];
#pragma unroll
        for (int f = 0; f < 4; f++)
#pragma unroll
            for (int h = 0; h < 2; h++) {
                const int r = wm * 64 + f * 16 + g + 8 * h;
                float mn = fmaxf(fmaxf(redmax[r * 4 + 0], redmax[r * 4 + 1]),
                                 fmaxf(redmax[r * 4 + 2], redmax[r * 4 + 3]));
                const int s = f * 2 + h;
                mn = fmaxf(mn, m_s[s]);
                float sf = __expf(m_s[s] - mn);
                m_s[s] = mn; l_s[s] *= sf; sf_[s] = sf;
            }
#pragma unroll
        for (int f = 0; f < 4; f++)
#pragma unroll
            for (int n2 = 0; n2 < 2; n2++) {
                accO[f][n2][0] *= sf_[f * 2];     accO[f][n2][1] *= sf_[f * 2];
                accO[f][n2][2] *= sf_[f * 2 + 1]; accO[f][n2][3] *= sf_[f * 2 + 1];
            }

        // ---- P = exp(S - m) -> fp16, row sums ----
#pragma unroll
        for (int f = 0; f < 4; f++) {
            float ps0 = 0.f, ps1 = 0.f;
            const uint32_t prow0 = (uint32_t)(wm * 64 + f * 16 + g) * RS;
#pragma unroll
            for (int fn = 0; fn < 4; fn++) {
                float p00 = __expf(accS[f][fn][0] * SCALE_ATT - m_s[f * 2]);
                float p01 = __expf(accS[f][fn][1] * SCALE_ATT - m_s[f * 2]);
                float p10 = __expf(accS[f][fn][2] * SCALE_ATT - m_s[f * 2 + 1]);
                float p11 = __expf(accS[f][fn][3] * SCALE_ATT - m_s[f * 2 + 1]);
                ps0 += p00 + p01; ps1 += p10 + p11;
                const uint32_t colb = (uint32_t)(wn * 32 + fn * 8 + 2 * tig) * 2;
                char* ph = smn + OFF_P;
                *(__half2*)(ph + prow0 + colb) =
                    __halves2half2(__float2half_rn(p00), __float2half_rn(p01));
                *(__half2*)(ph + prow0 + 8 * RS + colb) =
                    __halves2half2(__float2half_rn(p10), __float2half_rn(p11));
            }
            ps0 += __shfl_xor_sync(0xffffffffu, ps0, 1);
            ps0 += __shfl_xor_sync(0xffffffffu, ps0, 2);
            ps1 += __shfl_xor_sync(0xffffffffu, ps1, 1);
            ps1 += __shfl_xor_sync(0xffffffffu, ps1, 2);
            if (tig == 0) {
                redsum[(wm * 64 + f * 16 + g) * 4 + wn]     = ps0;
                redsum[(wm * 64 + f * 16 + g + 8) * 4 + wn] = ps1;
            }
        }
        __syncthreads();

#pragma unroll
        for (int f = 0; f < 4; f++)
#pragma unroll
            for (int h = 0; h < 2; h++) {
                const int r = wm * 64 + f * 16 + g + 8 * h;
                l_s[f * 2 + h] += redsum[r * 4 + 0] + redsum[r * 4 + 1] +
                                  redsum[r * 4 + 2] + redsum[r * 4 + 3];
            }

        // ---- O += P V (both fp16, 1-term; one x4 feeds both n2 tiles) ----
        const int pmr  = (lane & 7) + ((lane >> 3) & 1) * 8;
        const int pkc8 = (lane >> 4) * 8;
#pragma unroll
        for (int kc = 0; kc < 8; kc++) {
            uint32_t pa[4][4];
#pragma unroll
            for (int f = 0; f < 4; f++) {
                uint32_t ad = sb + OFF_P + (uint32_t)(wm * 64 + f * 16 + pmr) * RS +
                              (kc * 16 + pkc8) * 2;
                ldsm_x4(pa[f], ad);
            }
            uint32_t v4[4];
            {
                uint32_t bd = sb + OFF_V + vb * VBUF +
                              (uint32_t)(wn * 16 + vrow) * RS + (kc * 16 + vch) * 2;
                ldsm_x4(v4, bd);
            }
#pragma unroll
            for (int n2 = 0; n2 < 2; n2++)
#pragma unroll
                for (int f = 0; f < 4; f++)
                    mma_f16(accO[f][n2], pa[f], v4 + 2 * n2);
        }
    }

    float il[8];
#pragma unroll
    for (int s = 0; s < 8; s++) il[s] = 1.0f / l_s[s];
#pragma unroll
    for (int f = 0; f < 4; f++)
#pragma unroll
        for (int n2 = 0; n2 < 2; n2++) {
            const int d = wn * 16 + n2 * 8 + 2 * tig;
            const int r = r0 + wm * 64 + f * 16 + g;
            xa[(size_t)(bh * 64 + d) * NPIX + r]         = accO[f][n2][0] * il[f * 2];
            xa[(size_t)(bh * 64 + d + 1) * NPIX + r]     = accO[f][n2][1] * il[f * 2];
            xa[(size_t)(bh * 64 + d) * NPIX + r + 8]     = accO[f][n2][2] * il[f * 2 + 1];
            xa[(size_t)(bh * 64 + d + 1) * NPIX + r + 8] = accO[f][n2][3] * il[f * 2 + 1];
        }
}

// ---------------- depthwise 3x3 PE (reads v from fp16 hi/lo) -> xa fp16 hi/lo ----------------
__global__ __launch_bounds__(256) void dwconv_pe(
    const __half* __restrict__ qh, const __half* __restrict__ ql,
    const float* __restrict__ Wpe,
    const float* __restrict__ s, const float* __restrict__ bi,
    const float* __restrict__ xaf,
    __half* __restrict__ xah, __half* __restrict__ xal)
{
    __shared__ float t[34 * 34];
    const int c = blockIdx.x;
    const int b = blockIdx.y;
    const int qc = ((c >> 6) * 128) + 64 + (c & 63);
    const size_t srcoff = ((size_t)b * 512 + qc) * NPIX;
    const int tid = threadIdx.x;

    for (int i = tid; i < 34 * 34; i += 256) t[i] = 0.0f;
    __syncthreads();
    for (int i = tid; i < NPIX; i += 256) {
        int y = i >> 5, x = i & 31;
        t[(y + 1) * 34 + (x + 1)] =
            __half2float(qh[srcoff + i]) + __half2float(ql[srcoff + i]);
    }
    __syncthreads();

    float w[9];
#pragma unroll
    for (int i = 0; i < 9; i++) w[i] = Wpe[c * 9 + i];
    const float scv = s[c], bv = bi[c];
    const size_t off = ((size_t)b * 256 + c) * NPIX;

    for (int i = tid; i < NPIX; i += 256) {
        int y = i >> 5, x = i & 31;
        float acc = 0.0f;
#pragma unroll
        for (int ky = 0; ky < 3; ky++)
#pragma unroll
            for (int kx = 0; kx < 3; kx++)
                acc += w[ky * 3 + kx] * t[(y + ky) * 34 + (x + kx)];
        float v = xaf[off + i] + acc * scv + bv;
        __half h, l;
        hsplit(v, h, l);
        xah[off + i] = h;
        xal[off + i] = l;
    }
}

// ---------------- launcher ----------------
extern "C" void kernel_launch(void* const* d_in, const int* in_sizes, int n_in,
                              void* d_out, int out_size)
{
    (void)in_sizes; (void)n_in; (void)out_size;
    const float* x      = (const float*)d_in[0];
    const float* W_cv1  = (const float*)d_in[1];
    const float* s_cv1  = (const float*)d_in[2];
    const float* b_cv1  = (const float*)d_in[3];
    const float* W_qkv  = (const float*)d_in[4];
    const float* s_qkv  = (const float*)d_in[5];
    const float* b_qkv  = (const float*)d_in[6];
    const float* W_proj = (const float*)d_in[7];
    const float* s_proj = (const float*)d_in[8];
    const float* b_proj = (const float*)d_in[9];
    const float* W_pe   = (const float*)d_in[10];
    const float* s_pe   = (const float*)d_in[11];
    const float* b_pe   = (const float*)d_in[12];
    const float* W_ffn1 = (const float*)d_in[13];
    const float* s_ffn1 = (const float*)d_in[14];
    const float* b_ffn1 = (const float*)d_in[15];
    const float* W_ffn2 = (const float*)d_in[16];
    const float* s_ffn2 = (const float*)d_in[17];
    const float* b_ffn2 = (const float*)d_in[18];
    const float* W_cv2  = (const float*)d_in[19];
    const float* s_cv2  = (const float*)d_in[20];
    const float* b_cv2  = (const float*)d_in[21];

    static __half *xh = nullptr, *xl, *ch, *cl, *fh, *fl, *ah, *al, *wh, *wl;
    static float *bbf, *xaf;
    if (!xh) {
        cudaGetSymbolAddress((void**)&xh,  g_xh);
        cudaGetSymbolAddress((void**)&xl,  g_xl);
        cudaGetSymbolAddress((void**)&ch,  g_ch);
        cudaGetSymbolAddress((void**)&cl,  g_cl);
        cudaGetSymbolAddress((void**)&fh,  g_fh);
        cudaGetSymbolAddress((void**)&fl,  g_fl);
        cudaGetSymbolAddress((void**)&ah,  g_ah);
        cudaGetSymbolAddress((void**)&al,  g_al);
        cudaGetSymbolAddress((void**)&wh,  g_wh);
        cudaGetSymbolAddress((void**)&wl,  g_wl);
        cudaGetSymbolAddress((void**)&bbf,  g_bbf);
        cudaGetSymbolAddress((void**)&xaf,  g_xaf);
        cudaFuncSetAttribute(attn_mma,
                             cudaFuncAttributeMaxDynamicSharedMemorySize, ASMEM);
        cudaFuncSetAttribute(gemm_f16,
                             cudaFuncAttributeMaxDynamicSharedMemorySize, GSMEM);
    }
    float* out = (float*)d_out;
    const long S512 = 512 * NPIX, S256 = 256 * NPIX;

    const int W_CV1 = 0, W_QKV = 262144, W_PROJ = 393216,
              W_FFN1 = 458752, W_FFN2 = 589824, W_CV2 = 720896;

    // #0: split x
    {
        int n4 = BSZ * 512 * NPIX / 4;
        split_k<<<(n4 + 255) / 256, 256>>>((const float4*)x, (uint2*)xh, (uint2*)xl, n4);
    }
    // #1: split all weights
    wsplit_all<<<960, 256>>>(W_cv1, W_qkv, W_proj, W_ffn1, W_ffn2, W_cv2, wh, wl);
    // #2: cv1 gemm (SiLU) -> cat hi/lo + bbf fp32 for ch>=256
    gemm_f16<<<dim3(8, 4, BSZ), 256, GSMEM>>>(
        xh, xl, S512, 512, wh + W_CV1, wl + W_CV1, s_cv1, b_cv1,
        nullptr, 0, bbf, S256, 256, ch, cl, S512, 1);
    // #3: qkv gemm -> fp16 hi/lo
    gemm_f16<<<dim3(8, 4, BSZ), 256, GSMEM>>>(
        ch + S256, cl + S256, S512, 256, wh + W_QKV, wl + W_QKV, s_qkv, b_qkv,
        nullptr, 0, nullptr, 0, 1 << 30, fh, fl, S512, 0);
    // #4: tensor-core flash attention -> xaf (cm)
    attn_mma<<<dim3(8, 64), 256, ASMEM>>>(fh, fl, xaf);
    // #5: PE dwconv (v from fp16 hi/lo): xaf + conv(v) -> xa fp16 hi/lo
    dwconv_pe<<<dim3(256, BSZ), 256>>>(fh, fl, W_pe, s_pe, b_pe, xaf, ah, al);
    // #6: proj gemm (+bb residual, in-place bbf, re-split into cat ch256+)
    gemm_f16<<<dim3(8, 2, BSZ), 256, GSMEM>>>(
        ah, al, S256, 256, wh + W_PROJ, wl + W_PROJ, s_proj, b_proj,
        bbf, S256, bbf, S256, 0, ch + S256, cl + S256, S512, 0);
    // #7: ffn1 gemm (SiLU)
    gemm_f16<<<dim3(8, 4, BSZ), 256, GSMEM>>>(
        ch + S256, cl + S256, S512, 256, wh + W_FFN1, wl + W_FFN1, s_ffn1, b_ffn1,
        nullptr, 0, nullptr, 0, 1 << 30, fh, fl, S512, 1);
    // #8: ffn2 gemm (+bb2 residual -> cat ch256+)
    gemm_f16<<<dim3(8, 2, BSZ), 256, GSMEM>>>(
        fh, fl, S512, 512, wh + W_FFN2, wl + W_FFN2, s_ffn2, b_ffn2,
        bbf, S256, nullptr, 0, 1 << 30, ch + S256, cl + S256, S512, 0);
    // #9: cv2 gemm -> out (SiLU)
    gemm_f16<<<dim3(8, 4, BSZ), 256, GSMEM>>>(
        ch, cl, S512, 512, wh + W_CV2, wl + W_CV2, s_cv2, b_cv2,
        nullptr, 0, out, S512, 0, nullptr, nullptr, 0, 1);
}

// round 11
// speedup vs baseline: 6.5328x; 1.2724x over previous
#include <cuda_runtime.h>
#include <cuda_fp16.h>
#include <cstdint>

#define BSZ 16
#define NPIX 1024
#define SCALE_ATT 0.17677669529663687f

// ---------------- static scratch ----------------
__device__ __align__(16) __half g_x16[BSZ * 512 * NPIX];   // input x fp16
__device__ __align__(16) __half g_c16[BSZ * 512 * NPIX];   // cat [a|bb] fp16
__device__ __align__(16) __half g_t16[BSZ * 512 * NPIX];   // qkv / ffn1 fp16
__device__ __align__(16) __half g_a16[BSZ * 256 * NPIX];   // xa fp16
__device__ __align__(16) float g_bbf [BSZ * 256 * NPIX];   // bb chain f32 (cm)
__device__ __align__(16) float g_xaf [BSZ * 256 * NPIX];   // attn out f32 (cm)
__device__ __align__(16) __half g_wh[983040], g_wl[983040];

__device__ __forceinline__ float silu_f(float v) {
    return v / (1.0f + __expf(-v));
}

__device__ __forceinline__ void hsplit(float v, __half& h, __half& l) {
    h = __float2half_rn(v);
    l = __float2half_rn(v - __half2float(h));
}

__device__ __forceinline__ uint32_t s2u(const void* p) {
    uint32_t a;
    asm("{ .reg .u64 t; cvta.to.shared.u64 t, %1; cvt.u32.u64 %0, t; }" : "=r"(a) : "l"(p));
    return a;
}

__device__ __forceinline__ void cpa(uint32_t saddr, const void* g) {
    asm volatile("cp.async.cg.shared.global [%0], [%1], 16;" :: "r"(saddr), "l"(g));
}

__device__ __forceinline__ void ldsm_x4(uint32_t* r, uint32_t addr) {
    asm volatile("ldmatrix.sync.aligned.m8n8.x4.shared.b16 {%0,%1,%2,%3}, [%4];"
                 : "=r"(r[0]), "=r"(r[1]), "=r"(r[2]), "=r"(r[3]) : "r"(addr));
}

__device__ __forceinline__ void ldsm_x4t(uint32_t* r, uint32_t addr) {
    asm volatile("ldmatrix.sync.aligned.m8n8.x4.trans.shared.b16 {%0,%1,%2,%3}, [%4];"
                 : "=r"(r[0]), "=r"(r[1]), "=r"(r[2]), "=r"(r[3]) : "r"(addr));
}

__device__ __forceinline__ void mma_f16(float* c, const uint32_t* a, const uint32_t* b) {
    asm volatile(
        "mma.sync.aligned.m16n8k16.row.col.f32.f16.f16.f32 "
        "{%0,%1,%2,%3}, {%4,%5,%6,%7}, {%8,%9}, {%0,%1,%2,%3};\n"
        : "+f"(c[0]), "+f"(c[1]), "+f"(c[2]), "+f"(c[3])
        : "r"(a[0]), "r"(a[1]), "r"(a[2]), "r"(a[3]), "r"(b[0]), "r"(b[1]));
}

// ---------------- fp16 tensor-core GEMM (W hi/lo 2-term, X plain, BK=32) ----------------
#define A_BYTES (128 * 80)                   // per W half
#define AB2     (2 * A_BYTES)                // 20480
#define B_BYTES (32 * 256)                   // 8192 (single)
#define STAGE_B (AB2 + B_BYTES)              // 28672
#define GSMEM   (3 * STAGE_B)                // 86016

__global__ __launch_bounds__(256, 2) void gemm_f16(
    const __half* __restrict__ X, long xbs, int K,
    const __half* __restrict__ Wh, const __half* __restrict__ Wl,
    const float* __restrict__ sc, const float* __restrict__ bi,
    const float* __restrict__ res, long rbs,
    float* __restrict__ outf, long ofbs, int ofoff,
    __half* __restrict__ oh, long ohbs,
    int act)
{
    extern __shared__ __align__(16) char smem[];
    const uint32_t sb = s2u(smem);
    const int tid  = threadIdx.x;
    const int warp = tid >> 5;
    const int lane = tid & 31;
    const int g    = lane >> 2;
    const int tig  = lane & 3;
    const int wm   = warp >> 2;
    const int wn   = warp & 3;
    const int b  = blockIdx.z;
    const int n0 = blockIdx.x * 128;
    const int m0 = blockIdx.y * 128;

    const __half* Xb = X + (size_t)b * xbs;

    float acc[4][4][4];
#pragma unroll
    for (int f = 0; f < 4; f++)
#pragma unroll
        for (int fn = 0; fn < 4; fn++)
#pragma unroll
            for (int q = 0; q < 4; q++) acc[f][fn][q] = 0.0f;

    auto issue = [&](int c, int buf) {
        const uint32_t st = sb + buf * STAGE_B;
        const int k0 = c * 32;
#pragma unroll
        for (int r = 0; r < 2; r++) {
            const int ca  = tid + 256 * r;
            const int row = ca >> 2, kc16 = ca & 3;              // A: 128 rows x 4 chunks
            const uint32_t ad = st + row * 80 + kc16 * 16;
            cpa(ad,           Wh + (size_t)(m0 + row) * K + k0 + kc16 * 8);
            cpa(ad + A_BYTES, Wl + (size_t)(m0 + row) * K + k0 + kc16 * 8);
        }
        // B: 32 rows x 16 chunks = 512 chunks, 2 per thread
#pragma unroll
        for (int r = 0; r < 2; r++) {
            const int ca = tid + 256 * r;
            const int kr = ca >> 4, nc2 = ca & 15;
            const uint32_t bd = st + AB2 + kr * 256 + (((uint32_t)(nc2 ^ (kr & 7))) << 4);
            cpa(bd, Xb + (size_t)(k0 + kr) * NPIX + n0 + nc2 * 8);
        }
        asm volatile("cp.async.commit_group;");
    };

    const int nc = K >> 5;
    issue(0, 0);
    if (nc > 1) issue(1, 1);

    const int arow  = wm * 64 + (lane & 15);
    const int akoff = (lane >> 4) * 16;
    const int blk16 = lane & 15;
    const int ncsel = lane >> 4;   // lanes 16-31 take the odd n-chunk

    int buf = 0;
    for (int c = 0; c < nc; c++) {
        if (c + 1 < nc) asm volatile("cp.async.wait_group 1;");
        else            asm volatile("cp.async.wait_group 0;");
        __syncthreads();

        const uint32_t st = sb + buf * STAGE_B;

#pragma unroll
        for (int kc = 0; kc < 2; kc++) {
            uint32_t a_h[4][4], a_l[4][4];
#pragma unroll
            for (int f = 0; f < 4; f++) {
                const uint32_t off = st + (uint32_t)(arow + f * 16) * 80 + kc * 32 + akoff;
                ldsm_x4(a_h[f], off);
                ldsm_x4(a_l[f], off + A_BYTES);
            }
#pragma unroll
            for (int fnp = 0; fnp < 2; fnp++) {
                const int ncb = wn * 4 + fnp * 2 + ncsel;
                const uint32_t bd = st + AB2 + (uint32_t)(kc * 16 + blk16) * 256 +
                                    (((uint32_t)(ncb ^ (blk16 & 7))) << 4);
                uint32_t b4[4];
                ldsm_x4t(b4, bd);   // b4[0..1]: chunk fnp*2, b4[2..3]: chunk fnp*2+1
#pragma unroll
                for (int f = 0; f < 4; f++) {
                    mma_f16(acc[f][2 * fnp],     a_h[f], b4);
                    mma_f16(acc[f][2 * fnp],     a_l[f], b4);
                    mma_f16(acc[f][2 * fnp + 1], a_h[f], b4 + 2);
                    mma_f16(acc[f][2 * fnp + 1], a_l[f], b4 + 2);
                }
            }
            if (kc == 0 && c + 2 < nc) {
                int nb = buf + 2; if (nb >= 3) nb -= 3;
                issue(c + 2, nb);
            }
        }
        if (++buf == 3) buf = 0;
    }

    // ---------------- epilogue (channel-major) ----------------
    const bool do_f = (outf != nullptr) && (m0 >= ofoff);
#pragma unroll
    for (int f = 0; f < 4; f++) {
        const int m = m0 + wm * 64 + f * 16 + g;
        const float s0 = sc[m],     b0 = bi[m];
        const float s1 = sc[m + 8], b1 = bi[m + 8];
#pragma unroll
        for (int fn = 0; fn < 4; fn++) {
            const int n = n0 + wn * 32 + fn * 8 + 2 * tig;
            float v00 = acc[f][fn][0] * s0 + b0;
            float v01 = acc[f][fn][1] * s0 + b0;
            float v10 = acc[f][fn][2] * s1 + b1;
            float v11 = acc[f][fn][3] * s1 + b1;
            if (res) {
                float2 ra = *(const float2*)(res + (size_t)b * rbs + (size_t)m * NPIX + n);
                float2 rb = *(const float2*)(res + (size_t)b * rbs + (size_t)(m + 8) * NPIX + n);
                v00 += ra.x; v01 += ra.y; v10 += rb.x; v11 += rb.y;
            }
            if (act) {
                v00 = silu_f(v00); v01 = silu_f(v01);
                v10 = silu_f(v10); v11 = silu_f(v11);
            }
            if (do_f) {
                const int mo = m - ofoff;
                *(float2*)(outf + (size_t)b * ofbs + (size_t)mo * NPIX + n) = make_float2(v00, v01);
                *(float2*)(outf + (size_t)b * ofbs + (size_t)(mo + 8) * NPIX + n) = make_float2(v10, v11);
            }
            if (oh) {
                *(__half2*)(oh + (size_t)b * ohbs + (size_t)m * NPIX + n) =
                    __halves2half2(__float2half_rn(v00), __float2half_rn(v01));
                *(__half2*)(oh + (size_t)b * ohbs + (size_t)(m + 8) * NPIX + n) =
                    __halves2half2(__float2half_rn(v10), __float2half_rn(v11));
            }
        }
    }
}

// ---------------- converts / splits ----------------
__global__ void cvt16(const float4* __restrict__ src, uint2* __restrict__ dst, int n4)
{
    int i = blockIdx.x * 256 + threadIdx.x;
    if (i < n4) {
        float4 v = src[i];
        __half h[4];
        h[0] = __float2half_rn(v.x); h[1] = __float2half_rn(v.y);
        h[2] = __float2half_rn(v.z); h[3] = __float2half_rn(v.w);
        dst[i] = *(uint2*)h;
    }
}

__global__ void wsplit_all(
    const float* __restrict__ W0, const float* __restrict__ W1,
    const float* __restrict__ W2, const float* __restrict__ W3,
    const float* __restrict__ W4, const float* __restrict__ W5,
    __half* __restrict__ wh, __half* __restrict__ wl)
{
    int blk = blockIdx.x;
    const float* src; int off;
    if      (blk < 256) { src = W0; off = 0;      }
    else if (blk < 384) { src = W1; off = 262144; blk -= 256; }
    else if (blk < 448) { src = W2; off = 393216; blk -= 384; }
    else if (blk < 576) { src = W3; off = 458752; blk -= 448; }
    else if (blk < 704) { src = W4; off = 589824; blk -= 576; }
    else                { src = W5; off = 720896; blk -= 704; }
    int i = blk * 256 + threadIdx.x;
    float4 v = ((const float4*)src)[i];
    __half h[4], l[4];
    hsplit(v.x, h[0], l[0]); hsplit(v.y, h[1], l[1]);
    hsplit(v.z, h[2], l[2]); hsplit(v.w, h[3], l[3]);
    ((uint2*)(wh + off))[i] = *(uint2*)h;
    ((uint2*)(wl + off))[i] = *(uint2*)l;
}

// ---------------- tensor-core flash attention (all plain fp16 operands) ----------------
#define RS 272
#define OFF_Q 0                     // 32 x 272 = 8704
#define OFF_RM 8704                 // 2048
#define OFF_RSUM 10752              // 2048
#define OFF_K 12800                 // 2 buf x 32 x 272 = 17408
#define KBUF 8704
#define OFF_V 30208                 // 2 buf x 64 x 272 = 34816
#define VBUF 17408
#define OFF_P 65024                 // 128 x 272 = 34816
#define ASMEM 99840

__global__ __launch_bounds__(256, 2) void attn_mma(
    const __half* __restrict__ qv, float* __restrict__ xa)
{
    extern __shared__ __align__(16) char smn[];
    const uint32_t sb = s2u(smn);
    float* redmax = (float*)(smn + OFF_RM);
    float* redsum = (float*)(smn + OFF_RSUM);

    const int tid = threadIdx.x;
    const int warp = tid >> 5, lane = tid & 31;
    const int g = lane >> 2, tig = lane & 3;
    const int wm = warp >> 2, wn = warp & 3;
    const int bh = blockIdx.y;
    const int r0 = blockIdx.x * 128;
    const size_t cb = (size_t)bh * 128 * NPIX;

    // Q: 32 rows x 16 chunks
#pragma unroll
    for (int i = 0; i < 2; i++) {
        int idx = i * 256 + tid;
        int row = idx >> 4, ch = idx & 15;
        cpa(sb + OFF_Q + row * RS + ch * 16, qv + cb + (size_t)row * NPIX + r0 + ch * 8);
    }
    auto loadK = [&](int mt, int kb) {
#pragma unroll
        for (int i = 0; i < 2; i++) {
            int idx = i * 256 + tid;
            int row = idx >> 4, ch = idx & 15;
            cpa(sb + OFF_K + kb * KBUF + row * RS + ch * 16,
                qv + cb + (size_t)(32 + row) * NPIX + mt * 128 + ch * 8);
        }
    };
    auto loadV = [&](int mt, int vb) {
#pragma unroll
        for (int i = 0; i < 4; i++) {
            int idx = i * 256 + tid;
            int row = (idx >> 4) & 63, ch = idx & 15;
            cpa(sb + OFF_V + vb * VBUF + row * RS + ch * 16,
                qv + cb + (size_t)(64 + row) * NPIX + mt * 128 + ch * 8);
        }
    };
    loadK(0, 0); loadV(0, 0);
    asm volatile("cp.async.commit_group;");

    float m_s[8], l_s[8];
#pragma unroll
    for (int i = 0; i < 8; i++) { m_s[i] = -1e30f; l_s[i] = 0.f; }
    float accO[4][2][4];
#pragma unroll
    for (int f = 0; f < 4; f++)
#pragma unroll
        for (int n2 = 0; n2 < 2; n2++)
#pragma unroll
            for (int q = 0; q < 4; q++) accO[f][n2][q] = 0.f;

    const int krow = (lane & 7) + ((lane >> 4) << 3);
    const int mcol = ((lane >> 3) & 1) * 8;
    const int ncsel = lane >> 4;
    const int vrow = ((lane >> 4) << 3) + (lane & 7);
    const int vch  = ((lane >> 3) & 1) * 8;

    for (int mt = 0; mt < 8; mt++) {
        asm volatile("cp.async.wait_group 0;");
        __syncthreads();
        const int kb = mt & 1, vb = mt & 1;

        // ---- S = Q K^T (1-term; one x4t K load feeds two fn chunks) ----
        float accS[4][4][4];
#pragma unroll
        for (int f = 0; f < 4; f++)
#pragma unroll
            for (int fn = 0; fn < 4; fn++)
#pragma unroll
                for (int q = 0; q < 4; q++) accS[f][fn][q] = 0.f;

#pragma unroll
        for (int kc = 0; kc < 2; kc++) {
            uint32_t qf[4][4];
#pragma unroll
            for (int f = 0; f < 4; f++) {
                uint32_t ad = sb + OFF_Q + (kc * 16 + krow) * RS +
                              (wm * 64 + f * 16 + mcol) * 2;
                ldsm_x4t(qf[f], ad);
            }
#pragma unroll
            for (int fnp = 0; fnp < 2; fnp++) {
                const int ncb = wn * 4 + fnp * 2 + ncsel;
                uint32_t bd = sb + OFF_K + kb * KBUF +
                              (uint32_t)(kc * 16 + (lane & 15)) * RS + ncb * 16;
                uint32_t k4[4];
                ldsm_x4t(k4, bd);
#pragma unroll
                for (int f = 0; f < 4; f++) {
                    mma_f16(accS[f][2 * fnp],     qf[f], k4);
                    mma_f16(accS[f][2 * fnp + 1], qf[f], k4 + 2);
                }
            }
        }

        if (mt + 1 < 8) {
            loadK(mt + 1, kb ^ 1);
            loadV(mt + 1, vb ^ 1);
        }
        asm volatile("cp.async.commit_group;");

        // ---- online softmax ----
#pragma unroll
        for (int f = 0; f < 4; f++)
#pragma unroll
            for (int h = 0; h < 2; h++) {
                float pm = -1e30f;
#pragma unroll
                for (int fn = 0; fn < 4; fn++) {
                    float x0 = accS[f][fn][2 * h]     * SCALE_ATT;
                    float x1 = accS[f][fn][2 * h + 1] * SCALE_ATT;
                    pm = fmaxf(pm, fmaxf(x0, x1));
                }
                pm = fmaxf(pm, __shfl_xor_sync(0xffffffffu, pm, 1));
                pm = fmaxf(pm, __shfl_xor_sync(0xffffffffu, pm, 2));
                if (tig == 0) redmax[(wm * 64 + f * 16 + g + 8 * h) * 4 + wn] = pm;
            }
        __syncthreads();

        float sf_[8];
#pragma unroll
        for (int f = 0; f < 4; f++)
#pragma unroll
            for (int h = 0; h < 2; h++) {
                const int r = wm * 64 + f * 16 + g + 8 * h;
                float mn = fmaxf(fmaxf(redmax[r * 4 + 0], redmax[r * 4 + 1]),
                                 fmaxf(redmax[r * 4 + 2], redmax[r * 4 + 3]));
                const int s = f * 2 + h;
                mn = fmaxf(mn, m_s[s]);
                float sf = __expf(m_s[s] - mn);
                m_s[s] = mn; l_s[s] *= sf; sf_[s] = sf;
            }
#pragma unroll
        for (int f = 0; f < 4; f++)
#pragma unroll
            for (int n2 = 0; n2 < 2; n2++) {
                accO[f][n2][0] *= sf_[f * 2];     accO[f][n2][1] *= sf_[f * 2];
                accO[f][n2][2] *= sf_[f * 2 + 1]; accO[f][n2][3] *= sf_[f * 2 + 1];
            }

        // ---- P = exp(S - m) -> fp16, row sums ----
#pragma unroll
        for (int f = 0; f < 4; f++) {
            float ps0 = 0.f, ps1 = 0.f;
            const uint32_t prow0 = (uint32_t)(wm * 64 + f * 16 + g) * RS;
#pragma unroll
            for (int fn = 0; fn < 4; fn++) {
                float p00 = __expf(accS[f][fn][0] * SCALE_ATT - m_s[f * 2]);
                float p01 = __expf(accS[f][fn][1] * SCALE_ATT - m_s[f * 2]);
                float p10 = __expf(accS[f][fn][2] * SCALE_ATT - m_s[f * 2 + 1]);
                float p11 = __expf(accS[f][fn][3] * SCALE_ATT - m_s[f * 2 + 1]);
                ps0 += p00 + p01; ps1 += p10 + p11;
                const uint32_t colb = (uint32_t)(wn * 32 + fn * 8 + 2 * tig) * 2;
                char* ph = smn + OFF_P;
                *(__half2*)(ph + prow0 + colb) =
                    __halves2half2(__float2half_rn(p00), __float2half_rn(p01));
                *(__half2*)(ph + prow0 + 8 * RS + colb) =
                    __halves2half2(__float2half_rn(p10), __float2half_rn(p11));
            }
            ps0 += __shfl_xor_sync(0xffffffffu, ps0, 1);
            ps0 += __shfl_xor_sync(0xffffffffu, ps0, 2);
            ps1 += __shfl_xor_sync(0xffffffffu, ps1, 1);
            ps1 += __shfl_xor_sync(0xffffffffu, ps1, 2);
            if (tig == 0) {
                redsum[(wm * 64 + f * 16 + g) * 4 + wn]     = ps0;
                redsum[(wm * 64 + f * 16 + g + 8) * 4 + wn] = ps1;
            }
        }
        __syncthreads();

#pragma unroll
        for (int f = 0; f < 4; f++)
#pragma unroll
            for (int h = 0; h < 2; h++) {
                const int r = wm * 64 + f * 16 + g + 8 * h;
                l_s[f * 2 + h] += redsum[r * 4 + 0] + redsum[r * 4 + 1] +
                                  redsum[r * 4 + 2] + redsum[r * 4 + 3];
            }

        // ---- O += P V (1-term; one x4 V load feeds both n2 tiles) ----
        const int pmr  = (lane & 7) + ((lane >> 3) & 1) * 8;
        const int pkc8 = (lane >> 4) * 8;
#pragma unroll
        for (int kc = 0; kc < 8; kc++) {
            uint32_t pa[4][4];
#pragma unroll
            for (int f = 0; f < 4; f++) {
                uint32_t ad = sb + OFF_P + (uint32_t)(wm * 64 + f * 16 + pmr) * RS +
                              (kc * 16 + pkc8) * 2;
                ldsm_x4(pa[f], ad);
            }
            uint32_t v4[4];
            {
                uint32_t bd = sb + OFF_V + vb * VBUF +
                              (uint32_t)(wn * 16 + vrow) * RS + (kc * 16 + vch) * 2;
                ldsm_x4(v4, bd);
            }
#pragma unroll
            for (int n2 = 0; n2 < 2; n2++)
#pragma unroll
                for (int f = 0; f < 4; f++)
                    mma_f16(accO[f][n2], pa[f], v4 + 2 * n2);
        }
    }

    float il[8];
#pragma unroll
    for (int s = 0; s < 8; s++) il[s] = 1.0f / l_s[s];
#pragma unroll
    for (int f = 0; f < 4; f++)
#pragma unroll
        for (int n2 = 0; n2 < 2; n2++) {
            const int d = wn * 16 + n2 * 8 + 2 * tig;
            const int r = r0 + wm * 64 + f * 16 + g;
            xa[(size_t)(bh * 64 + d) * NPIX + r]         = accO[f][n2][0] * il[f * 2];
            xa[(size_t)(bh * 64 + d + 1) * NPIX + r]     = accO[f][n2][1] * il[f * 2];
            xa[(size_t)(bh * 64 + d) * NPIX + r + 8]     = accO[f][n2][2] * il[f * 2 + 1];
            xa[(size_t)(bh * 64 + d + 1) * NPIX + r + 8] = accO[f][n2][3] * il[f * 2 + 1];
        }
}

// ---------------- depthwise 3x3 PE (v plain fp16) -> xa fp16 ----------------
__global__ __launch_bounds__(256) void dwconv_pe(
    const __half* __restrict__ qv, const float* __restrict__ Wpe,
    const float* __restrict__ s, const float* __restrict__ bi,
    const float* __restrict__ xaf, __half* __restrict__ xah)
{
    __shared__ float t[34 * 34];
    const int c = blockIdx.x;
    const int b = blockIdx.y;
    const int qc = ((c >> 6) * 128) + 64 + (c & 63);
    const size_t srcoff = ((size_t)b * 512 + qc) * NPIX;
    const int tid = threadIdx.x;

    for (int i = tid; i < 34 * 34; i += 256) t[i] = 0.0f;
    __syncthreads();
    for (int i = tid; i < NPIX; i += 256) {
        int y = i >> 5, x = i & 31;
        t[(y + 1) * 34 + (x + 1)] = __half2float(qv[srcoff + i]);
    }
    __syncthreads();

    float w[9];
#pragma unroll
    for (int i = 0; i < 9; i++) w[i] = Wpe[c * 9 + i];
    const float scv = s[c], bv = bi[c];
    const size_t off = ((size_t)b * 256 + c) * NPIX;

    for (int i = tid; i < NPIX; i += 256) {
        int y = i >> 5, x = i & 31;
        float acc = 0.0f;
#pragma unroll
        for (int ky = 0; ky < 3; ky++)
#pragma unroll
            for (int kx = 0; kx < 3; kx++)
                acc += w[ky * 3 + kx] * t[(y + ky) * 34 + (x + kx)];
        float v = xaf[off + i] + acc * scv + bv;
        xah[off + i] = __float2half_rn(v);
    }
}

// ---------------- launcher ----------------
extern "C" void kernel_launch(void* const* d_in, const int* in_sizes, int n_in,
                              void* d_out, int out_size)
{
    (void)in_sizes; (void)n_in; (void)out_size;
    const float* x      = (const float*)d_in[0];
    const float* W_cv1  = (const float*)d_in[1];
    const float* s_cv1  = (const float*)d_in[2];
    const float* b_cv1  = (const float*)d_in[3];
    const float* W_qkv  = (const float*)d_in[4];
    const float* s_qkv  = (const float*)d_in[5];
    const float* b_qkv  = (const float*)d_in[6];
    const float* W_proj = (const float*)d_in[7];
    const float* s_proj = (const float*)d_in[8];
    const float* b_proj = (const float*)d_in[9];
    const float* W_pe   = (const float*)d_in[10];
    const float* s_pe   = (const float*)d_in[11];
    const float* b_pe   = (const float*)d_in[12];
    const float* W_ffn1 = (const float*)d_in[13];
    const float* s_ffn1 = (const float*)d_in[14];
    const float* b_ffn1 = (const float*)d_in[15];
    const float* W_ffn2 = (const float*)d_in[16];
    const float* s_ffn2 = (const float*)d_in[17];
    const float* b_ffn2 = (const float*)d_in[18];
    const float* W_cv2  = (const float*)d_in[19];
    const float* s_cv2  = (const float*)d_in[20];
    const float* b_cv2  = (const float*)d_in[21];

    static __half *x16 = nullptr, *c16, *t16, *a16, *wh, *wl;
    static float *bbf, *xaf;
    if (!x16) {
        cudaGetSymbolAddress((void**)&x16, g_x16);
        cudaGetSymbolAddress((void**)&c16, g_c16);
        cudaGetSymbolAddress((void**)&t16, g_t16);
        cudaGetSymbolAddress((void**)&a16, g_a16);
        cudaGetSymbolAddress((void**)&wh,  g_wh);
        cudaGetSymbolAddress((void**)&wl,  g_wl);
        cudaGetSymbolAddress((void**)&bbf, g_bbf);
        cudaGetSymbolAddress((void**)&xaf, g_xaf);
        cudaFuncSetAttribute(attn_mma,
                             cudaFuncAttributeMaxDynamicSharedMemorySize, ASMEM);
        cudaFuncSetAttribute(gemm_f16,
                             cudaFuncAttributeMaxDynamicSharedMemorySize, GSMEM);
    }
    float* out = (float*)d_out;
    const long S512 = 512 * NPIX, S256 = 256 * NPIX;

    const int W_CV1 = 0, W_QKV = 262144, W_PROJ = 393216,
              W_FFN1 = 458752, W_FFN2 = 589824, W_CV2 = 720896;

    // #0: convert x -> fp16
    {
        int n4 = BSZ * 512 * NPIX / 4;
        cvt16<<<(n4 + 255) / 256, 256>>>((const float4*)x, (uint2*)x16, n4);
    }
    // #1: split all weights (hi/lo)
    wsplit_all<<<960, 256>>>(W_cv1, W_qkv, W_proj, W_ffn1, W_ffn2, W_cv2, wh, wl);
    // #2: cv1 (SiLU) -> c16 fp16 + bbf f32 for ch>=256
    gemm_f16<<<dim3(8, 4, BSZ), 256, GSMEM>>>(
        x16, S512, 512, wh + W_CV1, wl + W_CV1, s_cv1, b_cv1,
        nullptr, 0, bbf, S256, 256, c16, S512, 1);
    // #3: qkv -> t16 fp16
    gemm_f16<<<dim3(8, 4, BSZ), 256, GSMEM>>>(
        c16 + S256, S512, 256, wh + W_QKV, wl + W_QKV, s_qkv, b_qkv,
        nullptr, 0, nullptr, 0, 1 << 30, t16, S512, 0);
    // #4: flash attention -> xaf
    attn_mma<<<dim3(8, 64), 256, ASMEM>>>(t16, xaf);
    // #5: PE dwconv -> a16
    dwconv_pe<<<dim3(256, BSZ), 256>>>(t16, W_pe, s_pe, b_pe, xaf, a16);
    // #6: proj (+bb residual) -> bbf (in place) + c16 ch256+
    gemm_f16<<<dim3(8, 2, BSZ), 256, GSMEM>>>(
        a16, S256, 256, wh + W_PROJ, wl + W_PROJ, s_proj, b_proj,
        bbf, S256, bbf, S256, 0, c16 + S256, S512, 0);
    // #7: ffn1 (SiLU) -> t16
    gemm_f16<<<dim3(8, 4, BSZ), 256, GSMEM>>>(
        c16 + S256, S512, 256, wh + W_FFN1, wl + W_FFN1, s_ffn1, b_ffn1,
        nullptr, 0, nullptr, 0, 1 << 30, t16, S512, 1);
    // #8: ffn2 (+bb2 residual) -> c16 ch256+
    gemm_f16<<<dim3(8, 2, BSZ), 256, GSMEM>>>(
        t16, S512, 512, wh + W_FFN2, wl + W_FFN2, s_ffn2, b_ffn2,
        bbf, S256, nullptr, 0, 1 << 30, c16 + S256, S512, 0);
    // #9: cv2 (SiLU) -> out
    gemm_f16<<<dim3(8, 4, BSZ), 256, GSMEM>>>(
        c16, S512, 512, wh + W_CV2, wl + W_CV2, s_cv2, b_cv2,
        nullptr, 0, out, S512, 0, nullptr, 0, 1);
}

// round 12
// speedup vs baseline: 7.2770x; 1.1139x over previous
#include <cuda_runtime.h>
#include <cuda_fp16.h>
#include <cstdint>

#define BSZ 16
#define NPIX 1024
#define SCALE_ATT 0.17677669529663687f

// ---------------- static scratch ----------------
__device__ __align__(16) __half g_x16[BSZ * 512 * NPIX];   // input x fp16
__device__ __align__(16) __half g_c16[BSZ * 512 * NPIX];   // cat [a|bb] fp16
__device__ __align__(16) __half g_t16[BSZ * 512 * NPIX];   // qkv / ffn1 fp16
__device__ __align__(16) __half g_a16[BSZ * 256 * NPIX];   // xa fp16
__device__ __align__(16) float g_bbf [BSZ * 256 * NPIX];   // bb chain f32 (cm)
__device__ __align__(16) float g_xaf [BSZ * 256 * NPIX];   // attn out f32 (cm)
__device__ __align__(16) __half g_wh[983040], g_wl[983040];

__device__ __forceinline__ float silu_f(float v) {
    return v / (1.0f + __expf(-v));
}

__device__ __forceinline__ void hsplit(float v, __half& h, __half& l) {
    h = __float2half_rn(v);
    l = __float2half_rn(v - __half2float(h));
}

__device__ __forceinline__ uint32_t s2u(const void* p) {
    uint32_t a;
    asm("{ .reg .u64 t; cvta.to.shared.u64 t, %1; cvt.u32.u64 %0, t; }" : "=r"(a) : "l"(p));
    return a;
}

__device__ __forceinline__ void cpa(uint32_t saddr, const void* g) {
    asm volatile("cp.async.cg.shared.global [%0], [%1], 16;" :: "r"(saddr), "l"(g));
}

__device__ __forceinline__ void ldsm_x4(uint32_t* r, uint32_t addr) {
    asm volatile("ldmatrix.sync.aligned.m8n8.x4.shared.b16 {%0,%1,%2,%3}, [%4];"
                 : "=r"(r[0]), "=r"(r[1]), "=r"(r[2]), "=r"(r[3]) : "r"(addr));
}

__device__ __forceinline__ void ldsm_x4t(uint32_t* r, uint32_t addr) {
    asm volatile("ldmatrix.sync.aligned.m8n8.x4.trans.shared.b16 {%0,%1,%2,%3}, [%4];"
                 : "=r"(r[0]), "=r"(r[1]), "=r"(r[2]), "=r"(r[3]) : "r"(addr));
}

__device__ __forceinline__ void mma_f16(float* c, const uint32_t* a, const uint32_t* b) {
    asm volatile(
        "mma.sync.aligned.m16n8k16.row.col.f32.f16.f16.f32 "
        "{%0,%1,%2,%3}, {%4,%5,%6,%7}, {%8,%9}, {%0,%1,%2,%3};\n"
        : "+f"(c[0]), "+f"(c[1]), "+f"(c[2]), "+f"(c[3])
        : "r"(a[0]), "r"(a[1]), "r"(a[2]), "r"(a[3]), "r"(b[0]), "r"(b[1]));
}

// ---------------- fp16 tensor-core GEMM (W hi/lo 2-term, X plain, BK=32) ----------------
#define A_BYTES (128 * 80)
#define AB2     (2 * A_BYTES)
#define B_BYTES (32 * 256)
#define STAGE_B (AB2 + B_BYTES)              // 28672
#define GSMEM   (3 * STAGE_B)                // 86016

__global__ __launch_bounds__(256, 2) void gemm_f16(
    const __half* __restrict__ X, long xbs, int K,
    const __half* __restrict__ Wh, const __half* __restrict__ Wl,
    const float* __restrict__ sc, const float* __restrict__ bi,
    const float* __restrict__ res, long rbs,
    float* __restrict__ outf, long ofbs, int ofoff,
    __half* __restrict__ oh, long ohbs,
    int act)
{
    extern __shared__ __align__(16) char smem[];
    const uint32_t sb = s2u(smem);
    const int tid  = threadIdx.x;
    const int warp = tid >> 5;
    const int lane = tid & 31;
    const int g    = lane >> 2;
    const int tig  = lane & 3;
    const int wm   = warp >> 2;
    const int wn   = warp & 3;
    const int b  = blockIdx.z;
    const int n0 = blockIdx.x * 128;
    const int m0 = blockIdx.y * 128;

    const __half* Xb = X + (size_t)b * xbs;

    float acc[4][4][4];
#pragma unroll
    for (int f = 0; f < 4; f++)
#pragma unroll
        for (int fn = 0; fn < 4; fn++)
#pragma unroll
            for (int q = 0; q < 4; q++) acc[f][fn][q] = 0.0f;

    auto issue = [&](int c, int buf) {
        const uint32_t st = sb + buf * STAGE_B;
        const int k0 = c * 32;
#pragma unroll
        for (int r = 0; r < 2; r++) {
            const int ca  = tid + 256 * r;
            const int row = ca >> 2, kc16 = ca & 3;
            const uint32_t ad = st + row * 80 + kc16 * 16;
            cpa(ad,           Wh + (size_t)(m0 + row) * K + k0 + kc16 * 8);
            cpa(ad + A_BYTES, Wl + (size_t)(m0 + row) * K + k0 + kc16 * 8);
        }
#pragma unroll
        for (int r = 0; r < 2; r++) {
            const int ca = tid + 256 * r;
            const int kr = ca >> 4, nc2 = ca & 15;
            const uint32_t bd = st + AB2 + kr * 256 + (((uint32_t)(nc2 ^ (kr & 7))) << 4);
            cpa(bd, Xb + (size_t)(k0 + kr) * NPIX + n0 + nc2 * 8);
        }
        asm volatile("cp.async.commit_group;");
    };

    const int nc = K >> 5;
    issue(0, 0);
    if (nc > 1) issue(1, 1);

    const int arow  = wm * 64 + (lane & 15);
    const int akoff = (lane >> 4) * 16;
    const int blk16 = lane & 15;
    const int ncsel = lane >> 4;

    int buf = 0;
    for (int c = 0; c < nc; c++) {
        if (c + 1 < nc) asm volatile("cp.async.wait_group 1;");
        else            asm volatile("cp.async.wait_group 0;");
        __syncthreads();

        const uint32_t st = sb + buf * STAGE_B;

#pragma unroll
        for (int kc = 0; kc < 2; kc++) {
            uint32_t a_h[4][4], a_l[4][4];
#pragma unroll
            for (int f = 0; f < 4; f++) {
                const uint32_t off = st + (uint32_t)(arow + f * 16) * 80 + kc * 32 + akoff;
                ldsm_x4(a_h[f], off);
                ldsm_x4(a_l[f], off + A_BYTES);
            }
#pragma unroll
            for (int fnp = 0; fnp < 2; fnp++) {
                const int ncb = wn * 4 + fnp * 2 + ncsel;
                const uint32_t bd = st + AB2 + (uint32_t)(kc * 16 + blk16) * 256 +
                                    (((uint32_t)(ncb ^ (blk16 & 7))) << 4);
                uint32_t b4[4];
                ldsm_x4t(b4, bd);
#pragma unroll
                for (int f = 0; f < 4; f++) {
                    mma_f16(acc[f][2 * fnp],     a_h[f], b4);
                    mma_f16(acc[f][2 * fnp],     a_l[f], b4);
                    mma_f16(acc[f][2 * fnp + 1], a_h[f], b4 + 2);
                    mma_f16(acc[f][2 * fnp + 1], a_l[f], b4 + 2);
                }
            }
            if (kc == 0 && c + 2 < nc) {
                int nb = buf + 2; if (nb >= 3) nb -= 3;
                issue(c + 2, nb);
            }
        }
        if (++buf == 3) buf = 0;
    }

    const bool do_f = (outf != nullptr) && (m0 >= ofoff);
#pragma unroll
    for (int f = 0; f < 4; f++) {
        const int m = m0 + wm * 64 + f * 16 + g;
        const float s0 = sc[m],     b0 = bi[m];
        const float s1 = sc[m + 8], b1 = bi[m + 8];
#pragma unroll
        for (int fn = 0; fn < 4; fn++) {
            const int n = n0 + wn * 32 + fn * 8 + 2 * tig;
            float v00 = acc[f][fn][0] * s0 + b0;
            float v01 = acc[f][fn][1] * s0 + b0;
            float v10 = acc[f][fn][2] * s1 + b1;
            float v11 = acc[f][fn][3] * s1 + b1;
            if (res) {
                float2 ra = *(const float2*)(res + (size_t)b * rbs + (size_t)m * NPIX + n);
                float2 rb = *(const float2*)(res + (size_t)b * rbs + (size_t)(m + 8) * NPIX + n);
                v00 += ra.x; v01 += ra.y; v10 += rb.x; v11 += rb.y;
            }
            if (act) {
                v00 = silu_f(v00); v01 = silu_f(v01);
                v10 = silu_f(v10); v11 = silu_f(v11);
            }
            if (do_f) {
                const int mo = m - ofoff;
                *(float2*)(outf + (size_t)b * ofbs + (size_t)mo * NPIX + n) = make_float2(v00, v01);
                *(float2*)(outf + (size_t)b * ofbs + (size_t)(mo + 8) * NPIX + n) = make_float2(v10, v11);
            }
            if (oh) {
                *(__half2*)(oh + (size_t)b * ohbs + (size_t)m * NPIX + n) =
                    __halves2half2(__float2half_rn(v00), __float2half_rn(v01));
                *(__half2*)(oh + (size_t)b * ohbs + (size_t)(m + 8) * NPIX + n) =
                    __halves2half2(__float2half_rn(v10), __float2half_rn(v11));
            }
        }
    }
}

// ---------------- converts / splits ----------------
__global__ void cvt16(const float4* __restrict__ src, uint2* __restrict__ dst, int n4)
{
    int i = blockIdx.x * 256 + threadIdx.x;
    if (i < n4) {
        float4 v = src[i];
        __half h[4];
        h[0] = __float2half_rn(v.x); h[1] = __float2half_rn(v.y);
        h[2] = __float2half_rn(v.z); h[3] = __float2half_rn(v.w);
        dst[i] = *(uint2*)h;
    }
}

__global__ void wsplit_all(
    const float* __restrict__ W0, const float* __restrict__ W1,
    const float* __restrict__ W2, const float* __restrict__ W3,
    const float* __restrict__ W4, const float* __restrict__ W5,
    __half* __restrict__ wh, __half* __restrict__ wl)
{
    int blk = blockIdx.x;
    const float* src; int off;
    if      (blk < 256) { src = W0; off = 0;      }
    else if (blk < 384) { src = W1; off = 262144; blk -= 256; }
    else if (blk < 448) { src = W2; off = 393216; blk -= 384; }
    else if (blk < 576) { src = W3; off = 458752; blk -= 448; }
    else if (blk < 704) { src = W4; off = 589824; blk -= 576; }
    else                { src = W5; off = 720896; blk -= 704; }
    int i = blk * 256 + threadIdx.x;
    float4 v = ((const float4*)src)[i];
    __half h[4], l[4];
    hsplit(v.x, h[0], l[0]); hsplit(v.y, h[1], l[1]);
    hsplit(v.z, h[2], l[2]); hsplit(v.w, h[3], l[3]);
    ((uint2*)(wh + off))[i] = *(uint2*)h;
    ((uint2*)(wl + off))[i] = *(uint2*)l;
}

// ---------------- tensor-core flash attention (FA2: 16 rows/warp, P in regs) ----------------
#define RS 272
#define OFF_Q 0                     // 32 x 272 = 8704
#define OFF_K 8704                  // 2 buf x 32 x 272 = 17408
#define KBUF 8704
#define OFF_V 26112                 // 2 buf x 64 x 272 = 34816
#define VBUF 17408
#define ASMEM 60928

__global__ __launch_bounds__(256, 2) void attn_mma(
    const __half* __restrict__ qv, float* __restrict__ xa)
{
    extern __shared__ __align__(16) char smn[];
    const uint32_t sb = s2u(smn);

    const int tid = threadIdx.x;
    const int warp = tid >> 5, lane = tid & 31;
    const int g = lane >> 2, tig = lane & 3;
    const int bh = blockIdx.y;
    const int r0 = blockIdx.x * 128;
    const size_t cb = (size_t)bh * 128 * NPIX;

    // Q: 32 k-rows x 128 pixels
#pragma unroll
    for (int i = 0; i < 2; i++) {
        int idx = i * 256 + tid;
        int row = idx >> 4, ch = idx & 15;
        cpa(sb + OFF_Q + row * RS + ch * 16, qv + cb + (size_t)row * NPIX + r0 + ch * 8);
    }
    auto loadK = [&](int mt, int kb) {
#pragma unroll
        for (int i = 0; i < 2; i++) {
            int idx = i * 256 + tid;
            int row = idx >> 4, ch = idx & 15;
            cpa(sb + OFF_K + kb * KBUF + row * RS + ch * 16,
                qv + cb + (size_t)(32 + row) * NPIX + mt * 128 + ch * 8);
        }
    };
    auto loadV = [&](int mt, int vb) {
#pragma unroll
        for (int i = 0; i < 4; i++) {
            int idx = i * 256 + tid;
            int row = (idx >> 4) & 63, ch = idx & 15;
            cpa(sb + OFF_V + vb * VBUF + row * RS + ch * 16,
                qv + cb + (size_t)(64 + row) * NPIX + mt * 128 + ch * 8);
        }
    };
    loadK(0, 0); loadV(0, 0);
    asm volatile("cp.async.commit_group;");

    float m_s[2] = {-1e30f, -1e30f}, l_s[2] = {0.f, 0.f};
    float accO[8][4];
#pragma unroll
    for (int nt = 0; nt < 8; nt++)
#pragma unroll
        for (int q = 0; q < 4; q++) accO[nt][q] = 0.f;

    const int krow = (lane & 7) + ((lane >> 4) << 3);
    const int mcol = ((lane >> 3) & 1) * 8;
    const int ncsel = lane >> 4;
    const int vrow = ((lane >> 4) << 3) + (lane & 7);
    const int vch  = ((lane >> 3) & 1) * 8;

    uint32_t qf[2][4];

    for (int mt = 0; mt < 8; mt++) {
        asm volatile("cp.async.wait_group 0;");
        __syncthreads();
        const int kb = mt & 1, vb = mt & 1;

        // prefetch next tile into the now-free other buffers (overlaps whole body)
        if (mt + 1 < 8) {
            loadK(mt + 1, kb ^ 1);
            loadV(mt + 1, vb ^ 1);
        }
        asm volatile("cp.async.commit_group;");

        if (mt == 0) {
#pragma unroll
            for (int kc = 0; kc < 2; kc++)
                ldsm_x4t(qf[kc], sb + OFF_Q + (kc * 16 + krow) * RS +
                                 (warp * 16 + mcol) * 2);
        }

        // ---- S = Q K^T : warp computes 16 rows x 128 cols ----
        float accS[16][4];
#pragma unroll
        for (int fn = 0; fn < 16; fn++)
#pragma unroll
            for (int q = 0; q < 4; q++) accS[fn][q] = 0.f;

#pragma unroll
        for (int kc = 0; kc < 2; kc++) {
#pragma unroll
            for (int fnp = 0; fnp < 8; fnp++) {
                const int ncb = fnp * 2 + ncsel;
                uint32_t bd = sb + OFF_K + kb * KBUF +
                              (uint32_t)(kc * 16 + (lane & 15)) * RS + ncb * 16;
                uint32_t k4[4];
                ldsm_x4t(k4, bd);
                mma_f16(accS[2 * fnp],     qf[kc], k4);
                mma_f16(accS[2 * fnp + 1], qf[kc], k4 + 2);
            }
        }

        // ---- warp-local online softmax (rows g, g+8) ----
        float mx0 = -1e30f, mx1 = -1e30f;
#pragma unroll
        for (int fn = 0; fn < 16; fn++) {
            mx0 = fmaxf(mx0, fmaxf(accS[fn][0], accS[fn][1]));
            mx1 = fmaxf(mx1, fmaxf(accS[fn][2], accS[fn][3]));
        }
        mx0 = fmaxf(mx0, __shfl_xor_sync(0xffffffffu, mx0, 1));
        mx0 = fmaxf(mx0, __shfl_xor_sync(0xffffffffu, mx0, 2));
        mx1 = fmaxf(mx1, __shfl_xor_sync(0xffffffffu, mx1, 1));
        mx1 = fmaxf(mx1, __shfl_xor_sync(0xffffffffu, mx1, 2));
        mx0 *= SCALE_ATT; mx1 *= SCALE_ATT;
        mx0 = fmaxf(mx0, m_s[0]);
        mx1 = fmaxf(mx1, m_s[1]);
        const float sf0 = __expf(m_s[0] - mx0);
        const float sf1 = __expf(m_s[1] - mx1);
        m_s[0] = mx0; m_s[1] = mx1;
        l_s[0] *= sf0; l_s[1] *= sf1;
#pragma unroll
        for (int nt = 0; nt < 8; nt++) {
            accO[nt][0] *= sf0; accO[nt][1] *= sf0;
            accO[nt][2] *= sf1; accO[nt][3] *= sf1;
        }

        // ---- P = exp(S*sc - m) packed fp16 in place; row sums ----
        float ps0 = 0.f, ps1 = 0.f;
#pragma unroll
        for (int fn = 0; fn < 16; fn++) {
            float p0 = __expf(accS[fn][0] * SCALE_ATT - mx0);
            float p1 = __expf(accS[fn][1] * SCALE_ATT - mx0);
            float p2 = __expf(accS[fn][2] * SCALE_ATT - mx1);
            float p3 = __expf(accS[fn][3] * SCALE_ATT - mx1);
            ps0 += p0 + p1; ps1 += p2 + p3;
            __half2 h01 = __halves2half2(__float2half_rn(p0), __float2half_rn(p1));
            __half2 h23 = __halves2half2(__float2half_rn(p2), __float2half_rn(p3));
            accS[fn][0] = __uint_as_float(*(uint32_t*)&h01);
            accS[fn][2] = __uint_as_float(*(uint32_t*)&h23);
        }
        ps0 += __shfl_xor_sync(0xffffffffu, ps0, 1);
        ps0 += __shfl_xor_sync(0xffffffffu, ps0, 2);
        ps1 += __shfl_xor_sync(0xffffffffu, ps1, 1);
        ps1 += __shfl_xor_sync(0xffffffffu, ps1, 2);
        l_s[0] += ps0; l_s[1] += ps1;

        // ---- O += P V (P from registers; one x4 V load per 2 n-tiles) ----
#pragma unroll
        for (int kc = 0; kc < 8; kc++) {
            uint32_t pa[4];
            pa[0] = __float_as_uint(accS[2 * kc][0]);
            pa[1] = __float_as_uint(accS[2 * kc][2]);
            pa[2] = __float_as_uint(accS[2 * kc + 1][0]);
            pa[3] = __float_as_uint(accS[2 * kc + 1][2]);
#pragma unroll
            for (int ntp = 0; ntp < 4; ntp++) {
                uint32_t bd = sb + OFF_V + vb * VBUF +
                              (uint32_t)(ntp * 16 + vrow) * RS + (kc * 16 + vch) * 2;
                uint32_t v4[4];
                ldsm_x4(v4, bd);
                mma_f16(accO[2 * ntp],     pa, v4);
                mma_f16(accO[2 * ntp + 1], pa, v4 + 2);
            }
        }
    }

    const float il0 = 1.0f / l_s[0], il1 = 1.0f / l_s[1];
    const int r = r0 + warp * 16 + g;
#pragma unroll
    for (int nt = 0; nt < 8; nt++) {
        const int d = nt * 8 + 2 * tig;
        xa[(size_t)(bh * 64 + d) * NPIX + r]         = accO[nt][0] * il0;
        xa[(size_t)(bh * 64 + d + 1) * NPIX + r]     = accO[nt][1] * il0;
        xa[(size_t)(bh * 64 + d) * NPIX + r + 8]     = accO[nt][2] * il1;
        xa[(size_t)(bh * 64 + d + 1) * NPIX + r + 8] = accO[nt][3] * il1;
    }
}

// ---------------- depthwise 3x3 PE (v plain fp16) -> xa fp16 ----------------
__global__ __launch_bounds__(256) void dwconv_pe(
    const __half* __restrict__ qv, const float* __restrict__ Wpe,
    const float* __restrict__ s, const float* __restrict__ bi,
    const float* __restrict__ xaf, __half* __restrict__ xah)
{
    __shared__ float t[34 * 34];
    const int c = blockIdx.x;
    const int b = blockIdx.y;
    const int qc = ((c >> 6) * 128) + 64 + (c & 63);
    const size_t srcoff = ((size_t)b * 512 + qc) * NPIX;
    const int tid = threadIdx.x;

    for (int i = tid; i < 34 * 34; i += 256) t[i] = 0.0f;
    __syncthreads();
    for (int i = tid; i < NPIX; i += 256) {
        int y = i >> 5, x = i & 31;
        t[(y + 1) * 34 + (x + 1)] = __half2float(qv[srcoff + i]);
    }
    __syncthreads();

    float w[9];
#pragma unroll
    for (int i = 0; i < 9; i++) w[i] = Wpe[c * 9 + i];
    const float scv = s[c], bv = bi[c];
    const size_t off = ((size_t)b * 256 + c) * NPIX;

    for (int i = tid; i < NPIX; i += 256) {
        int y = i >> 5, x = i & 31;
        float acc = 0.0f;
#pragma unroll
        for (int ky = 0; ky < 3; ky++)
#pragma unroll
            for (int kx = 0; kx < 3; kx++)
                acc += w[ky * 3 + kx] * t[(y + ky) * 34 + (x + kx)];
        float v = xaf[off + i] + acc * scv + bv;
        xah[off + i] = __float2half_rn(v);
    }
}

// ---------------- launcher ----------------
extern "C" void kernel_launch(void* const* d_in, const int* in_sizes, int n_in,
                              void* d_out, int out_size)
{
    (void)in_sizes; (void)n_in; (void)out_size;
    const float* x      = (const float*)d_in[0];
    const float* W_cv1  = (const float*)d_in[1];
    const float* s_cv1  = (const float*)d_in[2];
    const float* b_cv1  = (const float*)d_in[3];
    const float* W_qkv  = (const float*)d_in[4];
    const float* s_qkv  = (const float*)d_in[5];
    const float* b_qkv  = (const float*)d_in[6];
    const float* W_proj = (const float*)d_in[7];
    const float* s_proj = (const float*)d_in[8];
    const float* b_proj = (const float*)d_in[9];
    const float* W_pe   = (const float*)d_in[10];
    const float* s_pe   = (const float*)d_in[11];
    const float* b_pe   = (const float*)d_in[12];
    const float* W_ffn1 = (const float*)d_in[13];
    const float* s_ffn1 = (const float*)d_in[14];
    const float* b_ffn1 = (const float*)d_in[15];
    const float* W_ffn2 = (const float*)d_in[16];
    const float* s_ffn2 = (const float*)d_in[17];
    const float* b_ffn2 = (const float*)d_in[18];
    const float* W_cv2  = (const float*)d_in[19];
    const float* s_cv2  = (const float*)d_in[20];
    const float* b_cv2  = (const float*)d_in[21];

    static __half *x16 = nullptr, *c16, *t16, *a16, *wh, *wl;
    static float *bbf, *xaf;
    if (!x16) {
        cudaGetSymbolAddress((void**)&x16, g_x16);
        cudaGetSymbolAddress((void**)&c16, g_c16);
        cudaGetSymbolAddress((void**)&t16, g_t16);
        cudaGetSymbolAddress((void**)&a16, g_a16);
        cudaGetSymbolAddress((void**)&wh,  g_wh);
        cudaGetSymbolAddress((void**)&wl,  g_wl);
        cudaGetSymbolAddress((void**)&bbf, g_bbf);
        cudaGetSymbolAddress((void**)&xaf, g_xaf);
        cudaFuncSetAttribute(attn_mma,
                             cudaFuncAttributeMaxDynamicSharedMemorySize, ASMEM);
        cudaFuncSetAttribute(gemm_f16,
                             cudaFuncAttributeMaxDynamicSharedMemorySize, GSMEM);
    }
    float* out = (float*)d_out;
    const long S512 = 512 * NPIX, S256 = 256 * NPIX;

    const int W_CV1 = 0, W_QKV = 262144, W_PROJ = 393216,
              W_FFN1 = 458752, W_FFN2 = 589824, W_CV2 = 720896;

    // #0: convert x -> fp16
    {
        int n4 = BSZ * 512 * NPIX / 4;
        cvt16<<<(n4 + 255) / 256, 256>>>((const float4*)x, (uint2*)x16, n4);
    }
    // #1: split all weights (hi/lo)
    wsplit_all<<<960, 256>>>(W_cv1, W_qkv, W_proj, W_ffn1, W_ffn2, W_cv2, wh, wl);
    // #2: cv1 (SiLU) -> c16 fp16 + bbf f32 for ch>=256
    gemm_f16<<<dim3(8, 4, BSZ), 256, GSMEM>>>(
        x16, S512, 512, wh + W_CV1, wl + W_CV1, s_cv1, b_cv1,
        nullptr, 0, bbf, S256, 256, c16, S512, 1);
    // #3: qkv -> t16 fp16
    gemm_f16<<<dim3(8, 4, BSZ), 256, GSMEM>>>(
        c16 + S256, S512, 256, wh + W_QKV, wl + W_QKV, s_qkv, b_qkv,
        nullptr, 0, nullptr, 0, 1 << 30, t16, S512, 0);
    // #4: flash attention -> xaf
    attn_mma<<<dim3(8, 64), 256, ASMEM>>>(t16, xaf);
    // #5: PE dwconv -> a16
    dwconv_pe<<<dim3(256, BSZ), 256>>>(t16, W_pe, s_pe, b_pe, xaf, a16);
    // #6: proj (+bb residual) -> bbf (in place) + c16 ch256+
    gemm_f16<<<dim3(8, 2, BSZ), 256, GSMEM>>>(
        a16, S256, 256, wh + W_PROJ, wl + W_PROJ, s_proj, b_proj,
        bbf, S256, bbf, S256, 0, c16 + S256, S512, 0);
    // #7: ffn1 (SiLU) -> t16
    gemm_f16<<<dim3(8, 4, BSZ), 256, GSMEM>>>(
        c16 + S256, S512, 256, wh + W_FFN1, wl + W_FFN1, s_ffn1, b_ffn1,
        nullptr, 0, nullptr, 0, 1 << 30, t16, S512, 1);
    // #8: ffn2 (+bb2 residual) -> c16 ch256+
    gemm_f16<<<dim3(8, 2, BSZ), 256, GSMEM>>>(
        t16, S512, 512, wh + W_FFN2, wl + W_FFN2, s_ffn2, b_ffn2,
        bbf, S256, nullptr, 0, 1 << 30, c16 + S256, S512, 0);
    // #9: cv2 (SiLU) -> out
    gemm_f16<<<dim3(8, 4, BSZ), 256, GSMEM>>>(
        c16, S512, 512, wh + W_CV2, wl + W_CV2, s_cv2, b_cv2,
        nullptr, 0, out, S512, 0, nullptr, 0, 1);
}

// round 13
// speedup vs baseline: 9.3029x; 1.2784x over previous
#include <cuda_runtime.h>
#include <cuda_fp16.h>
#include <cstdint>

#define BSZ 16
#define NPIX 1024
#define SCALE_ATT 0.17677669529663687f

// ---------------- static scratch ----------------
__device__ __align__(16) __half g_x16[BSZ * 512 * NPIX];   // input x fp16
__device__ __align__(16) __half g_c16[BSZ * 512 * NPIX];   // cat [a|bb] fp16
__device__ __align__(16) __half g_t16[BSZ * 512 * NPIX];   // qkv / ffn1 fp16
__device__ __align__(16) __half g_a16[BSZ * 256 * NPIX];   // xa fp16 (attn out, then +pe)
__device__ __align__(16) float g_bbf [BSZ * 256 * NPIX];   // bb chain f32 (cm)
__device__ __align__(16) __half g_wh[983040];

__device__ __forceinline__ float silu_f(float v) {
    return v / (1.0f + __expf(-v));
}

__device__ __forceinline__ uint32_t s2u(const void* p) {
    uint32_t a;
    asm("{ .reg .u64 t; cvta.to.shared.u64 t, %1; cvt.u32.u64 %0, t; }" : "=r"(a) : "l"(p));
    return a;
}

__device__ __forceinline__ void cpa(uint32_t saddr, const void* g) {
    asm volatile("cp.async.cg.shared.global [%0], [%1], 16;" :: "r"(saddr), "l"(g));
}

__device__ __forceinline__ void ldsm_x4(uint32_t* r, uint32_t addr) {
    asm volatile("ldmatrix.sync.aligned.m8n8.x4.shared.b16 {%0,%1,%2,%3}, [%4];"
                 : "=r"(r[0]), "=r"(r[1]), "=r"(r[2]), "=r"(r[3]) : "r"(addr));
}

__device__ __forceinline__ void ldsm_x4t(uint32_t* r, uint32_t addr) {
    asm volatile("ldmatrix.sync.aligned.m8n8.x4.trans.shared.b16 {%0,%1,%2,%3}, [%4];"
                 : "=r"(r[0]), "=r"(r[1]), "=r"(r[2]), "=r"(r[3]) : "r"(addr));
}

__device__ __forceinline__ void mma_f16(float* c, const uint32_t* a, const uint32_t* b) {
    asm volatile(
        "mma.sync.aligned.m16n8k16.row.col.f32.f16.f16.f32 "
        "{%0,%1,%2,%3}, {%4,%5,%6,%7}, {%8,%9}, {%0,%1,%2,%3};\n"
        : "+f"(c[0]), "+f"(c[1]), "+f"(c[2]), "+f"(c[3])
        : "r"(a[0]), "r"(a[1]), "r"(a[2]), "r"(a[3]), "r"(b[0]), "r"(b[1]));
}

// ---------------- fp16 tensor-core GEMM (W plain, X plain, BK=32, 3-stage) ----------------
#define A_BYTES (128 * 80)                   // 10240
#define B_BYTES (32 * 256)                   // 8192
#define STAGE_B (A_BYTES + B_BYTES)          // 18432
#define GSMEM   (3 * STAGE_B)                // 55296

__global__ __launch_bounds__(256, 2) void gemm_f16(
    const __half* __restrict__ X, long xbs, int K,
    const __half* __restrict__ W,
    const float* __restrict__ sc, const float* __restrict__ bi,
    const float* __restrict__ res, long rbs,
    float* __restrict__ outf, long ofbs, int ofoff,
    __half* __restrict__ oh, long ohbs,
    int act)
{
    extern __shared__ __align__(16) char smem[];
    const uint32_t sb = s2u(smem);
    const int tid  = threadIdx.x;
    const int warp = tid >> 5;
    const int lane = tid & 31;
    const int g    = lane >> 2;
    const int tig  = lane & 3;
    const int wm   = warp >> 2;
    const int wn   = warp & 3;
    const int b  = blockIdx.z;
    const int n0 = blockIdx.x * 128;
    const int m0 = blockIdx.y * 128;

    const __half* Xb = X + (size_t)b * xbs;

    float acc[4][4][4];
#pragma unroll
    for (int f = 0; f < 4; f++)
#pragma unroll
        for (int fn = 0; fn < 4; fn++)
#pragma unroll
            for (int q = 0; q < 4; q++) acc[f][fn][q] = 0.0f;

    auto issue = [&](int c, int buf) {
        const uint32_t st = sb + buf * STAGE_B;
        const int k0 = c * 32;
#pragma unroll
        for (int r = 0; r < 2; r++) {
            const int ca  = tid + 256 * r;
            const int row = ca >> 2, kc16 = ca & 3;
            cpa(st + row * 80 + kc16 * 16, W + (size_t)(m0 + row) * K + k0 + kc16 * 8);
        }
#pragma unroll
        for (int r = 0; r < 2; r++) {
            const int ca = tid + 256 * r;
            const int kr = ca >> 4, nc2 = ca & 15;
            cpa(st + A_BYTES + kr * 256 + (((uint32_t)(nc2 ^ (kr & 7))) << 4),
                Xb + (size_t)(k0 + kr) * NPIX + n0 + nc2 * 8);
        }
        asm volatile("cp.async.commit_group;");
    };

    const int nc = K >> 5;
    issue(0, 0);
    if (nc > 1) issue(1, 1);

    const int arow  = wm * 64 + (lane & 15);
    const int akoff = (lane >> 4) * 16;
    const int blk16 = lane & 15;
    const int ncsel = lane >> 4;

    int buf = 0;
    for (int c = 0; c < nc; c++) {
        if (c + 1 < nc) asm volatile("cp.async.wait_group 1;");
        else            asm volatile("cp.async.wait_group 0;");
        __syncthreads();

        const uint32_t st = sb + buf * STAGE_B;

#pragma unroll
        for (int kc = 0; kc < 2; kc++) {
            uint32_t a_h[4][4];
#pragma unroll
            for (int f = 0; f < 4; f++)
                ldsm_x4(a_h[f], st + (uint32_t)(arow + f * 16) * 80 + kc * 32 + akoff);
#pragma unroll
            for (int fnp = 0; fnp < 2; fnp++) {
                const int ncb = wn * 4 + fnp * 2 + ncsel;
                const uint32_t bd = st + A_BYTES + (uint32_t)(kc * 16 + blk16) * 256 +
                                    (((uint32_t)(ncb ^ (blk16 & 7))) << 4);
                uint32_t b4[4];
                ldsm_x4t(b4, bd);
#pragma unroll
                for (int f = 0; f < 4; f++) {
                    mma_f16(acc[f][2 * fnp],     a_h[f], b4);
                    mma_f16(acc[f][2 * fnp + 1], a_h[f], b4 + 2);
                }
            }
            if (kc == 0 && c + 2 < nc) {
                int nb = buf + 2; if (nb >= 3) nb -= 3;
                issue(c + 2, nb);
            }
        }
        if (++buf == 3) buf = 0;
    }

    const bool do_f = (outf != nullptr) && (m0 >= ofoff);
#pragma unroll
    for (int f = 0; f < 4; f++) {
        const int m = m0 + wm * 64 + f * 16 + g;
        const float s0 = sc[m],     b0 = bi[m];
        const float s1 = sc[m + 8], b1 = bi[m + 8];
#pragma unroll
        for (int fn = 0; fn < 4; fn++) {
            const int n = n0 + wn * 32 + fn * 8 + 2 * tig;
            float v00 = acc[f][fn][0] * s0 + b0;
            float v01 = acc[f][fn][1] * s0 + b0;
            float v10 = acc[f][fn][2] * s1 + b1;
            float v11 = acc[f][fn][3] * s1 + b1;
            if (res) {
                float2 ra = *(const float2*)(res + (size_t)b * rbs + (size_t)m * NPIX + n);
                float2 rb = *(const float2*)(res + (size_t)b * rbs + (size_t)(m + 8) * NPIX + n);
                v00 += ra.x; v01 += ra.y; v10 += rb.x; v11 += rb.y;
            }
            if (act) {
                v00 = silu_f(v00); v01 = silu_f(v01);
                v10 = silu_f(v10); v11 = silu_f(v11);
            }
            if (do_f) {
                const int mo = m - ofoff;
                *(float2*)(outf + (size_t)b * ofbs + (size_t)mo * NPIX + n) = make_float2(v00, v01);
                *(float2*)(outf + (size_t)b * ofbs + (size_t)(mo + 8) * NPIX + n) = make_float2(v10, v11);
            }
            if (oh) {
                *(__half2*)(oh + (size_t)b * ohbs + (size_t)m * NPIX + n) =
                    __halves2half2(__float2half_rn(v00), __float2half_rn(v01));
                *(__half2*)(oh + (size_t)b * ohbs + (size_t)(m + 8) * NPIX + n) =
                    __halves2half2(__float2half_rn(v10), __float2half_rn(v11));
            }
        }
    }
}

// ---------------- converts ----------------
__global__ void cvt16(const float4* __restrict__ src, uint2* __restrict__ dst, int n4)
{
    int i = blockIdx.x * 256 + threadIdx.x;
    if (i < n4) {
        float4 v = src[i];
        __half h[4];
        h[0] = __float2half_rn(v.x); h[1] = __float2half_rn(v.y);
        h[2] = __float2half_rn(v.z); h[3] = __float2half_rn(v.w);
        dst[i] = *(uint2*)h;
    }
}

__global__ void wcvt_all(
    const float* __restrict__ W0, const float* __restrict__ W1,
    const float* __restrict__ W2, const float* __restrict__ W3,
    const float* __restrict__ W4, const float* __restrict__ W5,
    __half* __restrict__ wh)
{
    int blk = blockIdx.x;
    const float* src; int off;
    if      (blk < 256) { src = W0; off = 0;      }
    else if (blk < 384) { src = W1; off = 262144; blk -= 256; }
    else if (blk < 448) { src = W2; off = 393216; blk -= 384; }
    else if (blk < 576) { src = W3; off = 458752; blk -= 448; }
    else if (blk < 704) { src = W4; off = 589824; blk -= 576; }
    else                { src = W5; off = 720896; blk -= 704; }
    int i = blk * 256 + threadIdx.x;
    float4 v = ((const float4*)src)[i];
    __half h[4];
    h[0] = __float2half_rn(v.x); h[1] = __float2half_rn(v.y);
    h[2] = __float2half_rn(v.z); h[3] = __float2half_rn(v.w);
    ((uint2*)(wh + off))[i] = *(uint2*)h;
}

// ---------------- tensor-core flash attention (FA2, h2exp, fp16 out) ----------------
#define RS 272
#define OFF_Q 0
#define OFF_K 8704
#define KBUF 8704
#define OFF_V 26112
#define VBUF 17408
#define ASMEM 60928

__global__ __launch_bounds__(256, 2) void attn_mma(
    const __half* __restrict__ qv, __half* __restrict__ xa)
{
    extern __shared__ __align__(16) char smn[];
    const uint32_t sb = s2u(smn);

    const int tid = threadIdx.x;
    const int warp = tid >> 5, lane = tid & 31;
    const int g = lane >> 2, tig = lane & 3;
    const int bh = blockIdx.y;
    const int r0 = blockIdx.x * 128;
    const size_t cb = (size_t)bh * 128 * NPIX;

#pragma unroll
    for (int i = 0; i < 2; i++) {
        int idx = i * 256 + tid;
        int row = idx >> 4, ch = idx & 15;
        cpa(sb + OFF_Q + row * RS + ch * 16, qv + cb + (size_t)row * NPIX + r0 + ch * 8);
    }
    auto loadK = [&](int mt, int kb) {
#pragma unroll
        for (int i = 0; i < 2; i++) {
            int idx = i * 256 + tid;
            int row = idx >> 4, ch = idx & 15;
            cpa(sb + OFF_K + kb * KBUF + row * RS + ch * 16,
                qv + cb + (size_t)(32 + row) * NPIX + mt * 128 + ch * 8);
        }
    };
    auto loadV = [&](int mt, int vb) {
#pragma unroll
        for (int i = 0; i < 4; i++) {
            int idx = i * 256 + tid;
            int row = (idx >> 4) & 63, ch = idx & 15;
            cpa(sb + OFF_V + vb * VBUF + row * RS + ch * 16,
                qv + cb + (size_t)(64 + row) * NPIX + mt * 128 + ch * 8);
        }
    };
    loadK(0, 0); loadV(0, 0);
    asm volatile("cp.async.commit_group;");

    float m_s[2] = {-1e30f, -1e30f}, l_s[2] = {0.f, 0.f};
    float accO[8][4];
#pragma unroll
    for (int nt = 0; nt < 8; nt++)
#pragma unroll
        for (int q = 0; q < 4; q++) accO[nt][q] = 0.f;

    const int krow = (lane & 7) + ((lane >> 4) << 3);
    const int mcol = ((lane >> 3) & 1) * 8;
    const int ncsel = lane >> 4;
    const int vrow = ((lane >> 4) << 3) + (lane & 7);
    const int vch  = ((lane >> 3) & 1) * 8;

    uint32_t qf[2][4];

    for (int mt = 0; mt < 8; mt++) {
        asm volatile("cp.async.wait_group 0;");
        __syncthreads();
        const int kb = mt & 1, vb = mt & 1;

        if (mt + 1 < 8) {
            loadK(mt + 1, kb ^ 1);
            loadV(mt + 1, vb ^ 1);
        }
        asm volatile("cp.async.commit_group;");

        if (mt == 0) {
#pragma unroll
            for (int kc = 0; kc < 2; kc++)
                ldsm_x4t(qf[kc], sb + OFF_Q + (kc * 16 + krow) * RS +
                                 (warp * 16 + mcol) * 2);
        }

        float accS[16][4];
#pragma unroll
        for (int fn = 0; fn < 16; fn++)
#pragma unroll
            for (int q = 0; q < 4; q++) accS[fn][q] = 0.f;

#pragma unroll
        for (int kc = 0; kc < 2; kc++) {
#pragma unroll
            for (int fnp = 0; fnp < 8; fnp++) {
                const int ncb = fnp * 2 + ncsel;
                uint32_t bd = sb + OFF_K + kb * KBUF +
                              (uint32_t)(kc * 16 + (lane & 15)) * RS + ncb * 16;
                uint32_t k4[4];
                ldsm_x4t(k4, bd);
                mma_f16(accS[2 * fnp],     qf[kc], k4);
                mma_f16(accS[2 * fnp + 1], qf[kc], k4 + 2);
            }
        }

        // ---- warp-local online softmax ----
        float mx0 = -1e30f, mx1 = -1e30f;
#pragma unroll
        for (int fn = 0; fn < 16; fn++) {
            mx0 = fmaxf(mx0, fmaxf(accS[fn][0], accS[fn][1]));
            mx1 = fmaxf(mx1, fmaxf(accS[fn][2], accS[fn][3]));
        }
        mx0 = fmaxf(mx0, __shfl_xor_sync(0xffffffffu, mx0, 1));
        mx0 = fmaxf(mx0, __shfl_xor_sync(0xffffffffu, mx0, 2));
        mx1 = fmaxf(mx1, __shfl_xor_sync(0xffffffffu, mx1, 1));
        mx1 = fmaxf(mx1, __shfl_xor_sync(0xffffffffu, mx1, 2));
        mx0 *= SCALE_ATT; mx1 *= SCALE_ATT;
        mx0 = fmaxf(mx0, m_s[0]);
        mx1 = fmaxf(mx1, m_s[1]);
        const float sf0 = __expf(m_s[0] - mx0);
        const float sf1 = __expf(m_s[1] - mx1);
        m_s[0] = mx0; m_s[1] = mx1;
        l_s[0] *= sf0; l_s[1] *= sf1;
#pragma unroll
        for (int nt = 0; nt < 8; nt++) {
            accO[nt][0] *= sf0; accO[nt][1] *= sf0;
            accO[nt][2] *= sf1; accO[nt][3] *= sf1;
        }

        // ---- P = exp(S*sc - m) via h2exp (2 elems per MUFU), fp32 row sums ----
        float ps0 = 0.f, ps1 = 0.f;
#pragma unroll
        for (int fn = 0; fn < 16; fn++) {
            float t0 = fmaf(accS[fn][0], SCALE_ATT, -mx0);
            float t1 = fmaf(accS[fn][1], SCALE_ATT, -mx0);
            float t2 = fmaf(accS[fn][2], SCALE_ATT, -mx1);
            float t3 = fmaf(accS[fn][3], SCALE_ATT, -mx1);
            __half2 ha = h2exp(__floats2half2_rn(t0, t1));
            __half2 hb = h2exp(__floats2half2_rn(t2, t3));
            float2 fa = __half22float2(ha);
            float2 fb = __half22float2(hb);
            ps0 += fa.x + fa.y; ps1 += fb.x + fb.y;
            accS[fn][0] = __uint_as_float(*(uint32_t*)&ha);
            accS[fn][2] = __uint_as_float(*(uint32_t*)&hb);
        }
        ps0 += __shfl_xor_sync(0xffffffffu, ps0, 1);
        ps0 += __shfl_xor_sync(0xffffffffu, ps0, 2);
        ps1 += __shfl_xor_sync(0xffffffffu, ps1, 1);
        ps1 += __shfl_xor_sync(0xffffffffu, ps1, 2);
        l_s[0] += ps0; l_s[1] += ps1;

        // ---- O += P V (P from registers) ----
#pragma unroll
        for (int kc = 0; kc < 8; kc++) {
            uint32_t pa[4];
            pa[0] = __float_as_uint(accS[2 * kc][0]);
            pa[1] = __float_as_uint(accS[2 * kc][2]);
            pa[2] = __float_as_uint(accS[2 * kc + 1][0]);
            pa[3] = __float_as_uint(accS[2 * kc + 1][2]);
#pragma unroll
            for (int ntp = 0; ntp < 4; ntp++) {
                uint32_t bd = sb + OFF_V + vb * VBUF +
                              (uint32_t)(ntp * 16 + vrow) * RS + (kc * 16 + vch) * 2;
                uint32_t v4[4];
                ldsm_x4(v4, bd);
                mma_f16(accO[2 * ntp],     pa, v4);
                mma_f16(accO[2 * ntp + 1], pa, v4 + 2);
            }
        }
    }

    const float il0 = 1.0f / l_s[0], il1 = 1.0f / l_s[1];
    const int r = r0 + warp * 16 + g;
#pragma unroll
    for (int nt = 0; nt < 8; nt++) {
        const int d = nt * 8 + 2 * tig;
        xa[(size_t)(bh * 64 + d) * NPIX + r]         = __float2half_rn(accO[nt][0] * il0);
        xa[(size_t)(bh * 64 + d + 1) * NPIX + r]     = __float2half_rn(accO[nt][1] * il0);
        xa[(size_t)(bh * 64 + d) * NPIX + r + 8]     = __float2half_rn(accO[nt][2] * il1);
        xa[(size_t)(bh * 64 + d + 1) * NPIX + r + 8] = __float2half_rn(accO[nt][3] * il1);
    }
}

// ---------------- depthwise 3x3 PE: xa16 (+= conv(v)) in place ----------------
__global__ __launch_bounds__(256) void dwconv_pe(
    const __half* __restrict__ qv, const float* __restrict__ Wpe,
    const float* __restrict__ s, const float* __restrict__ bi,
    __half* __restrict__ xa)
{
    __shared__ float t[34 * 34];
    const int c = blockIdx.x;
    const int b = blockIdx.y;
    const int qc = ((c >> 6) * 128) + 64 + (c & 63);
    const size_t srcoff = ((size_t)b * 512 + qc) * NPIX;
    const int tid = threadIdx.x;

    for (int i = tid; i < 34 * 34; i += 256) t[i] = 0.0f;
    __syncthreads();
    for (int i = tid; i < NPIX; i += 256) {
        int y = i >> 5, x = i & 31;
        t[(y + 1) * 34 + (x + 1)] = __half2float(qv[srcoff + i]);
    }
    __syncthreads();

    float w[9];
#pragma unroll
    for (int i = 0; i < 9; i++) w[i] = Wpe[c * 9 + i];
    const float scv = s[c], bv = bi[c];
    const size_t off = ((size_t)b * 256 + c) * NPIX;

    for (int i = tid; i < NPIX; i += 256) {
        int y = i >> 5, x = i & 31;
        float acc = 0.0f;
#pragma unroll
        for (int ky = 0; ky < 3; ky++)
#pragma unroll
            for (int kx = 0; kx < 3; kx++)
                acc += w[ky * 3 + kx] * t[(y + ky) * 34 + (x + kx)];
        float v = __half2float(xa[off + i]) + acc * scv + bv;
        xa[off + i] = __float2half_rn(v);
    }
}

// ---------------- launcher ----------------
extern "C" void kernel_launch(void* const* d_in, const int* in_sizes, int n_in,
                              void* d_out, int out_size)
{
    (void)in_sizes; (void)n_in; (void)out_size;
    const float* x      = (const float*)d_in[0];
    const float* W_cv1  = (const float*)d_in[1];
    const float* s_cv1  = (const float*)d_in[2];
    const float* b_cv1  = (const float*)d_in[3];
    const float* W_qkv  = (const float*)d_in[4];
    const float* s_qkv  = (const float*)d_in[5];
    const float* b_qkv  = (const float*)d_in[6];
    const float* W_proj = (const float*)d_in[7];
    const float* s_proj = (const float*)d_in[8];
    const float* b_proj = (const float*)d_in[9];
    const float* W_pe   = (const float*)d_in[10];
    const float* s_pe   = (const float*)d_in[11];
    const float* b_pe   = (const float*)d_in[12];
    const float* W_ffn1 = (const float*)d_in[13];
    const float* s_ffn1 = (const float*)d_in[14];
    const float* b_ffn1 = (const float*)d_in[15];
    const float* W_ffn2 = (const float*)d_in[16];
    const float* s_ffn2 = (const float*)d_in[17];
    const float* b_ffn2 = (const float*)d_in[18];
    const float* W_cv2  = (const float*)d_in[19];
    const float* s_cv2  = (const float*)d_in[20];
    const float* b_cv2  = (const float*)d_in[21];

    static __half *x16 = nullptr, *c16, *t16, *a16, *wh;
    static float *bbf;
    if (!x16) {
        cudaGetSymbolAddress((void**)&x16, g_x16);
        cudaGetSymbolAddress((void**)&c16, g_c16);
        cudaGetSymbolAddress((void**)&t16, g_t16);
        cudaGetSymbolAddress((void**)&a16, g_a16);
        cudaGetSymbolAddress((void**)&wh,  g_wh);
        cudaGetSymbolAddress((void**)&bbf, g_bbf);
        cudaFuncSetAttribute(attn_mma,
                             cudaFuncAttributeMaxDynamicSharedMemorySize, ASMEM);
        cudaFuncSetAttribute(gemm_f16,
                             cudaFuncAttributeMaxDynamicSharedMemorySize, GSMEM);
    }
    float* out = (float*)d_out;
    const long S512 = 512 * NPIX, S256 = 256 * NPIX;

    const int W_CV1 = 0, W_QKV = 262144, W_PROJ = 393216,
              W_FFN1 = 458752, W_FFN2 = 589824, W_CV2 = 720896;

    // #0: convert x -> fp16
    {
        int n4 = BSZ * 512 * NPIX / 4;
        cvt16<<<(n4 + 255) / 256, 256>>>((const float4*)x, (uint2*)x16, n4);
    }
    // #1: convert all weights -> fp16
    wcvt_all<<<960, 256>>>(W_cv1, W_qkv, W_proj, W_ffn1, W_ffn2, W_cv2, wh);
    // #2: cv1 (SiLU) -> c16 fp16 + bbf f32 for ch>=256
    gemm_f16<<<dim3(8, 4, BSZ), 256, GSMEM>>>(
        x16, S512, 512, wh + W_CV1, s_cv1, b_cv1,
        nullptr, 0, bbf, S256, 256, c16, S512, 1);
    // #3: qkv -> t16 fp16
    gemm_f16<<<dim3(8, 4, BSZ), 256, GSMEM>>>(
        c16 + S256, S512, 256, wh + W_QKV, s_qkv, b_qkv,
        nullptr, 0, nullptr, 0, 1 << 30, t16, S512, 0);
    // #4: flash attention -> a16 (fp16)
    attn_mma<<<dim3(8, 64), 256, ASMEM>>>(t16, a16);
    // #5: PE dwconv: a16 += conv(v) (in place)
    dwconv_pe<<<dim3(256, BSZ), 256>>>(t16, W_pe, s_pe, b_pe, a16);
    // #6: proj (+bb residual) -> bbf (in place) + c16 ch256+
    gemm_f16<<<dim3(8, 2, BSZ), 256, GSMEM>>>(
        a16, S256, 256, wh + W_PROJ, s_proj, b_proj,
        bbf, S256, bbf, S256, 0, c16 + S256, S512, 0);
    // #7: ffn1 (SiLU) -> t16
    gemm_f16<<<dim3(8, 4, BSZ), 256, GSMEM>>>(
        c16 + S256, S512, 256, wh + W_FFN1, s_ffn1, b_ffn1,
        nullptr, 0, nullptr, 0, 1 << 30, t16, S512, 1);
    // #8: ffn2 (+bb2 residual) -> c16 ch256+
    gemm_f16<<<dim3(8, 2, BSZ), 256, GSMEM>>>(
        t16, S512, 512, wh + W_FFN2, s_ffn2, b_ffn2,
        bbf, S256, nullptr, 0, 1 << 30, c16 + S256, S512, 0);
    // #9: cv2 (SiLU) -> out
    gemm_f16<<<dim3(8, 4, BSZ), 256, GSMEM>>>(
        c16, S512, 512, wh + W_CV2, s_cv2, b_cv2,
        nullptr, 0, out, S512, 0, nullptr, 0, 1);
}